// round 1
// baseline (speedup 1.0000x reference)
#include <cuda_runtime.h>
#include <cstdint>
#include <cstddef>

// Problem constants
#define PB 4
#define PN 256
#define PD 256
#define PL 128
#define POUT 256

// ---------------- scratch (device globals; no runtime allocation) ----------------
__device__ float g_xhat [PB*PN*PL];        // (B,N,128)
__device__ float g_pnorm[PB*PN*PN];        // (B,N,N)
__device__ float g_adj2 [PB*PN*PN];        // (B,N,N)
__device__ float g_xi0  [PB*PN*POUT];
__device__ float g_c0   [PB*PN*POUT];
__device__ float g_AH0  [PB*PN*POUT];
__device__ float g_x1   [PB*PN*POUT];
__device__ float g_xi1  [PB*PN*POUT];
__device__ float g_c1   [PB*PN*POUT];
__device__ float g_AH1  [PB*PN*POUT];
__device__ float g_alpha1[(size_t)PB*PN*PN*POUT];   // 256 MB

// ---------------------------------------------------------------------------
// Generic row GEMM: out[row,k] = sum_d X[row,d]*W[d,k] (+bias_nk[i,k]) (+bias_k[k]) (relu?)
// D fixed = 256. 8 rows per block, blockDim.x = K (128 or 256). grid = (B*N)/8.
// ---------------------------------------------------------------------------
__global__ void rowgemm_kernel(const float* __restrict__ X, const float* __restrict__ W,
                               const float* __restrict__ bias_nk, const float* __restrict__ bias_k,
                               float* __restrict__ out, int K, int do_relu)
{
    __shared__ float xs[8 * 256];
    const int r0 = blockIdx.x * 8;
    const int t  = threadIdx.x;
    for (int f = t; f < 8 * 256; f += K) xs[f] = X[r0 * 256 + f];
    __syncthreads();

    float acc[8];
#pragma unroll
    for (int r = 0; r < 8; ++r) acc[r] = 0.f;

#pragma unroll 4
    for (int d = 0; d < 256; ++d) {
        const float wv = __ldg(&W[d * K + t]);
#pragma unroll
        for (int r = 0; r < 8; ++r) acc[r] = fmaf(xs[r * 256 + d], wv, acc[r]);
    }

    const float bk = bias_k ? __ldg(&bias_k[t]) : 0.f;
#pragma unroll
    for (int r = 0; r < 8; ++r) {
        const int row = r0 + r;
        float v = acc[r] + bk;
        if (bias_nk) v += __ldg(&bias_nk[(row & (PN - 1)) * K + t]);
        if (do_relu) v = fmaxf(v, 0.f);
        out[row * K + t] = v;
    }
}

// ---------------------------------------------------------------------------
// Fused graph-learning kernel. One block per (b,i) row; 256 threads (8 warps).
// Computes: s = sum_d |xh_i-xh_j|*w_d ; pair_norm ; leaky_relu(s + mask*sum(w));
// then row-softmax-like soft_adj and adj2 = adj*soft_adj.
// ---------------------------------------------------------------------------
__global__ void pair_softadj_kernel(const float* __restrict__ xhat,
                                    const float* __restrict__ adj,
                                    const float* __restrict__ learn_w,
                                    const int*   __restrict__ box_num,
                                    float* __restrict__ soft_adj_out,
                                    float* __restrict__ adj2,
                                    float* __restrict__ pair_norm)
{
    const int row = blockIdx.x;
    const int b = row >> 8;
    const int i = row & 255;
    const int t = threadIdx.x;
    const int warp = t >> 5, lane = t & 31;

    __shared__ float xi_s[128];
    __shared__ float w_s[128];
    __shared__ float sval[256];
    __shared__ float red[256];
    __shared__ float wsum_s, rmax_s;

    if (t < 128) { xi_s[t] = xhat[row * 128 + t]; w_s[t] = learn_w[t]; }
    __syncthreads();
    if (t == 0) {
        float s = 0.f;
        for (int d = 0; d < 128; ++d) s += w_s[d];
        wsum_s = s;
    }
    __syncthreads();

    const int bn = box_num[b];
    const bool vi = (i < bn);
    const float wsum = wsum_s;
    const float4 xi4 = reinterpret_cast<const float4*>(xi_s)[lane];
    const float4 w4  = reinterpret_cast<const float4*>(w_s)[lane];

    for (int j = warp; j < 256; j += 8) {
        const float4 xj4 = __ldg(reinterpret_cast<const float4*>(xhat + (b * 256 + j) * 128) + lane);
        const float d0 = xi4.x - xj4.x, d1 = xi4.y - xj4.y;
        const float d2 = xi4.z - xj4.z, d3 = xi4.w - xj4.w;
        float s = fabsf(d0) * w4.x + fabsf(d1) * w4.y + fabsf(d2) * w4.z + fabsf(d3) * w4.w;
        float q = d0 * d0 + d1 * d1 + d2 * d2 + d3 * d3;
#pragma unroll
        for (int off = 16; off; off >>= 1) {
            s += __shfl_down_sync(0xffffffffu, s, off);
            q += __shfl_down_sync(0xffffffffu, q, off);
        }
        if (lane == 0) {
            const float m = (vi && (j < bn)) ? 0.f : -1.f;
            float v = s + m * wsum;
            v = (v > 0.f) ? v : 0.01f * v;          // leaky_relu(0.01)
            sval[j] = v;
            pair_norm[row * 256 + j] = sqrtf(q + 1e-12f);
        }
    }
    __syncthreads();

    const float v = sval[t];
    red[t] = v;
    __syncthreads();
    for (int sft = 128; sft; sft >>= 1) {
        if (t < sft) red[t] = fmaxf(red[t], red[t + sft]);
        __syncthreads();
    }
    if (t == 0) rmax_s = red[0];
    __syncthreads();

    const float a = adj[row * 256 + t];
    const float e = expf(v - rmax_s) * a;
    red[t] = e;
    __syncthreads();
    for (int sft = 128; sft; sft >>= 1) {
        if (t < sft) red[t] += red[t + sft];
        __syncthreads();
    }
    const float sa = e / red[0] + 1e-10f;
    soft_adj_out[row * 256 + t] = sa;
    adj2[row * 256 + t] = a * sa;
}

// ---------------------------------------------------------------------------
// gl_loss: per batch b reduce over 65536 pairs.
// ---------------------------------------------------------------------------
__global__ void glloss_kernel(const float* __restrict__ soft_adj,
                              const float* __restrict__ pair_norm,
                              const int*   __restrict__ box_num,
                              float* __restrict__ gl_out)
{
    const int b = blockIdx.x;
    const int t = threadIdx.x;
    const float* sa = soft_adj + b * 65536;
    const float* pn = pair_norm + b * 65536;
    float s1 = 0.f, s2 = 0.f;
    for (int idx = t; idx < 65536; idx += 256) {
        const float s = sa[idx];
        s1 += expf(s + pn[idx]);       // ETA = 1.0
        s2 += s * s;
    }
    __shared__ float r1[256], r2[256];
    r1[t] = s1; r2[t] = s2;
    __syncthreads();
    for (int sft = 128; sft; sft >>= 1) {
        if (t < sft) { r1[t] += r1[t + sft]; r2[t] += r2[t + sft]; }
        __syncthreads();
    }
    if (t == 0) {
        const float bnf = (float)box_num[b];
        gl_out[b] = r1[0] / (bnf * bnf) + 1e-4f * sqrtf(r2[0]);   // GAMMA = 1e-4
    }
}

// ---------------------------------------------------------------------------
// Fused GCN layer 0. One block per (b,i); 256 threads.
//   H[j,k]   = relu(xi0[i,k] + c0[j,k] + rel[i,j,:]@Wt[:,k])   (c0 folds xj+bias_h+b_alpha)
//   AH0[i,k] = sum_j adj2[i,j]*H[j,k]
//   alpha1[i,j,:] = relu(H[j,:] @ w_alpha)       <- 34.4 GFLOP GEMM, SMEM tiled
// H lives only in SMEM (64-j tiles); alpha0/H0 never hit HBM.
// ---------------------------------------------------------------------------
__global__ void __launch_bounds__(256, 1) layer0_kernel(
    const float* __restrict__ xi0, const float* __restrict__ c0,
    const float* __restrict__ rel, const float* __restrict__ Wt,
    const float* __restrict__ adj2, const float* __restrict__ w_alpha,
    float* __restrict__ alpha1, float* __restrict__ AH0)
{
    extern __shared__ float sm[];
    float* Wt_s  = sm;                 // 6*256 = 1536
    float* xi_s  = Wt_s + 1536;        // 256
    float* rel_s = xi_s + 256;         // 64*6 = 384
    float* adj_s = rel_s + 384;        // 64
    float* Hs    = adj_s + 64;         // 64*257 (padded vs bank conflicts)
    float* ws    = Hs + 64 * 257;      // 32*256

    const int row = blockIdx.x;        // b*256 + i
    const int b = row >> 8;
    const int t = threadIdx.x;
    const int tj = t >> 5;             // 0..7 -> 8 j-rows each
    const int tk = t & 31;             // 0..31 -> 8 k' cols each

    for (int f = t; f < 1536; f += 256) Wt_s[f] = Wt[f];
    xi_s[t] = xi0[row * 256 + t];

    const float* c0b    = c0 + b * 65536;
    const float* relrow = rel + (size_t)row * 256 * 6;
    const float* adjrow = adj2 + row * 256;
    float ah = 0.f;

    for (int jt = 0; jt < 4; ++jt) {
        const int jbase = jt * 64;
        // stage rel + adj tiles
        for (int f = t; f < 384; f += 256) rel_s[f] = relrow[jbase * 6 + f];
        if (t < 64) adj_s[t] = adjrow[jbase + t];
        __syncthreads();

        // build H tile (thread t = column k), accumulate AH
#pragma unroll 4
        for (int j = 0; j < 64; ++j) {
            const float* rj = rel_s + j * 6;
            float a = rj[0] * Wt_s[t]        + rj[1] * Wt_s[256 + t]
                    + rj[2] * Wt_s[512 + t]  + rj[3] * Wt_s[768 + t]
                    + rj[4] * Wt_s[1024 + t] + rj[5] * Wt_s[1280 + t];
            float h = xi_s[t] + c0b[(jbase + j) * 256 + t] + a;
            h = fmaxf(h, 0.f);
            Hs[j * 257 + t] = h;
            ah = fmaf(adj_s[j], h, ah);
        }

        // GEMM: (64 x 256) @ (256 x 256), 8x8 microtile per thread
        float acc[8][8];
#pragma unroll
        for (int r = 0; r < 8; ++r)
#pragma unroll
            for (int u = 0; u < 8; ++u) acc[r][u] = 0.f;

        for (int kkb = 0; kkb < 8; ++kkb) {
            __syncthreads();   // ws reuse fence (first iter also publishes Hs)
#pragma unroll
            for (int s = 0; s < 32; ++s)
                ws[s * 256 + t] = __ldg(&w_alpha[kkb * 8192 + s * 256 + t]);
            __syncthreads();

            const float* hbase = Hs + (tj * 8) * 257 + kkb * 32;
#pragma unroll
            for (int k = 0; k < 32; ++k) {
                float av[8];
#pragma unroll
                for (int r = 0; r < 8; ++r) av[r] = hbase[r * 257 + k];   // warp broadcast
                const float4 b0 = *reinterpret_cast<const float4*>(&ws[k * 256 + tk * 8]);
                const float4 b1 = *reinterpret_cast<const float4*>(&ws[k * 256 + tk * 8 + 4]);
#pragma unroll
                for (int r = 0; r < 8; ++r) {
                    acc[r][0] = fmaf(av[r], b0.x, acc[r][0]);
                    acc[r][1] = fmaf(av[r], b0.y, acc[r][1]);
                    acc[r][2] = fmaf(av[r], b0.z, acc[r][2]);
                    acc[r][3] = fmaf(av[r], b0.w, acc[r][3]);
                    acc[r][4] = fmaf(av[r], b1.x, acc[r][4]);
                    acc[r][5] = fmaf(av[r], b1.y, acc[r][5]);
                    acc[r][6] = fmaf(av[r], b1.z, acc[r][6]);
                    acc[r][7] = fmaf(av[r], b1.w, acc[r][7]);
                }
            }
        }

        // write relu(alpha1) for this 64-j tile
        float* dst = alpha1 + ((size_t)row * 256 + jbase + tj * 8) * 256 + tk * 8;
#pragma unroll
        for (int r = 0; r < 8; ++r) {
            float4 o0, o1;
            o0.x = fmaxf(acc[r][0], 0.f); o0.y = fmaxf(acc[r][1], 0.f);
            o0.z = fmaxf(acc[r][2], 0.f); o0.w = fmaxf(acc[r][3], 0.f);
            o1.x = fmaxf(acc[r][4], 0.f); o1.y = fmaxf(acc[r][5], 0.f);
            o1.z = fmaxf(acc[r][6], 0.f); o1.w = fmaxf(acc[r][7], 0.f);
            *reinterpret_cast<float4*>(dst + (size_t)r * 256)     = o0;
            *reinterpret_cast<float4*>(dst + (size_t)r * 256 + 4) = o1;
        }
        __syncthreads();
    }

    AH0[row * 256 + t] = ah;
}

// ---------------------------------------------------------------------------
// GCN layer 1 (alpha2 never needed): AH1[i,k] = sum_j adj2[i,j]*relu(xi1[i,k]+c1[j,k]+alpha1[i,j,k])
// ---------------------------------------------------------------------------
__global__ void layer1_kernel(const float* __restrict__ xi1, const float* __restrict__ c1,
                              const float* __restrict__ alpha1, const float* __restrict__ adj2,
                              float* __restrict__ AH1)
{
    const int row = blockIdx.x;
    const int b = row >> 8;
    const int t = threadIdx.x;
    __shared__ float adj_s[256];
    adj_s[t] = adj2[row * 256 + t];
    const float xik = xi1[row * 256 + t];
    __syncthreads();

    const float* c1b = c1 + b * 65536;
    const float* al  = alpha1 + (size_t)row * 65536;
    float ah = 0.f;
#pragma unroll 4
    for (int j = 0; j < 256; ++j) {
        float h = xik + __ldg(&c1b[j * 256 + t]) + al[j * 256 + t];
        h = fmaxf(h, 0.f);
        ah = fmaf(adj_s[j], h, ah);
    }
    AH1[row * 256 + t] = ah;
}

// ---------------------------------------------------------------------------
extern "C" void kernel_launch(void* const* d_in, const int* in_sizes, int n_in,
                              void* d_out, int out_size)
{
    (void)in_sizes; (void)n_in; (void)out_size;

    const float* x        = (const float*)d_in[0];
    const float* rel      = (const float*)d_in[1];
    const float* adj      = (const float*)d_in[2];
    const int*   bnum     = (const int*)  d_in[3];
    const float* Wt       = (const float*)d_in[4];   // W_alpha_t (6,256)
    const float* b_alpha  = (const float*)d_in[5];
    const float* W_proj   = (const float*)d_in[6];
    const float* b_proj   = (const float*)d_in[7];
    const float* learn_w  = (const float*)d_in[8];
    const float* w_alpha0 = (const float*)d_in[9];
    const float* w_vi0    = (const float*)d_in[10];
    const float* w_vj0    = (const float*)d_in[11];
    const float* bias_h0  = (const float*)d_in[12];
    const float* w_node0  = (const float*)d_in[13];
    /* d_in[14] = l1_w_alpha: unused (alpha2 discarded) */
    const float* w_vi1    = (const float*)d_in[15];
    const float* w_vj1    = (const float*)d_in[16];
    const float* bias_h1  = (const float*)d_in[17];
    const float* w_node1  = (const float*)d_in[18];

    float* out      = (float*)d_out;
    float* out_x2   = out;            // 262144
    float* out_sadj = out + 262144;   // 262144
    float* out_gl   = out + 524288;   // 4

    float *xhat, *pnorm, *adj2, *xi0, *c0, *AH0, *x1, *xi1, *c1, *AH1, *alpha1;
    cudaGetSymbolAddress((void**)&xhat,   g_xhat);
    cudaGetSymbolAddress((void**)&pnorm,  g_pnorm);
    cudaGetSymbolAddress((void**)&adj2,   g_adj2);
    cudaGetSymbolAddress((void**)&xi0,    g_xi0);
    cudaGetSymbolAddress((void**)&c0,     g_c0);
    cudaGetSymbolAddress((void**)&AH0,    g_AH0);
    cudaGetSymbolAddress((void**)&x1,     g_x1);
    cudaGetSymbolAddress((void**)&xi1,    g_xi1);
    cudaGetSymbolAddress((void**)&c1,     g_c1);
    cudaGetSymbolAddress((void**)&AH1,    g_AH1);
    cudaGetSymbolAddress((void**)&alpha1, g_alpha1);

    // ---- graph learning ----
    rowgemm_kernel<<<128, 128>>>(x, W_proj, nullptr, b_proj, xhat, 128, 0);
    pair_softadj_kernel<<<1024, 256>>>(xhat, adj, learn_w, bnum, out_sadj, adj2, pnorm);
    glloss_kernel<<<4, 256>>>(out_sadj, pnorm, bnum, out_gl);

    // ---- GCN layer 0 ----
    rowgemm_kernel<<<128, 256>>>(x, w_vi0, nullptr, nullptr, xi0, 256, 0);
    rowgemm_kernel<<<128, 256>>>(x, w_vj0, bias_h0, b_alpha, c0, 256, 0);   // xj + bias_h + b_alpha

    const int SMEM = (1536 + 256 + 384 + 64 + 64 * 257 + 32 * 256) * 4;     // 107520 B
    cudaFuncSetAttribute(layer0_kernel, cudaFuncAttributeMaxDynamicSharedMemorySize, SMEM);
    layer0_kernel<<<1024, 256, SMEM>>>(xi0, c0, rel, Wt, adj2, w_alpha0, alpha1, AH0);

    rowgemm_kernel<<<128, 256>>>(AH0, w_node0, nullptr, nullptr, x1, 256, 1);

    // ---- GCN layer 1 ----
    rowgemm_kernel<<<128, 256>>>(x1, w_vi1, nullptr, nullptr, xi1, 256, 0);
    rowgemm_kernel<<<128, 256>>>(x1, w_vj1, bias_h1, nullptr, c1, 256, 0);
    layer1_kernel<<<1024, 256>>>(xi1, c1, alpha1, adj2, AH1);
    rowgemm_kernel<<<128, 256>>>(AH1, w_node1, nullptr, nullptr, out_x2, 256, 1);
}

// round 2
// speedup vs baseline: 1.0000x; 1.0000x over previous
#include <cuda_runtime.h>
#include <cuda_bf16.h>
#include <cstdint>
#include <cstddef>

// Problem constants
#define PB 4
#define PN 256
#define PD 256
#define PL 128
#define POUT 256

// ---------------- scratch (device globals; no runtime allocation) ----------------
__device__ float g_xhat [PB*PN*PL];
__device__ float g_pnorm[PB*PN*PN];
__device__ float g_adj2 [PB*PN*PN];
__device__ float g_xi0  [PB*PN*POUT];
__device__ float g_c0   [PB*PN*POUT];
__device__ float g_AH0  [PB*PN*POUT];
__device__ float g_x1   [PB*PN*POUT];
__device__ float g_xi1  [PB*PN*POUT];
__device__ float g_c1   [PB*PN*POUT];
__device__ float g_AH1  [PB*PN*POUT];
__device__ __nv_bfloat16 g_alpha1[(size_t)PB*PN*PN*POUT];   // 128 MB

// ---------------------------------------------------------------------------
// Row GEMM: 4 rows/block, blockDim = K (128 or 256), grid = B*N/4 = 256.
// out[row,k] = sum_d X[row,d]*W[d,k] (+bias_nk[row&255,k]) (+bias_k[k]) (relu?)
// ---------------------------------------------------------------------------
__global__ void rowgemm_kernel(const float* __restrict__ X, const float* __restrict__ W,
                               const float* __restrict__ bias_nk, const float* __restrict__ bias_k,
                               float* __restrict__ out, int K, int do_relu)
{
    __shared__ float xs[4 * 256];
    const int r0 = blockIdx.x * 4;
    const int t  = threadIdx.x;
    for (int f = t; f < 4 * 256; f += K) xs[f] = X[r0 * 256 + f];
    __syncthreads();

    float acc[4] = {0.f, 0.f, 0.f, 0.f};
#pragma unroll 8
    for (int d = 0; d < 256; ++d) {
        const float wv = __ldg(&W[d * K + t]);
#pragma unroll
        for (int r = 0; r < 4; ++r) acc[r] = fmaf(xs[r * 256 + d], wv, acc[r]);
    }

    const float bk = bias_k ? __ldg(&bias_k[t]) : 0.f;
#pragma unroll
    for (int r = 0; r < 4; ++r) {
        const int row = r0 + r;
        float v = acc[r] + bk;
        if (bias_nk) v += __ldg(&bias_nk[(row & (PN - 1)) * K + t]);
        if (do_relu) v = fmaxf(v, 0.f);
        out[row * K + t] = v;
    }
}

// Dual row GEMM (K=256): out1 = X@W1 ; out2 = X@W2 + bias_nk[row&255,:] (+bias_k)
__global__ void rowgemm_dual_kernel(const float* __restrict__ X,
                                    const float* __restrict__ W1, const float* __restrict__ W2,
                                    const float* __restrict__ bias_nk, const float* __restrict__ bias_k,
                                    float* __restrict__ out1, float* __restrict__ out2)
{
    __shared__ float xs[4 * 256];
    const int r0 = blockIdx.x * 4;
    const int t  = threadIdx.x;
    for (int f = t; f < 4 * 256; f += 256) xs[f] = X[r0 * 256 + f];
    __syncthreads();

    float a1[4] = {0.f, 0.f, 0.f, 0.f};
    float a2[4] = {0.f, 0.f, 0.f, 0.f};
#pragma unroll 8
    for (int d = 0; d < 256; ++d) {
        const float w1 = __ldg(&W1[d * 256 + t]);
        const float w2 = __ldg(&W2[d * 256 + t]);
#pragma unroll
        for (int r = 0; r < 4; ++r) {
            const float xv = xs[r * 256 + d];
            a1[r] = fmaf(xv, w1, a1[r]);
            a2[r] = fmaf(xv, w2, a2[r]);
        }
    }

    const float bk = bias_k ? __ldg(&bias_k[t]) : 0.f;
#pragma unroll
    for (int r = 0; r < 4; ++r) {
        const int row = r0 + r;
        out1[row * 256 + t] = a1[r];
        out2[row * 256 + t] = a2[r] + bk + __ldg(&bias_nk[(row & (PN - 1)) * 256 + t]);
    }
}

// ---------------------------------------------------------------------------
// Fused graph-learning kernel. One block per (b,i) row; 256 threads (8 warps).
// ---------------------------------------------------------------------------
__global__ void pair_softadj_kernel(const float* __restrict__ xhat,
                                    const float* __restrict__ adj,
                                    const float* __restrict__ learn_w,
                                    const int*   __restrict__ box_num,
                                    float* __restrict__ soft_adj_out,
                                    float* __restrict__ adj2,
                                    float* __restrict__ pair_norm)
{
    const int row = blockIdx.x;
    const int b = row >> 8;
    const int i = row & 255;
    const int t = threadIdx.x;
    const int warp = t >> 5, lane = t & 31;

    __shared__ float xi_s[128];
    __shared__ float w_s[128];
    __shared__ float sval[256];
    __shared__ float red[256];
    __shared__ float wsum_s, rmax_s;

    if (t < 128) { xi_s[t] = xhat[row * 128 + t]; w_s[t] = learn_w[t]; }
    __syncthreads();
    if (t == 0) {
        float s = 0.f;
        for (int d = 0; d < 128; ++d) s += w_s[d];
        wsum_s = s;
    }
    __syncthreads();

    const int bn = box_num[b];
    const bool vi = (i < bn);
    const float wsum = wsum_s;
    const float4 xi4 = reinterpret_cast<const float4*>(xi_s)[lane];
    const float4 w4  = reinterpret_cast<const float4*>(w_s)[lane];

    for (int j = warp; j < 256; j += 8) {
        const float4 xj4 = __ldg(reinterpret_cast<const float4*>(xhat + (b * 256 + j) * 128) + lane);
        const float d0 = xi4.x - xj4.x, d1 = xi4.y - xj4.y;
        const float d2 = xi4.z - xj4.z, d3 = xi4.w - xj4.w;
        float s = fabsf(d0) * w4.x + fabsf(d1) * w4.y + fabsf(d2) * w4.z + fabsf(d3) * w4.w;
        float q = d0 * d0 + d1 * d1 + d2 * d2 + d3 * d3;
#pragma unroll
        for (int off = 16; off; off >>= 1) {
            s += __shfl_down_sync(0xffffffffu, s, off);
            q += __shfl_down_sync(0xffffffffu, q, off);
        }
        if (lane == 0) {
            const float m = (vi && (j < bn)) ? 0.f : -1.f;
            float v = s + m * wsum;
            v = (v > 0.f) ? v : 0.01f * v;          // leaky_relu(0.01)
            sval[j] = v;
            pair_norm[row * 256 + j] = sqrtf(q + 1e-12f);
        }
    }
    __syncthreads();

    const float v = sval[t];
    red[t] = v;
    __syncthreads();
    for (int sft = 128; sft; sft >>= 1) {
        if (t < sft) red[t] = fmaxf(red[t], red[t + sft]);
        __syncthreads();
    }
    if (t == 0) rmax_s = red[0];
    __syncthreads();

    const float a = adj[row * 256 + t];
    const float e = expf(v - rmax_s) * a;
    red[t] = e;
    __syncthreads();
    for (int sft = 128; sft; sft >>= 1) {
        if (t < sft) red[t] += red[t + sft];
        __syncthreads();
    }
    const float sa = e / red[0] + 1e-10f;
    soft_adj_out[row * 256 + t] = sa;
    adj2[row * 256 + t] = a * sa;
}

// ---------------------------------------------------------------------------
__global__ void glloss_kernel(const float* __restrict__ soft_adj,
                              const float* __restrict__ pair_norm,
                              const int*   __restrict__ box_num,
                              float* __restrict__ gl_out)
{
    const int b = blockIdx.x;
    const int t = threadIdx.x;
    const float* sa = soft_adj + b * 65536;
    const float* pn = pair_norm + b * 65536;
    float s1 = 0.f, s2 = 0.f;
    for (int idx = t; idx < 65536; idx += 256) {
        const float s = sa[idx];
        s1 += expf(s + pn[idx]);       // ETA = 1.0
        s2 += s * s;
    }
    __shared__ float r1[256], r2[256];
    r1[t] = s1; r2[t] = s2;
    __syncthreads();
    for (int sft = 128; sft; sft >>= 1) {
        if (t < sft) { r1[t] += r1[t + sft]; r2[t] += r2[t + sft]; }
        __syncthreads();
    }
    if (t == 0) {
        const float bnf = (float)box_num[b];
        gl_out[b] = r1[0] / (bnf * bnf) + 1e-4f * sqrtf(r2[0]);   // GAMMA = 1e-4
    }
}

// ---------------------------------------------------------------------------
// Fused GCN layer 0. One block per (b,i); 256 threads; 2 blocks/SM.
//   H[j,k]   = relu(xi0[i,k] + c0[j,k] + rel[i,j,:]@Wt[:,k])
//   AH0[i,k] = sum_j adj2[i,j]*H[j,k]
//   alpha1[i,j,:] = relu(H[j,:] @ w_alpha)  -> bf16
// ---------------------------------------------------------------------------
__global__ void __launch_bounds__(256, 2) layer0_kernel(
    const float* __restrict__ xi0, const float* __restrict__ c0,
    const float* __restrict__ rel, const float* __restrict__ Wt,
    const float* __restrict__ adj2, const float* __restrict__ w_alpha,
    __nv_bfloat16* __restrict__ alpha1, float* __restrict__ AH0)
{
    extern __shared__ float sm[];
    float* Wt_s  = sm;                 // 6*256 = 1536
    float* xi_s  = Wt_s + 1536;        // 256
    float* rel_s = xi_s + 256;         // 64*6 = 384
    float* adj_s = rel_s + 384;        // 64
    float* Hs    = adj_s + 64;         // 64*257
    float* ws    = Hs + 64 * 257;      // 16*256

    const int row = blockIdx.x;        // b*256 + i
    const int b = row >> 8;
    const int t = threadIdx.x;
    const int tj = t >> 5;             // 0..7 -> 8 j-rows each
    const int tk = t & 31;             // 0..31 -> 8 k' cols each

    for (int f = t; f < 1536; f += 256) Wt_s[f] = Wt[f];
    xi_s[t] = xi0[row * 256 + t];
    __syncthreads();

    // hoist j-invariant Wt column + xi
    const float wv0 = Wt_s[t],        wv1 = Wt_s[256 + t],  wv2 = Wt_s[512 + t];
    const float wv3 = Wt_s[768 + t],  wv4 = Wt_s[1024 + t], wv5 = Wt_s[1280 + t];
    const float xik = xi_s[t];

    const float* c0b    = c0 + b * 65536;
    const float* relrow = rel + (size_t)row * 256 * 6;
    const float* adjrow = adj2 + row * 256;
    float ah = 0.f;

    for (int jt = 0; jt < 4; ++jt) {
        const int jbase = jt * 64;
        for (int f = t; f < 384; f += 256) rel_s[f] = relrow[jbase * 6 + f];
        if (t < 64) adj_s[t] = adjrow[jbase + t];
        __syncthreads();

        // build H tile (thread t = column k), accumulate AH
#pragma unroll 4
        for (int j = 0; j < 64; ++j) {
            const float* rj = rel_s + j * 6;
            float a = rj[0] * wv0 + rj[1] * wv1 + rj[2] * wv2
                    + rj[3] * wv3 + rj[4] * wv4 + rj[5] * wv5;
            float h = xik + __ldg(&c0b[(jbase + j) * 256 + t]) + a;
            h = fmaxf(h, 0.f);
            Hs[j * 257 + t] = h;
            ah = fmaf(adj_s[j], h, ah);
        }

        // GEMM: (64 x 256) @ (256 x 256), 8x8 microtile per thread
        float acc[8][8];
#pragma unroll
        for (int r = 0; r < 8; ++r)
#pragma unroll
            for (int u = 0; u < 8; ++u) acc[r][u] = 0.f;

        for (int kkb = 0; kkb < 16; ++kkb) {
            __syncthreads();   // ws reuse fence (first iter also publishes Hs)
#pragma unroll
            for (int s = 0; s < 16; ++s)
                ws[s * 256 + t] = __ldg(&w_alpha[kkb * 4096 + s * 256 + t]);
            __syncthreads();

            const float* hbase = Hs + (tj * 8) * 257 + kkb * 16;
#pragma unroll
            for (int k = 0; k < 16; ++k) {
                float av[8];
#pragma unroll
                for (int r = 0; r < 8; ++r) av[r] = hbase[r * 257 + k];   // warp broadcast
                const float4 b0 = *reinterpret_cast<const float4*>(&ws[k * 256 + tk * 8]);
                const float4 b1 = *reinterpret_cast<const float4*>(&ws[k * 256 + tk * 8 + 4]);
#pragma unroll
                for (int r = 0; r < 8; ++r) {
                    acc[r][0] = fmaf(av[r], b0.x, acc[r][0]);
                    acc[r][1] = fmaf(av[r], b0.y, acc[r][1]);
                    acc[r][2] = fmaf(av[r], b0.z, acc[r][2]);
                    acc[r][3] = fmaf(av[r], b0.w, acc[r][3]);
                    acc[r][4] = fmaf(av[r], b1.x, acc[r][4]);
                    acc[r][5] = fmaf(av[r], b1.y, acc[r][5]);
                    acc[r][6] = fmaf(av[r], b1.z, acc[r][6]);
                    acc[r][7] = fmaf(av[r], b1.w, acc[r][7]);
                }
            }
        }

        // write relu(alpha1) tile as bf16
        __nv_bfloat16* dst = alpha1 + ((size_t)row * 256 + jbase + tj * 8) * 256 + tk * 8;
#pragma unroll
        for (int r = 0; r < 8; ++r) {
            __nv_bfloat162 p0 = __floats2bfloat162_rn(fmaxf(acc[r][0], 0.f), fmaxf(acc[r][1], 0.f));
            __nv_bfloat162 p1 = __floats2bfloat162_rn(fmaxf(acc[r][2], 0.f), fmaxf(acc[r][3], 0.f));
            __nv_bfloat162 p2 = __floats2bfloat162_rn(fmaxf(acc[r][4], 0.f), fmaxf(acc[r][5], 0.f));
            __nv_bfloat162 p3 = __floats2bfloat162_rn(fmaxf(acc[r][6], 0.f), fmaxf(acc[r][7], 0.f));
            uint4 u;
            u.x = *reinterpret_cast<uint32_t*>(&p0);
            u.y = *reinterpret_cast<uint32_t*>(&p1);
            u.z = *reinterpret_cast<uint32_t*>(&p2);
            u.w = *reinterpret_cast<uint32_t*>(&p3);
            *reinterpret_cast<uint4*>(dst + (size_t)r * 256) = u;
        }
        __syncthreads();
    }

    AH0[row * 256 + t] = ah;
}

// ---------------------------------------------------------------------------
// GCN layer 1: AH1[i,k] = sum_j adj2[i,j]*relu(xi1[i,k]+c1[j,k]+alpha1[i,j,k])
// 128 threads/block, each handles 2 adjacent k columns (bf162 alpha1 loads).
// ---------------------------------------------------------------------------
__global__ void layer1_kernel(const float* __restrict__ xi1, const float* __restrict__ c1,
                              const __nv_bfloat16* __restrict__ alpha1,
                              const float* __restrict__ adj2,
                              float* __restrict__ AH1)
{
    const int row = blockIdx.x;
    const int b = row >> 8;
    const int t = threadIdx.x;           // 0..127 -> cols 2t, 2t+1
    __shared__ float adj_s[256];
    adj_s[t]       = adj2[row * 256 + t];
    adj_s[t + 128] = adj2[row * 256 + t + 128];
    const float2 xik = *reinterpret_cast<const float2*>(xi1 + row * 256 + 2 * t);
    __syncthreads();

    const float2* c1b = reinterpret_cast<const float2*>(c1 + b * 65536);
    const __nv_bfloat162* al = reinterpret_cast<const __nv_bfloat162*>(alpha1 + (size_t)row * 65536);
    float ah0 = 0.f, ah1 = 0.f;
#pragma unroll 4
    for (int j = 0; j < 256; ++j) {
        const float2 c = __ldg(&c1b[j * 128 + t]);
        const float2 a = __bfloat1622float2(__ldg(&al[j * 128 + t]));
        const float h0 = fmaxf(xik.x + c.x + a.x, 0.f);
        const float h1 = fmaxf(xik.y + c.y + a.y, 0.f);
        const float w = adj_s[j];
        ah0 = fmaf(w, h0, ah0);
        ah1 = fmaf(w, h1, ah1);
    }
    float2 o; o.x = ah0; o.y = ah1;
    *reinterpret_cast<float2*>(AH1 + row * 256 + 2 * t) = o;
}

// ---------------------------------------------------------------------------
extern "C" void kernel_launch(void* const* d_in, const int* in_sizes, int n_in,
                              void* d_out, int out_size)
{
    (void)in_sizes; (void)n_in; (void)out_size;

    const float* x        = (const float*)d_in[0];
    const float* rel      = (const float*)d_in[1];
    const float* adj      = (const float*)d_in[2];
    const int*   bnum     = (const int*)  d_in[3];
    const float* Wt       = (const float*)d_in[4];   // W_alpha_t (6,256)
    const float* b_alpha  = (const float*)d_in[5];
    const float* W_proj   = (const float*)d_in[6];
    const float* b_proj   = (const float*)d_in[7];
    const float* learn_w  = (const float*)d_in[8];
    const float* w_alpha0 = (const float*)d_in[9];
    const float* w_vi0    = (const float*)d_in[10];
    const float* w_vj0    = (const float*)d_in[11];
    const float* bias_h0  = (const float*)d_in[12];
    const float* w_node0  = (const float*)d_in[13];
    /* d_in[14] = l1_w_alpha: unused (alpha2 discarded) */
    const float* w_vi1    = (const float*)d_in[15];
    const float* w_vj1    = (const float*)d_in[16];
    const float* bias_h1  = (const float*)d_in[17];
    const float* w_node1  = (const float*)d_in[18];

    float* out      = (float*)d_out;
    float* out_x2   = out;            // 262144
    float* out_sadj = out + 262144;   // 262144
    float* out_gl   = out + 524288;   // 4

    float *xhat, *pnorm, *adj2, *xi0, *c0, *AH0, *x1, *xi1, *c1, *AH1;
    __nv_bfloat16* alpha1;
    cudaGetSymbolAddress((void**)&xhat,   g_xhat);
    cudaGetSymbolAddress((void**)&pnorm,  g_pnorm);
    cudaGetSymbolAddress((void**)&adj2,   g_adj2);
    cudaGetSymbolAddress((void**)&xi0,    g_xi0);
    cudaGetSymbolAddress((void**)&c0,     g_c0);
    cudaGetSymbolAddress((void**)&AH0,    g_AH0);
    cudaGetSymbolAddress((void**)&x1,     g_x1);
    cudaGetSymbolAddress((void**)&xi1,    g_xi1);
    cudaGetSymbolAddress((void**)&c1,     g_c1);
    cudaGetSymbolAddress((void**)&AH1,    g_AH1);
    cudaGetSymbolAddress((void**)&alpha1, g_alpha1);

    // ---- graph learning ----
    rowgemm_kernel<<<256, 128>>>(x, W_proj, nullptr, b_proj, xhat, 128, 0);
    pair_softadj_kernel<<<1024, 256>>>(xhat, adj, learn_w, bnum, out_sadj, adj2, pnorm);
    glloss_kernel<<<4, 256>>>(out_sadj, pnorm, bnum, out_gl);

    // ---- GCN layer 0 ----
    rowgemm_dual_kernel<<<256, 256>>>(x, w_vi0, w_vj0, bias_h0, b_alpha, xi0, c0);

    const int SMEM = (1536 + 256 + 384 + 64 + 64 * 257 + 16 * 256) * 4;     // 91136 B
    cudaFuncSetAttribute(layer0_kernel, cudaFuncAttributeMaxDynamicSharedMemorySize, SMEM);
    layer0_kernel<<<1024, 256, SMEM>>>(xi0, c0, rel, Wt, adj2, w_alpha0, alpha1, AH0);

    rowgemm_kernel<<<256, 256>>>(AH0, w_node0, nullptr, nullptr, x1, 256, 1);

    // ---- GCN layer 1 ----
    rowgemm_dual_kernel<<<256, 256>>>(x1, w_vi1, w_vj1, bias_h1, nullptr, xi1, c1);
    layer1_kernel<<<1024, 128>>>(xi1, c1, alpha1, adj2, AH1);
    rowgemm_kernel<<<256, 256>>>(AH1, w_node1, nullptr, nullptr, out_x2, 256, 1);
}

// round 4
// speedup vs baseline: 1.7751x; 1.7751x over previous
#include <cuda_runtime.h>
#include <cuda_bf16.h>
#include <cstdint>
#include <cstddef>

// Problem constants
#define PB 4
#define PN 256
#define PD 256
#define PL 128
#define POUT 256

// ============================ helpers ============================
__device__ __forceinline__ uint32_t smem_to_u32(const void* smem_ptr) {
    uint32_t addr;
    asm("{ .reg .u64 tmp; cvta.to.shared.u64 tmp, %1; cvt.u32.u64 %0, tmp; }"
        : "=r"(addr) : "l"(smem_ptr));
    return addr;
}

__device__ __forceinline__ void ldsm4(uint32_t* r, uint32_t addr) {
    asm volatile("ldmatrix.sync.aligned.m8n8.x4.shared.b16 {%0,%1,%2,%3}, [%4];"
        : "=r"(r[0]), "=r"(r[1]), "=r"(r[2]), "=r"(r[3]) : "r"(addr));
}

__device__ __forceinline__ void mma_bf16(float* c, const uint32_t* a, uint32_t b0, uint32_t b1) {
    asm volatile(
        "mma.sync.aligned.m16n8k16.row.col.f32.bf16.bf16.f32 "
        "{%0,%1,%2,%3}, {%4,%5,%6,%7}, {%8,%9}, {%0,%1,%2,%3};"
        : "+f"(c[0]), "+f"(c[1]), "+f"(c[2]), "+f"(c[3])
        : "r"(a[0]), "r"(a[1]), "r"(a[2]), "r"(a[3]), "r"(b0), "r"(b1));
}

// ---------------- scratch (device globals; no runtime allocation) ----------------
__device__ float g_xhat [PB*PN*PL];
__device__ float g_pnorm[PB*PN*PN];
__device__ float g_adj2 [PB*PN*PN];
__device__ float g_xi0  [PB*PN*POUT];
__device__ float g_c0   [PB*PN*POUT];
__device__ float g_AH0  [PB*PN*POUT];
__device__ float g_x1   [PB*PN*POUT];
__device__ float g_xi1  [PB*PN*POUT];
__device__ float g_c1   [PB*PN*POUT];
__device__ float g_AH1  [PB*PN*POUT];
__device__ float g_alpha1[(size_t)PB*PN*PN*POUT];        // 256 MB fp32
// Pre-split w_alpha images: layout [kh:2][n:256][k:128] bf16, 256B rows,
// XOR-swizzled by (n&7)<<4 within the row -> ldmatrix conflict-free, verbatim staging.
__device__ __nv_bfloat16 g_wimg1[2*256*128];             // hi
__device__ __nv_bfloat16 g_wimg2[2*256*128];             // lo residual

// ---------------------------------------------------------------------------
// Prep: split w_alpha0 (d,k)=(256,256) into bf16 hi/lo transposed images.
// Element (k=d, n): image[kh][n][kk] with kh=k>>7, kk=k&127.
// ---------------------------------------------------------------------------
__global__ void prep_wsplit_kernel(const float* __restrict__ w_alpha)
{
    const int e = blockIdx.x * 256 + threadIdx.x;    // 65536
    const int k = e >> 8;
    const int n = e & 255;
    const float v = w_alpha[k * 256 + n];
    const __nv_bfloat16 hi = __float2bfloat16_rn(v);
    const __nv_bfloat16 lo = __float2bfloat16_rn(v - __bfloat162float(hi));
    const int kh = k >> 7, kk = k & 127;
    const uint32_t off = kh * 65536u + n * 256u + (uint32_t)((kk * 2) ^ ((n & 7) << 4));
    *reinterpret_cast<__nv_bfloat16*>(reinterpret_cast<char*>(g_wimg1) + off) = hi;
    *reinterpret_cast<__nv_bfloat16*>(reinterpret_cast<char*>(g_wimg2) + off) = lo;
}

// ---------------------------------------------------------------------------
// Simple row GEMM for xhat (K=128)
// ---------------------------------------------------------------------------
__global__ void rowgemm_kernel(const float* __restrict__ X, const float* __restrict__ W,
                               const float* __restrict__ bias_k, float* __restrict__ out)
{
    __shared__ float xs[4 * 256];
    const int r0 = blockIdx.x * 4;
    const int t  = threadIdx.x;
    for (int f = t; f < 4 * 256; f += 128) xs[f] = X[r0 * 256 + f];
    __syncthreads();

    float acc[4] = {0.f, 0.f, 0.f, 0.f};
#pragma unroll 8
    for (int d = 0; d < 256; ++d) {
        const float wv = __ldg(&W[d * 128 + t]);
#pragma unroll
        for (int r = 0; r < 4; ++r) acc[r] = fmaf(xs[r * 256 + d], wv, acc[r]);
    }
    const float bk = __ldg(&bias_k[t]);
#pragma unroll
    for (int r = 0; r < 4; ++r) out[(r0 + r) * 128 + t] = acc[r] + bk;
}

// ---------------------------------------------------------------------------
// SMEM-tiled row GEMM (K=256): 8 rows/block, 256 threads, relu output.
// ---------------------------------------------------------------------------
__global__ __launch_bounds__(256) void rowgemm8_kernel(
    const float* __restrict__ X, const float* __restrict__ W, float* __restrict__ out)
{
    __shared__ float xs[8 * 256];
    __shared__ float ws[32 * 256];
    const int r0 = blockIdx.x * 8;
    const int t  = threadIdx.x;
    for (int f = t; f < 8 * 256; f += 256) xs[f] = X[r0 * 256 + f];

    float acc[8];
#pragma unroll
    for (int r = 0; r < 8; ++r) acc[r] = 0.f;

    for (int dt = 0; dt < 8; ++dt) {
        __syncthreads();
        const float4* Wv = reinterpret_cast<const float4*>(W + dt * 32 * 256);
        float4* wsv = reinterpret_cast<float4*>(ws);
        for (int i = t; i < 2048; i += 256) wsv[i] = __ldg(&Wv[i]);
        __syncthreads();
#pragma unroll
        for (int d4 = 0; d4 < 32; d4 += 4) {
            float wv0 = ws[(d4 + 0) * 256 + t];
            float wv1 = ws[(d4 + 1) * 256 + t];
            float wv2 = ws[(d4 + 2) * 256 + t];
            float wv3 = ws[(d4 + 3) * 256 + t];
#pragma unroll
            for (int r = 0; r < 8; ++r) {
                const float4 xv = *reinterpret_cast<const float4*>(&xs[r * 256 + dt * 32 + d4]);
                acc[r] = fmaf(xv.x, wv0, acc[r]);
                acc[r] = fmaf(xv.y, wv1, acc[r]);
                acc[r] = fmaf(xv.z, wv2, acc[r]);
                acc[r] = fmaf(xv.w, wv3, acc[r]);
            }
        }
    }
#pragma unroll
    for (int r = 0; r < 8; ++r) out[(r0 + r) * 256 + t] = fmaxf(acc[r], 0.f);
}

// Dual variant: out1 = X@W1 (plain), out2 = X@W2 + bias_nk[row&255,:] (+bias_k).
__global__ __launch_bounds__(256) void rowgemm8_dual_kernel(
    const float* __restrict__ X, const float* __restrict__ W1, const float* __restrict__ W2,
    const float* __restrict__ bias_nk, const float* __restrict__ bias_k,
    float* __restrict__ out1, float* __restrict__ out2)
{
    extern __shared__ float dsm[];
    float* xs  = dsm;          // 2048
    float* ws1 = dsm + 2048;   // 8192
    float* ws2 = dsm + 10240;  // 8192
    const int r0 = blockIdx.x * 8;
    const int t  = threadIdx.x;
    for (int f = t; f < 8 * 256; f += 256) xs[f] = X[r0 * 256 + f];

    float a1[8], a2[8];
#pragma unroll
    for (int r = 0; r < 8; ++r) { a1[r] = 0.f; a2[r] = 0.f; }

    for (int dt = 0; dt < 8; ++dt) {
        __syncthreads();
        const float4* W1v = reinterpret_cast<const float4*>(W1 + dt * 32 * 256);
        const float4* W2v = reinterpret_cast<const float4*>(W2 + dt * 32 * 256);
        float4* w1s = reinterpret_cast<float4*>(ws1);
        float4* w2s = reinterpret_cast<float4*>(ws2);
        for (int i = t; i < 2048; i += 256) { w1s[i] = __ldg(&W1v[i]); w2s[i] = __ldg(&W2v[i]); }
        __syncthreads();
#pragma unroll
        for (int d4 = 0; d4 < 32; d4 += 4) {
            float u0 = ws1[(d4 + 0) * 256 + t], v0 = ws2[(d4 + 0) * 256 + t];
            float u1 = ws1[(d4 + 1) * 256 + t], v1 = ws2[(d4 + 1) * 256 + t];
            float u2 = ws1[(d4 + 2) * 256 + t], v2 = ws2[(d4 + 2) * 256 + t];
            float u3 = ws1[(d4 + 3) * 256 + t], v3 = ws2[(d4 + 3) * 256 + t];
#pragma unroll
            for (int r = 0; r < 8; ++r) {
                const float4 xv = *reinterpret_cast<const float4*>(&xs[r * 256 + dt * 32 + d4]);
                a1[r] = fmaf(xv.x, u0, a1[r]); a2[r] = fmaf(xv.x, v0, a2[r]);
                a1[r] = fmaf(xv.y, u1, a1[r]); a2[r] = fmaf(xv.y, v1, a2[r]);
                a1[r] = fmaf(xv.z, u2, a1[r]); a2[r] = fmaf(xv.z, v2, a2[r]);
                a1[r] = fmaf(xv.w, u3, a1[r]); a2[r] = fmaf(xv.w, v3, a2[r]);
            }
        }
    }
    const float bk = bias_k ? __ldg(&bias_k[t]) : 0.f;
#pragma unroll
    for (int r = 0; r < 8; ++r) {
        const int row = r0 + r;
        out1[row * 256 + t] = a1[r];
        out2[row * 256 + t] = a2[r] + bk + __ldg(&bias_nk[(row & (PN - 1)) * 256 + t]);
    }
}

// ---------------------------------------------------------------------------
// Fused graph-learning kernel.
// ---------------------------------------------------------------------------
__global__ void pair_softadj_kernel(const float* __restrict__ xhat,
                                    const float* __restrict__ adj,
                                    const float* __restrict__ learn_w,
                                    const int*   __restrict__ box_num,
                                    float* __restrict__ soft_adj_out,
                                    float* __restrict__ adj2,
                                    float* __restrict__ pair_norm)
{
    const int row = blockIdx.x;
    const int b = row >> 8;
    const int i = row & 255;
    const int t = threadIdx.x;
    const int warp = t >> 5, lane = t & 31;

    __shared__ float xi_s[128];
    __shared__ float w_s[128];
    __shared__ float sval[256];
    __shared__ float red[256];
    __shared__ float wsum_s, rmax_s;

    if (t < 128) { xi_s[t] = xhat[row * 128 + t]; w_s[t] = learn_w[t]; }
    __syncthreads();
    if (t == 0) {
        float s = 0.f;
        for (int d = 0; d < 128; ++d) s += w_s[d];
        wsum_s = s;
    }
    __syncthreads();

    const int bn = box_num[b];
    const bool vi = (i < bn);
    const float wsum = wsum_s;
    const float4 xi4 = reinterpret_cast<const float4*>(xi_s)[lane];
    const float4 w4  = reinterpret_cast<const float4*>(w_s)[lane];

    for (int j = warp; j < 256; j += 8) {
        const float4 xj4 = __ldg(reinterpret_cast<const float4*>(xhat + (b * 256 + j) * 128) + lane);
        const float d0 = xi4.x - xj4.x, d1 = xi4.y - xj4.y;
        const float d2 = xi4.z - xj4.z, d3 = xi4.w - xj4.w;
        float s = fabsf(d0) * w4.x + fabsf(d1) * w4.y + fabsf(d2) * w4.z + fabsf(d3) * w4.w;
        float q = d0 * d0 + d1 * d1 + d2 * d2 + d3 * d3;
#pragma unroll
        for (int off = 16; off; off >>= 1) {
            s += __shfl_down_sync(0xffffffffu, s, off);
            q += __shfl_down_sync(0xffffffffu, q, off);
        }
        if (lane == 0) {
            const float m = (vi && (j < bn)) ? 0.f : -1.f;
            float v = s + m * wsum;
            v = (v > 0.f) ? v : 0.01f * v;
            sval[j] = v;
            pair_norm[row * 256 + j] = sqrtf(q + 1e-12f);
        }
    }
    __syncthreads();

    const float v = sval[t];
    red[t] = v;
    __syncthreads();
    for (int sft = 128; sft; sft >>= 1) {
        if (t < sft) red[t] = fmaxf(red[t], red[t + sft]);
        __syncthreads();
    }
    if (t == 0) rmax_s = red[0];
    __syncthreads();

    const float a = adj[row * 256 + t];
    const float e = expf(v - rmax_s) * a;
    red[t] = e;
    __syncthreads();
    for (int sft = 128; sft; sft >>= 1) {
        if (t < sft) red[t] += red[t + sft];
        __syncthreads();
    }
    const float sa = e / red[0] + 1e-10f;
    soft_adj_out[row * 256 + t] = sa;
    adj2[row * 256 + t] = a * sa;
}

// ---------------------------------------------------------------------------
__global__ void glloss_kernel(const float* __restrict__ soft_adj,
                              const float* __restrict__ pair_norm,
                              const int*   __restrict__ box_num,
                              float* __restrict__ gl_out)
{
    const int b = blockIdx.x;
    const int t = threadIdx.x;
    const float* sa = soft_adj + b * 65536;
    const float* pn = pair_norm + b * 65536;
    float s1 = 0.f, s2 = 0.f;
    for (int idx = t; idx < 65536; idx += 256) {
        const float s = sa[idx];
        s1 += expf(s + pn[idx]);
        s2 += s * s;
    }
    __shared__ float r1[256], r2[256];
    r1[t] = s1; r2[t] = s2;
    __syncthreads();
    for (int sft = 128; sft; sft >>= 1) {
        if (t < sft) { r1[t] += r1[t + sft]; r2[t] += r2[t + sft]; }
        __syncthreads();
    }
    if (t == 0) {
        const float bnf = (float)box_num[b];
        gl_out[b] = r1[0] / (bnf * bnf) + 1e-4f * sqrtf(r2[0]);
    }
}

// ---------------------------------------------------------------------------
// Fused GCN layer 0 with mma.sync split-bf16 GEMM (3 terms, fp32 accum).
// One block per (b,i); 256 threads (8 warps). Warp w owns j in [32w, 32w+32).
// For nc in {0,1} (n-chunks of 128), kh in {0,1} (k-halves of 128):
//   build H half (256j x 128k) as bf16 hi/lo in SMEM (+ AH0 accum on nc==0),
//   stage pre-split W images, HMMA-accumulate C (32j x 128n per warp).
// ---------------------------------------------------------------------------
// SMEM byte offsets
#define SM_A1      0
#define SM_A2      65536
#define SM_B1      131072
#define SM_B2      163840
#define SM_REL     196608
#define SM_WT      202752
#define SM_ADJ     208896
#define SM_AHRED   209920
#define SM_XI      214016
#define SM_TOTAL   215040

__global__ void __launch_bounds__(256, 1) layer0_mma_kernel(
    const float* __restrict__ xi0, const float* __restrict__ c0,
    const float* __restrict__ rel, const float* __restrict__ Wt,
    const float* __restrict__ adj2,
    float* __restrict__ alpha1, float* __restrict__ AH0)
{
    extern __shared__ char sm[];
    const uint32_t sb = smem_to_u32(sm);
    float* rel_s = reinterpret_cast<float*>(sm + SM_REL);
    float* wt_s  = reinterpret_cast<float*>(sm + SM_WT);
    float* adj_s = reinterpret_cast<float*>(sm + SM_ADJ);
    float* ahred = reinterpret_cast<float*>(sm + SM_AHRED);
    float* xi_s  = reinterpret_cast<float*>(sm + SM_XI);

    const int t = threadIdx.x;
    const int wid = t >> 5;
    const int lane = t & 31;
    const int row = blockIdx.x;      // b*256 + i
    const int b = row >> 8;

    // stage row-invariant data
    const float* relrow = rel + (size_t)row * 256 * 6;
    for (int f = t; f < 1536; f += 256) { rel_s[f] = relrow[f]; wt_s[f] = Wt[f]; }
    adj_s[t] = adj2[row * 256 + t];
    xi_s[t]  = xi0[row * 256 + t];

    const float* c0b = c0 + b * 65536;

    // --- per-lane ldmatrix address components ---
    // A (H): 16x16 tile at (j0, k0): lanes 0-15 rows, lanes 16-31 same rows col+8
    const int jrowA = (wid * 32) + (lane & 15);
    const uint32_t acol = (uint32_t)((lane >> 4) * 16);
    const uint32_t jmask = (uint32_t)((jrowA & 7) << 4);
    const uint32_t aRowByte = (uint32_t)jrowA * 256u;
    // B (W^T): x4 covers 2 n-tiles: n = nlocal + p*16
    const int nrow_l = (lane & 7) | ((lane & 16) >> 1);
    const uint32_t kbB = (uint32_t)(((lane >> 3) & 1) * 16);
    const uint32_t nmask = (uint32_t)((nrow_l & 7) << 4);
    const uint32_t bRowByte = (uint32_t)nrow_l * 256u;

    // build-phase mapping
    const int jg = wid;      // j group of 32
    const int bl = lane;     // k-pair lane

#pragma unroll 1
    for (int nc = 0; nc < 2; ++nc) {
        float C[2][16][4];
#pragma unroll
        for (int m = 0; m < 2; ++m)
#pragma unroll
            for (int nt = 0; nt < 16; ++nt)
#pragma unroll
                for (int u = 0; u < 4; ++u) C[m][nt][u] = 0.f;

#pragma unroll 1
        for (int kh = 0; kh < 2; ++kh) {
            __syncthreads();   // protect A/B smem from previous mma readers

            // ---- stage B slice (verbatim pre-swizzled copy) ----
            {
                const uint4* s1 = reinterpret_cast<const uint4*>(
                    reinterpret_cast<const char*>(g_wimg1) + kh * 65536 + nc * 32768);
                const uint4* s2 = reinterpret_cast<const uint4*>(
                    reinterpret_cast<const char*>(g_wimg2) + kh * 65536 + nc * 32768);
                uint4* d1 = reinterpret_cast<uint4*>(sm + SM_B1);
                uint4* d2 = reinterpret_cast<uint4*>(sm + SM_B2);
                for (int i = t; i < 2048; i += 256) { d1[i] = __ldg(&s1[i]); d2[i] = __ldg(&s2[i]); }
            }

            // ---- build H half (256j x 128k) split hi/lo ----
            {
                const int kA = 2 * bl;            // k (within half) for pair A
                const int kB = 2 * (bl + 32);     // pair B
                const float2 xivA = *reinterpret_cast<const float2*>(&xi_s[kh * 128 + kA]);
                const float2 xivB = *reinterpret_cast<const float2*>(&xi_s[kh * 128 + kB]);
                float2 wtA[6], wtB[6];
#pragma unroll
                for (int c = 0; c < 6; ++c) {
                    wtA[c] = *reinterpret_cast<const float2*>(&wt_s[c * 256 + kh * 128 + kA]);
                    wtB[c] = *reinterpret_cast<const float2*>(&wt_s[c * 256 + kh * 128 + kB]);
                }
                float ah0 = 0.f, ah1 = 0.f, ah2 = 0.f, ah3 = 0.f;
                const float2* c02 = reinterpret_cast<const float2*>(c0b);
#pragma unroll 2
                for (int s = 0; s < 32; ++s) {
                    const int j = jg * 32 + s;
                    const float* rj = rel_s + j * 6;
                    const float r0 = rj[0], r1 = rj[1], r2 = rj[2];
                    const float r3 = rj[3], r4 = rj[4], r5 = rj[5];
                    const float aw = adj_s[j];
                    const float2 cvA = __ldg(&c02[j * 128 + kh * 64 + bl]);
                    const float2 cvB = __ldg(&c02[j * 128 + kh * 64 + bl + 32]);
                    float aA0 = r0*wtA[0].x + r1*wtA[1].x + r2*wtA[2].x + r3*wtA[3].x + r4*wtA[4].x + r5*wtA[5].x;
                    float aA1 = r0*wtA[0].y + r1*wtA[1].y + r2*wtA[2].y + r3*wtA[3].y + r4*wtA[4].y + r5*wtA[5].y;
                    float aB0 = r0*wtB[0].x + r1*wtB[1].x + r2*wtB[2].x + r3*wtB[3].x + r4*wtB[4].x + r5*wtB[5].x;
                    float aB1 = r0*wtB[0].y + r1*wtB[1].y + r2*wtB[2].y + r3*wtB[3].y + r4*wtB[4].y + r5*wtB[5].y;
                    float hA0 = fmaxf(xivA.x + cvA.x + aA0, 0.f);
                    float hA1 = fmaxf(xivA.y + cvA.y + aA1, 0.f);
                    float hB0 = fmaxf(xivB.x + cvB.x + aB0, 0.f);
                    float hB1 = fmaxf(xivB.y + cvB.y + aB1, 0.f);
                    ah0 = fmaf(aw, hA0, ah0); ah1 = fmaf(aw, hA1, ah1);
                    ah2 = fmaf(aw, hB0, ah2); ah3 = fmaf(aw, hB1, ah3);

                    __nv_bfloat162 hiA, loA, hiB, loB;
                    hiA.x = __float2bfloat16_rn(hA0); hiA.y = __float2bfloat16_rn(hA1);
                    loA.x = __float2bfloat16_rn(hA0 - __bfloat162float(hiA.x));
                    loA.y = __float2bfloat16_rn(hA1 - __bfloat162float(hiA.y));
                    hiB.x = __float2bfloat16_rn(hB0); hiB.y = __float2bfloat16_rn(hB1);
                    loB.x = __float2bfloat16_rn(hB0 - __bfloat162float(hiB.x));
                    loB.y = __float2bfloat16_rn(hB1 - __bfloat162float(hiB.y));

                    const uint32_t jm = (uint32_t)((j & 7) << 4);
                    const uint32_t offA = (uint32_t)j * 256u + ((uint32_t)(4 * bl) ^ jm);
                    const uint32_t offB = (uint32_t)j * 256u + ((uint32_t)(4 * (bl + 32)) ^ jm);
                    *reinterpret_cast<uint32_t*>(sm + SM_A1 + offA) = *reinterpret_cast<uint32_t*>(&hiA);
                    *reinterpret_cast<uint32_t*>(sm + SM_A1 + offB) = *reinterpret_cast<uint32_t*>(&hiB);
                    *reinterpret_cast<uint32_t*>(sm + SM_A2 + offA) = *reinterpret_cast<uint32_t*>(&loA);
                    *reinterpret_cast<uint32_t*>(sm + SM_A2 + offB) = *reinterpret_cast<uint32_t*>(&loB);
                }
                if (nc == 0) {
                    ahred[jg * 128 + 2 * bl]      = ah0;
                    ahred[jg * 128 + 2 * bl + 1]  = ah1;
                    ahred[jg * 128 + 2 * bl + 64] = ah2;
                    ahred[jg * 128 + 2 * bl + 65] = ah3;
                }
            }
            __syncthreads();

            if (nc == 0 && t < 128) {
                float s = 0.f;
#pragma unroll
                for (int g = 0; g < 8; ++g) s += ahred[g * 128 + t];
                AH0[row * 256 + kh * 128 + t] = s;
            }

            // ---- HMMA: C += Hhi*Whi + Hhi*Wlo + Hlo*Whi ----
#pragma unroll 1
            for (int ks = 0; ks < 8; ++ks) {
                const uint32_t aoff = ((uint32_t)(ks * 32) + acol) ^ jmask;
                const uint32_t boff = ((uint32_t)(ks * 32) + kbB) ^ nmask;
                uint32_t Ah[2][4], Al[2][4];
                ldsm4(Ah[0], sb + SM_A1 + aRowByte + aoff);
                ldsm4(Ah[1], sb + SM_A1 + 4096 + aRowByte + aoff);
                ldsm4(Al[0], sb + SM_A2 + aRowByte + aoff);
                ldsm4(Al[1], sb + SM_A2 + 4096 + aRowByte + aoff);

                uint32_t bb[4];
#pragma unroll
                for (int p = 0; p < 8; ++p) {   // pass 1: Ah * Bhi
                    ldsm4(bb, sb + SM_B1 + (uint32_t)p * 4096 + bRowByte + boff);
                    mma_bf16(C[0][2 * p],     Ah[0], bb[0], bb[1]);
                    mma_bf16(C[1][2 * p],     Ah[1], bb[0], bb[1]);
                    mma_bf16(C[0][2 * p + 1], Ah[0], bb[2], bb[3]);
                    mma_bf16(C[1][2 * p + 1], Ah[1], bb[2], bb[3]);
                }
#pragma unroll
                for (int p = 0; p < 8; ++p) {   // pass 2: Ah * Blo
                    ldsm4(bb, sb + SM_B2 + (uint32_t)p * 4096 + bRowByte + boff);
                    mma_bf16(C[0][2 * p],     Ah[0], bb[0], bb[1]);
                    mma_bf16(C[1][2 * p],     Ah[1], bb[0], bb[1]);
                    mma_bf16(C[0][2 * p + 1], Ah[0], bb[2], bb[3]);
                    mma_bf16(C[1][2 * p + 1], Ah[1], bb[2], bb[3]);
                }
#pragma unroll
                for (int p = 0; p < 8; ++p) {   // pass 3: Al * Bhi
                    ldsm4(bb, sb + SM_B1 + (uint32_t)p * 4096 + bRowByte + boff);
                    mma_bf16(C[0][2 * p],     Al[0], bb[0], bb[1]);
                    mma_bf16(C[1][2 * p],     Al[1], bb[0], bb[1]);
                    mma_bf16(C[0][2 * p + 1], Al[0], bb[2], bb[3]);
                    mma_bf16(C[1][2 * p + 1], Al[1], bb[2], bb[3]);
                }
            }
        }

        // ---- writeback C (relu) -> alpha1 fp32 ----
        {
            const int r = lane >> 2;
            const int cq = (lane & 3) * 2;
#pragma unroll
            for (int m = 0; m < 2; ++m) {
#pragma unroll
                for (int nt = 0; nt < 16; ++nt) {
                    const int j = wid * 32 + m * 16 + r;
                    const int n = nc * 128 + nt * 8 + cq;
                    float* d0 = alpha1 + ((size_t)row * 256 + j) * 256 + n;
                    float2 v0, v1;
                    v0.x = fmaxf(C[m][nt][0], 0.f);
                    v0.y = fmaxf(C[m][nt][1], 0.f);
                    v1.x = fmaxf(C[m][nt][2], 0.f);
                    v1.y = fmaxf(C[m][nt][3], 0.f);
                    *reinterpret_cast<float2*>(d0) = v0;
                    *reinterpret_cast<float2*>(d0 + 8 * 256) = v1;
                }
            }
        }
    }
}

// ---------------------------------------------------------------------------
// GCN layer 1: AH1[i,k] = sum_j adj2[i,j]*relu(xi1[i,k]+c1[j,k]+alpha1[i,j,k])
// ---------------------------------------------------------------------------
__global__ void layer1_kernel(const float* __restrict__ xi1, const float* __restrict__ c1,
                              const float* __restrict__ alpha1,
                              const float* __restrict__ adj2,
                              float* __restrict__ AH1)
{
    const int row = blockIdx.x;
    const int b = row >> 8;
    const int t = threadIdx.x;           // 0..127 -> cols 2t, 2t+1
    __shared__ float adj_s[256];
    adj_s[t]       = adj2[row * 256 + t];
    adj_s[t + 128] = adj2[row * 256 + t + 128];
    const float2 xik = *reinterpret_cast<const float2*>(xi1 + row * 256 + 2 * t);
    __syncthreads();

    const float2* c1b = reinterpret_cast<const float2*>(c1 + b * 65536);
    const float2* al  = reinterpret_cast<const float2*>(alpha1 + (size_t)row * 65536);
    float ah0 = 0.f, ah1 = 0.f;
#pragma unroll 4
    for (int j = 0; j < 256; ++j) {
        const float2 c = __ldg(&c1b[j * 128 + t]);
        const float2 a = __ldg(&al[j * 128 + t]);
        const float h0 = fmaxf(xik.x + c.x + a.x, 0.f);
        const float h1 = fmaxf(xik.y + c.y + a.y, 0.f);
        const float w = adj_s[j];
        ah0 = fmaf(w, h0, ah0);
        ah1 = fmaf(w, h1, ah1);
    }
    float2 o; o.x = ah0; o.y = ah1;
    *reinterpret_cast<float2*>(AH1 + row * 256 + 2 * t) = o;
}

// ---------------------------------------------------------------------------
extern "C" void kernel_launch(void* const* d_in, const int* in_sizes, int n_in,
                              void* d_out, int out_size)
{
    (void)in_sizes; (void)n_in; (void)out_size;

    const float* x        = (const float*)d_in[0];
    const float* rel      = (const float*)d_in[1];
    const float* adj      = (const float*)d_in[2];
    const int*   bnum     = (const int*)  d_in[3];
    const float* Wt       = (const float*)d_in[4];
    const float* b_alpha  = (const float*)d_in[5];
    const float* W_proj   = (const float*)d_in[6];
    const float* b_proj   = (const float*)d_in[7];
    const float* learn_w  = (const float*)d_in[8];
    const float* w_alpha0 = (const float*)d_in[9];
    const float* w_vi0    = (const float*)d_in[10];
    const float* w_vj0    = (const float*)d_in[11];
    const float* bias_h0  = (const float*)d_in[12];
    const float* w_node0  = (const float*)d_in[13];
    /* d_in[14] = l1_w_alpha: unused (alpha2 discarded) */
    const float* w_vi1    = (const float*)d_in[15];
    const float* w_vj1    = (const float*)d_in[16];
    const float* bias_h1  = (const float*)d_in[17];
    const float* w_node1  = (const float*)d_in[18];

    float* out      = (float*)d_out;
    float* out_x2   = out;
    float* out_sadj = out + 262144;
    float* out_gl   = out + 524288;

    float *xhat, *pnorm, *adj2, *xi0, *c0, *AH0, *x1, *xi1, *c1, *AH1, *alpha1;
    cudaGetSymbolAddress((void**)&xhat,   g_xhat);
    cudaGetSymbolAddress((void**)&pnorm,  g_pnorm);
    cudaGetSymbolAddress((void**)&adj2,   g_adj2);
    cudaGetSymbolAddress((void**)&xi0,    g_xi0);
    cudaGetSymbolAddress((void**)&c0,     g_c0);
    cudaGetSymbolAddress((void**)&AH0,    g_AH0);
    cudaGetSymbolAddress((void**)&x1,     g_x1);
    cudaGetSymbolAddress((void**)&xi1,    g_xi1);
    cudaGetSymbolAddress((void**)&c1,     g_c1);
    cudaGetSymbolAddress((void**)&AH1,    g_AH1);
    cudaGetSymbolAddress((void**)&alpha1, g_alpha1);

    // ---- prep: split + transpose + swizzle w_alpha0 images ----
    prep_wsplit_kernel<<<256, 256>>>(w_alpha0);

    // ---- graph learning ----
    rowgemm_kernel<<<256, 128>>>(x, W_proj, b_proj, xhat);
    pair_softadj_kernel<<<1024, 256>>>(xhat, adj, learn_w, bnum, out_sadj, adj2, pnorm);
    glloss_kernel<<<4, 256>>>(out_sadj, pnorm, bnum, out_gl);

    // ---- GCN layer 0 ----
    const int DUAL_SMEM = 18432 * 4;
    cudaFuncSetAttribute(rowgemm8_dual_kernel, cudaFuncAttributeMaxDynamicSharedMemorySize, DUAL_SMEM);
    rowgemm8_dual_kernel<<<128, 256, DUAL_SMEM>>>(x, w_vi0, w_vj0, bias_h0, b_alpha, xi0, c0);

    cudaFuncSetAttribute(layer0_mma_kernel, cudaFuncAttributeMaxDynamicSharedMemorySize, SM_TOTAL);
    layer0_mma_kernel<<<1024, 256, SM_TOTAL>>>(xi0, c0, rel, Wt, adj2, alpha1, AH0);

    rowgemm8_kernel<<<128, 256>>>(AH0, w_node0, x1);

    // ---- GCN layer 1 ----
    rowgemm8_dual_kernel<<<128, 256, DUAL_SMEM>>>(x1, w_vi1, w_vj1, bias_h1, nullptr, xi1, c1);
    layer1_kernel<<<1024, 128>>>(xi1, c1, alpha1, adj2, AH1);
    rowgemm8_kernel<<<128, 256>>>(AH1, w_node1, out_x2);
}

// round 6
// speedup vs baseline: 2.2009x; 1.2399x over previous
#include <cuda_runtime.h>
#include <cuda_fp16.h>
#include <cstdint>
#include <cstddef>

// Problem constants
#define PB 4
#define PN 256
#define PD 256
#define PL 128
#define POUT 256

// ============================ helpers ============================
__device__ __forceinline__ uint32_t smem_to_u32(const void* smem_ptr) {
    uint32_t addr;
    asm("{ .reg .u64 tmp; cvta.to.shared.u64 tmp, %1; cvt.u32.u64 %0, tmp; }"
        : "=r"(addr) : "l"(smem_ptr));
    return addr;
}

__device__ __forceinline__ void ldsm4(uint32_t* r, uint32_t addr) {
    asm volatile("ldmatrix.sync.aligned.m8n8.x4.shared.b16 {%0,%1,%2,%3}, [%4];"
        : "=r"(r[0]), "=r"(r[1]), "=r"(r[2]), "=r"(r[3]) : "r"(addr));
}

__device__ __forceinline__ void mma_f16(float* c, const uint32_t* a, uint32_t b0, uint32_t b1) {
    asm volatile(
        "mma.sync.aligned.m16n8k16.row.col.f32.f16.f16.f32 "
        "{%0,%1,%2,%3}, {%4,%5,%6,%7}, {%8,%9}, {%0,%1,%2,%3};"
        : "+f"(c[0]), "+f"(c[1]), "+f"(c[2]), "+f"(c[3])
        : "r"(a[0]), "r"(a[1]), "r"(a[2]), "r"(a[3]), "r"(b0), "r"(b1));
}

// ---------------- scratch (device globals; no runtime allocation) ----------------
__device__ float g_xhat [PB*PN*PL];
__device__ float g_pnorm[PB*PN*PN];
__device__ float g_adj2 [PB*PN*PN];
__device__ float g_xi0  [PB*PN*POUT];
__device__ float g_c0   [PB*PN*POUT];
__device__ float g_AH0  [PB*PN*POUT];
__device__ float g_x1   [PB*PN*POUT];
__device__ float g_xi1  [PB*PN*POUT];
__device__ float g_c1   [PB*PN*POUT];
__device__ float g_AH1  [PB*PN*POUT];
__device__ float g_alpha1[(size_t)PB*PN*PN*POUT];        // 256 MB fp32
__device__ float g_part1[512];
__device__ float g_part2[512];
// Pre-split w_alpha images: [kh:2][n:256][k:128] fp16, 256B rows,
// XOR-swizzled by (n&7)<<4 -> ldmatrix conflict-free, verbatim staging.
// kh stride = 256 rows * 256 B = 65536 BYTES.
__device__ __half g_wimg1[2*256*128];                    // hi
__device__ __half g_wimg2[2*256*128];                    // lo residual

// ---------------------------------------------------------------------------
// Prep: split w_alpha0 (k=d:256, n:256) into fp16 hi/lo transposed images.
// ---------------------------------------------------------------------------
__global__ void prep_wsplit_kernel(const float* __restrict__ w_alpha)
{
    const int e = blockIdx.x * 256 + threadIdx.x;    // 65536
    const int k = e >> 8;
    const int n = e & 255;
    const float v = w_alpha[k * 256 + n];
    const __half hi = __float2half_rn(v);
    const __half lo = __float2half_rn(v - __half2float(hi));
    const int kh = k >> 7, kk = k & 127;
    const uint32_t off = kh * 65536u + n * 256u + (uint32_t)((kk * 2) ^ ((n & 7) << 4));
    *reinterpret_cast<__half*>(reinterpret_cast<char*>(g_wimg1) + off) = hi;
    *reinterpret_cast<__half*>(reinterpret_cast<char*>(g_wimg2) + off) = lo;
}

// ---------------------------------------------------------------------------
// Simple row GEMM for xhat (K=128)
// ---------------------------------------------------------------------------
__global__ void rowgemm_kernel(const float* __restrict__ X, const float* __restrict__ W,
                               const float* __restrict__ bias_k, float* __restrict__ out)
{
    __shared__ float xs[4 * 256];
    const int r0 = blockIdx.x * 4;
    const int t  = threadIdx.x;
    for (int f = t; f < 4 * 256; f += 128) xs[f] = X[r0 * 256 + f];
    __syncthreads();

    float acc[4] = {0.f, 0.f, 0.f, 0.f};
#pragma unroll 8
    for (int d = 0; d < 256; ++d) {
        const float wv = __ldg(&W[d * 128 + t]);
#pragma unroll
        for (int r = 0; r < 4; ++r) acc[r] = fmaf(xs[r * 256 + d], wv, acc[r]);
    }
    const float bk = __ldg(&bias_k[t]);
#pragma unroll
    for (int r = 0; r < 4; ++r) out[(r0 + r) * 128 + t] = acc[r] + bk;
}

// ---------------------------------------------------------------------------
// SMEM-tiled row GEMM (K=256): 8 rows/block, 256 threads, relu output.
// ---------------------------------------------------------------------------
__global__ __launch_bounds__(256) void rowgemm8_kernel(
    const float* __restrict__ X, const float* __restrict__ W, float* __restrict__ out)
{
    __shared__ float xs[8 * 256];
    __shared__ float ws[32 * 256];
    const int r0 = blockIdx.x * 8;
    const int t  = threadIdx.x;
    for (int f = t; f < 8 * 256; f += 256) xs[f] = X[r0 * 256 + f];

    float acc[8];
#pragma unroll
    for (int r = 0; r < 8; ++r) acc[r] = 0.f;

    for (int dt = 0; dt < 8; ++dt) {
        __syncthreads();
        const float4* Wv = reinterpret_cast<const float4*>(W + dt * 32 * 256);
        float4* wsv = reinterpret_cast<float4*>(ws);
        for (int i = t; i < 2048; i += 256) wsv[i] = __ldg(&Wv[i]);
        __syncthreads();
#pragma unroll
        for (int d4 = 0; d4 < 32; d4 += 4) {
            float wv0 = ws[(d4 + 0) * 256 + t];
            float wv1 = ws[(d4 + 1) * 256 + t];
            float wv2 = ws[(d4 + 2) * 256 + t];
            float wv3 = ws[(d4 + 3) * 256 + t];
#pragma unroll
            for (int r = 0; r < 8; ++r) {
                const float4 xv = *reinterpret_cast<const float4*>(&xs[r * 256 + dt * 32 + d4]);
                acc[r] = fmaf(xv.x, wv0, acc[r]);
                acc[r] = fmaf(xv.y, wv1, acc[r]);
                acc[r] = fmaf(xv.z, wv2, acc[r]);
                acc[r] = fmaf(xv.w, wv3, acc[r]);
            }
        }
    }
#pragma unroll
    for (int r = 0; r < 8; ++r) out[(r0 + r) * 256 + t] = fmaxf(acc[r], 0.f);
}

// Dual variant: out1 = X@W1 (plain), out2 = X@W2 + bias_nk[row&255,:] (+bias_k).
__global__ __launch_bounds__(256) void rowgemm8_dual_kernel(
    const float* __restrict__ X, const float* __restrict__ W1, const float* __restrict__ W2,
    const float* __restrict__ bias_nk, const float* __restrict__ bias_k,
    float* __restrict__ out1, float* __restrict__ out2)
{
    extern __shared__ float dsm[];
    float* xs  = dsm;          // 2048
    float* ws1 = dsm + 2048;   // 8192
    float* ws2 = dsm + 10240;  // 8192
    const int r0 = blockIdx.x * 8;
    const int t  = threadIdx.x;
    for (int f = t; f < 8 * 256; f += 256) xs[f] = X[r0 * 256 + f];

    float a1[8], a2[8];
#pragma unroll
    for (int r = 0; r < 8; ++r) { a1[r] = 0.f; a2[r] = 0.f; }

    for (int dt = 0; dt < 8; ++dt) {
        __syncthreads();
        const float4* W1v = reinterpret_cast<const float4*>(W1 + dt * 32 * 256);
        const float4* W2v = reinterpret_cast<const float4*>(W2 + dt * 32 * 256);
        float4* w1s = reinterpret_cast<float4*>(ws1);
        float4* w2s = reinterpret_cast<float4*>(ws2);
        for (int i = t; i < 2048; i += 256) { w1s[i] = __ldg(&W1v[i]); w2s[i] = __ldg(&W2v[i]); }
        __syncthreads();
#pragma unroll
        for (int d4 = 0; d4 < 32; d4 += 4) {
            float u0 = ws1[(d4 + 0) * 256 + t], v0 = ws2[(d4 + 0) * 256 + t];
            float u1 = ws1[(d4 + 1) * 256 + t], v1 = ws2[(d4 + 1) * 256 + t];
            float u2 = ws1[(d4 + 2) * 256 + t], v2 = ws2[(d4 + 2) * 256 + t];
            float u3 = ws1[(d4 + 3) * 256 + t], v3 = ws2[(d4 + 3) * 256 + t];
#pragma unroll
            for (int r = 0; r < 8; ++r) {
                const float4 xv = *reinterpret_cast<const float4*>(&xs[r * 256 + dt * 32 + d4]);
                a1[r] = fmaf(xv.x, u0, a1[r]); a2[r] = fmaf(xv.x, v0, a2[r]);
                a1[r] = fmaf(xv.y, u1, a1[r]); a2[r] = fmaf(xv.y, v1, a2[r]);
                a1[r] = fmaf(xv.z, u2, a1[r]); a2[r] = fmaf(xv.z, v2, a2[r]);
                a1[r] = fmaf(xv.w, u3, a1[r]); a2[r] = fmaf(xv.w, v3, a2[r]);
            }
        }
    }
    const float bk = bias_k ? __ldg(&bias_k[t]) : 0.f;
#pragma unroll
    for (int r = 0; r < 8; ++r) {
        const int row = r0 + r;
        out1[row * 256 + t] = a1[r];
        out2[row * 256 + t] = a2[r] + bk + __ldg(&bias_nk[(row & (PN - 1)) * 256 + t]);
    }
}

// ---------------------------------------------------------------------------
// Fused graph-learning kernel.
// ---------------------------------------------------------------------------
__global__ void pair_softadj_kernel(const float* __restrict__ xhat,
                                    const float* __restrict__ adj,
                                    const float* __restrict__ learn_w,
                                    const int*   __restrict__ box_num,
                                    float* __restrict__ soft_adj_out,
                                    float* __restrict__ adj2,
                                    float* __restrict__ pair_norm)
{
    const int row = blockIdx.x;
    const int b = row >> 8;
    const int i = row & 255;
    const int t = threadIdx.x;
    const int warp = t >> 5, lane = t & 31;

    __shared__ float xi_s[128];
    __shared__ float w_s[128];
    __shared__ float sval[256];
    __shared__ float red[256];
    __shared__ float wsum_s, rmax_s;

    if (t < 128) { xi_s[t] = xhat[row * 128 + t]; w_s[t] = learn_w[t]; }
    __syncthreads();
    if (t == 0) {
        float s = 0.f;
        for (int d = 0; d < 128; ++d) s += w_s[d];
        wsum_s = s;
    }
    __syncthreads();

    const int bn = box_num[b];
    const bool vi = (i < bn);
    const float wsum = wsum_s;
    const float4 xi4 = reinterpret_cast<const float4*>(xi_s)[lane];
    const float4 w4  = reinterpret_cast<const float4*>(w_s)[lane];

    for (int j = warp; j < 256; j += 8) {
        const float4 xj4 = __ldg(reinterpret_cast<const float4*>(xhat + (b * 256 + j) * 128) + lane);
        const float d0 = xi4.x - xj4.x, d1 = xi4.y - xj4.y;
        const float d2 = xi4.z - xj4.z, d3 = xi4.w - xj4.w;
        float s = fabsf(d0) * w4.x + fabsf(d1) * w4.y + fabsf(d2) * w4.z + fabsf(d3) * w4.w;
        float q = d0 * d0 + d1 * d1 + d2 * d2 + d3 * d3;
#pragma unroll
        for (int off = 16; off; off >>= 1) {
            s += __shfl_down_sync(0xffffffffu, s, off);
            q += __shfl_down_sync(0xffffffffu, q, off);
        }
        if (lane == 0) {
            const float m = (vi && (j < bn)) ? 0.f : -1.f;
            float v = s + m * wsum;
            v = (v > 0.f) ? v : 0.01f * v;
            sval[j] = v;
            pair_norm[row * 256 + j] = sqrtf(q + 1e-12f);
        }
    }
    __syncthreads();

    const float v = sval[t];
    red[t] = v;
    __syncthreads();
    for (int sft = 128; sft; sft >>= 1) {
        if (t < sft) red[t] = fmaxf(red[t], red[t + sft]);
        __syncthreads();
    }
    if (t == 0) rmax_s = red[0];
    __syncthreads();

    const float a = adj[row * 256 + t];
    const float e = expf(v - rmax_s) * a;
    red[t] = e;
    __syncthreads();
    for (int sft = 128; sft; sft >>= 1) {
        if (t < sft) red[t] += red[t + sft];
        __syncthreads();
    }
    const float sa = e / red[0] + 1e-10f;
    soft_adj_out[row * 256 + t] = sa;
    adj2[row * 256 + t] = a * sa;
}

// ---------------------------------------------------------------------------
// gl_loss: phase 1 — 512 blocks (128 per batch), 512 elements each.
// ---------------------------------------------------------------------------
__global__ void glloss_part_kernel(const float* __restrict__ soft_adj,
                                   const float* __restrict__ pair_norm)
{
    const int blk = blockIdx.x;               // b*128 + part
    const int b = blk >> 7;
    const int t = threadIdx.x;                // 256 threads
    const int base = b * 65536 + (blk & 127) * 512;
    float s1 = 0.f, s2 = 0.f;
#pragma unroll
    for (int u = 0; u < 2; ++u) {
        const int idx = base + u * 256 + t;
        const float s = soft_adj[idx];
        s1 += expf(s + pair_norm[idx]);       // ETA = 1.0
        s2 += s * s;
    }
    __shared__ float r1[256], r2[256];
    r1[t] = s1; r2[t] = s2;
    __syncthreads();
    for (int sft = 128; sft; sft >>= 1) {
        if (t < sft) { r1[t] += r1[t + sft]; r2[t] += r2[t + sft]; }
        __syncthreads();
    }
    if (t == 0) { g_part1[blk] = r1[0]; g_part2[blk] = r2[0]; }
}

__global__ void glloss_fin_kernel(const int* __restrict__ box_num, float* __restrict__ gl_out)
{
    const int b = blockIdx.x;
    const int t = threadIdx.x;                // 128 threads
    __shared__ float r1[128], r2[128];
    r1[t] = g_part1[b * 128 + t];
    r2[t] = g_part2[b * 128 + t];
    __syncthreads();
    for (int sft = 64; sft; sft >>= 1) {
        if (t < sft) { r1[t] += r1[t + sft]; r2[t] += r2[t + sft]; }
        __syncthreads();
    }
    if (t == 0) {
        const float bnf = (float)box_num[b];
        gl_out[b] = r1[0] / (bnf * bnf) + 1e-4f * sqrtf(r2[0]);   // GAMMA = 1e-4
    }
}

// ---------------------------------------------------------------------------
// Fused GCN layer 0, fp16 HMMA (A single fp16, B hi/lo fp16 -> 2 passes).
// One block per (b,i); 256 threads (8 warps). Warp w owns j in [32w, 32w+32).
// Build full H (256j x 256k fp16) ONCE; then nc(2) x kh(2) MMA accumulation.
// ---------------------------------------------------------------------------
// SMEM byte offsets
#define SM_A       0         // 256*512 = 131072 (fp16, 512B rows, xor-swizzled)
#define SM_B1      131072    // 32768
#define SM_B2      163840    // 32768
#define SM_REL     196608    // 6144
#define SM_WT      202752    // 6144
#define SM_ADJ     208896    // 1024
#define SM_AHRED   209920    // 8192
#define SM_XI      218112    // 1024
#define SM_TOTAL   219136

__global__ void __launch_bounds__(256, 1) layer0_mma_kernel(
    const float* __restrict__ xi0, const float* __restrict__ c0,
    const float* __restrict__ rel, const float* __restrict__ Wt,
    const float* __restrict__ adj2,
    float* __restrict__ alpha1, float* __restrict__ AH0)
{
    extern __shared__ char sm[];
    const uint32_t sb = smem_to_u32(sm);
    float* rel_s = reinterpret_cast<float*>(sm + SM_REL);
    float* wt_s  = reinterpret_cast<float*>(sm + SM_WT);
    float* adj_s = reinterpret_cast<float*>(sm + SM_ADJ);
    float* ahred = reinterpret_cast<float*>(sm + SM_AHRED);
    float* xi_s  = reinterpret_cast<float*>(sm + SM_XI);

    const int t = threadIdx.x;
    const int wid = t >> 5;
    const int lane = t & 31;
    const int row = blockIdx.x;      // b*256 + i
    const int b = row >> 8;

    // stage row-invariant data
    const float* relrow = rel + (size_t)row * 256 * 6;
    for (int f = t; f < 1536; f += 256) { rel_s[f] = relrow[f]; wt_s[f] = Wt[f]; }
    adj_s[t] = adj2[row * 256 + t];
    xi_s[t]  = xi0[row * 256 + t];
    __syncthreads();

    const float* c0b = c0 + b * 65536;
    const int jg = wid;
    const int bl = lane;

    // ---- build full H (256j x 256k) as fp16, AH0 accumulation ----
#pragma unroll
    for (int kq = 0; kq < 4; ++kq) {
        const int p = bl + 32 * kq;       // k-pair index 0..127
        const int k = 2 * p;
        const float2 xiv = *reinterpret_cast<const float2*>(&xi_s[k]);
        float2 wtv[6];
#pragma unroll
        for (int c = 0; c < 6; ++c)
            wtv[c] = *reinterpret_cast<const float2*>(&wt_s[c * 256 + k]);

        float ah0 = 0.f, ah1 = 0.f;
        const float2* c02 = reinterpret_cast<const float2*>(c0b);
#pragma unroll 2
        for (int s = 0; s < 32; ++s) {
            const int j = jg * 32 + s;
            const float* rj = rel_s + j * 6;
            const float2 cv = __ldg(&c02[j * 128 + p]);
            float a0 = rj[0]*wtv[0].x + rj[1]*wtv[1].x + rj[2]*wtv[2].x
                     + rj[3]*wtv[3].x + rj[4]*wtv[4].x + rj[5]*wtv[5].x;
            float a1 = rj[0]*wtv[0].y + rj[1]*wtv[1].y + rj[2]*wtv[2].y
                     + rj[3]*wtv[3].y + rj[4]*wtv[4].y + rj[5]*wtv[5].y;
            const float h0 = fmaxf(xiv.x + cv.x + a0, 0.f);
            const float h1 = fmaxf(xiv.y + cv.y + a1, 0.f);
            const float aw = adj_s[j];
            ah0 = fmaf(aw, h0, ah0);
            ah1 = fmaf(aw, h1, ah1);
            __half2 hp;
            hp.x = __float2half_rn(h0);
            hp.y = __float2half_rn(h1);
            const uint32_t off = (uint32_t)j * 512u + ((uint32_t)(4 * p) ^ ((uint32_t)(j & 7) << 4));
            *reinterpret_cast<uint32_t*>(sm + SM_A + off) = *reinterpret_cast<uint32_t*>(&hp);
        }
        ahred[jg * 256 + k]     = ah0;
        ahred[jg * 256 + k + 1] = ah1;
    }
    __syncthreads();

    {
        float s = 0.f;
#pragma unroll
        for (int g = 0; g < 8; ++g) s += ahred[g * 256 + t];
        AH0[row * 256 + t] = s;
    }

    // --- per-lane ldmatrix address components ---
    const int jrowA = (wid * 32) + (lane & 15);
    const uint32_t acolByte = (uint32_t)((lane >> 4) * 16);
    const uint32_t jmask = (uint32_t)((jrowA & 7) << 4);
    const uint32_t aRowByte = (uint32_t)jrowA * 512u;
    const int nrow_l = (lane & 7) | ((lane & 16) >> 1);
    const uint32_t kbB = (uint32_t)(((lane >> 3) & 1) * 16);
    const uint32_t nmask = (uint32_t)((nrow_l & 7) << 4);
    const uint32_t bRowByte = (uint32_t)nrow_l * 256u;

#pragma unroll 1
    for (int nc = 0; nc < 2; ++nc) {
        float C[2][16][4];
#pragma unroll
        for (int m = 0; m < 2; ++m)
#pragma unroll
            for (int nt = 0; nt < 16; ++nt)
#pragma unroll
                for (int u = 0; u < 4; ++u) C[m][nt][u] = 0.f;

#pragma unroll 1
        for (int kh = 0; kh < 2; ++kh) {
            __syncthreads();   // B reuse guard
            // ---- stage B slice (verbatim pre-swizzled copy) ----
            // kh stride = 65536 BYTES ([n:256][k:128] fp16 = 256B rows x 256 rows).
            {
                const uint4* s1 = reinterpret_cast<const uint4*>(
                    reinterpret_cast<const char*>(g_wimg1) + kh * 65536 + nc * 32768);
                const uint4* s2 = reinterpret_cast<const uint4*>(
                    reinterpret_cast<const char*>(g_wimg2) + kh * 65536 + nc * 32768);
                uint4* d1 = reinterpret_cast<uint4*>(sm + SM_B1);
                uint4* d2 = reinterpret_cast<uint4*>(sm + SM_B2);
                for (int i = t; i < 2048; i += 256) { d1[i] = __ldg(&s1[i]); d2[i] = __ldg(&s2[i]); }
            }
            __syncthreads();

            // ---- HMMA: C += Ah*Bhi + Ah*Blo ----
#pragma unroll 1
            for (int ks = 0; ks < 8; ++ks) {
                const uint32_t aoff = ((uint32_t)((kh * 8 + ks) * 32) + acolByte) ^ jmask;
                const uint32_t boff = ((uint32_t)(ks * 32) + kbB) ^ nmask;
                uint32_t Ah[2][4];
                ldsm4(Ah[0], sb + SM_A + aRowByte + aoff);
                ldsm4(Ah[1], sb + SM_A + 8192 + aRowByte + aoff);

                uint32_t bb[4];
#pragma unroll
                for (int p = 0; p < 8; ++p) {   // pass 1: A * Bhi
                    ldsm4(bb, sb + SM_B1 + (uint32_t)p * 4096 + bRowByte + boff);
                    mma_f16(C[0][2 * p],     Ah[0], bb[0], bb[1]);
                    mma_f16(C[1][2 * p],     Ah[1], bb[0], bb[1]);
                    mma_f16(C[0][2 * p + 1], Ah[0], bb[2], bb[3]);
                    mma_f16(C[1][2 * p + 1], Ah[1], bb[2], bb[3]);
                }
#pragma unroll
                for (int p = 0; p < 8; ++p) {   // pass 2: A * Blo
                    ldsm4(bb, sb + SM_B2 + (uint32_t)p * 4096 + bRowByte + boff);
                    mma_f16(C[0][2 * p],     Ah[0], bb[0], bb[1]);
                    mma_f16(C[1][2 * p],     Ah[1], bb[0], bb[1]);
                    mma_f16(C[0][2 * p + 1], Ah[0], bb[2], bb[3]);
                    mma_f16(C[1][2 * p + 1], Ah[1], bb[2], bb[3]);
                }
            }
        }

        // ---- writeback C (relu) -> alpha1 fp32 ----
        {
            const int r = lane >> 2;
            const int cq = (lane & 3) * 2;
#pragma unroll
            for (int m = 0; m < 2; ++m) {
#pragma unroll
                for (int nt = 0; nt < 16; ++nt) {
                    const int j = wid * 32 + m * 16 + r;
                    const int n = nc * 128 + nt * 8 + cq;
                    float* d0 = alpha1 + ((size_t)row * 256 + j) * 256 + n;
                    float2 v0, v1;
                    v0.x = fmaxf(C[m][nt][0], 0.f);
                    v0.y = fmaxf(C[m][nt][1], 0.f);
                    v1.x = fmaxf(C[m][nt][2], 0.f);
                    v1.y = fmaxf(C[m][nt][3], 0.f);
                    *reinterpret_cast<float2*>(d0) = v0;
                    *reinterpret_cast<float2*>(d0 + 8 * 256) = v1;
                }
            }
        }
    }
}

// ---------------------------------------------------------------------------
// GCN layer 1: AH1[i,k] = sum_j adj2[i,j]*relu(xi1[i,k]+c1[j,k]+alpha1[i,j,k])
// ---------------------------------------------------------------------------
__global__ void layer1_kernel(const float* __restrict__ xi1, const float* __restrict__ c1,
                              const float* __restrict__ alpha1,
                              const float* __restrict__ adj2,
                              float* __restrict__ AH1)
{
    const int row = blockIdx.x;
    const int b = row >> 8;
    const int t = threadIdx.x;           // 0..127 -> cols 2t, 2t+1
    __shared__ float adj_s[256];
    adj_s[t]       = adj2[row * 256 + t];
    adj_s[t + 128] = adj2[row * 256 + t + 128];
    const float2 xik = *reinterpret_cast<const float2*>(xi1 + row * 256 + 2 * t);
    __syncthreads();

    const float2* c1b = reinterpret_cast<const float2*>(c1 + b * 65536);
    const float2* al  = reinterpret_cast<const float2*>(alpha1 + (size_t)row * 65536);
    float ah0 = 0.f, ah1 = 0.f;
#pragma unroll 4
    for (int j = 0; j < 256; ++j) {
        const float2 c = __ldg(&c1b[j * 128 + t]);
        const float2 a = __ldg(&al[j * 128 + t]);
        const float h0 = fmaxf(xik.x + c.x + a.x, 0.f);
        const float h1 = fmaxf(xik.y + c.y + a.y, 0.f);
        const float w = adj_s[j];
        ah0 = fmaf(w, h0, ah0);
        ah1 = fmaf(w, h1, ah1);
    }
    float2 o; o.x = ah0; o.y = ah1;
    *reinterpret_cast<float2*>(AH1 + row * 256 + 2 * t) = o;
}

// ---------------------------------------------------------------------------
extern "C" void kernel_launch(void* const* d_in, const int* in_sizes, int n_in,
                              void* d_out, int out_size)
{
    (void)in_sizes; (void)n_in; (void)out_size;

    const float* x        = (const float*)d_in[0];
    const float* rel      = (const float*)d_in[1];
    const float* adj      = (const float*)d_in[2];
    const int*   bnum     = (const int*)  d_in[3];
    const float* Wt       = (const float*)d_in[4];
    const float* b_alpha  = (const float*)d_in[5];
    const float* W_proj   = (const float*)d_in[6];
    const float* b_proj   = (const float*)d_in[7];
    const float* learn_w  = (const float*)d_in[8];
    const float* w_alpha0 = (const float*)d_in[9];
    const float* w_vi0    = (const float*)d_in[10];
    const float* w_vj0    = (const float*)d_in[11];
    const float* bias_h0  = (const float*)d_in[12];
    const float* w_node0  = (const float*)d_in[13];
    /* d_in[14] = l1_w_alpha: unused (alpha2 discarded) */
    const float* w_vi1    = (const float*)d_in[15];
    const float* w_vj1    = (const float*)d_in[16];
    const float* bias_h1  = (const float*)d_in[17];
    const float* w_node1  = (const float*)d_in[18];

    float* out      = (float*)d_out;
    float* out_x2   = out;
    float* out_sadj = out + 262144;
    float* out_gl   = out + 524288;

    float *xhat, *pnorm, *adj2, *xi0, *c0, *AH0, *x1, *xi1, *c1, *AH1, *alpha1;
    cudaGetSymbolAddress((void**)&xhat,   g_xhat);
    cudaGetSymbolAddress((void**)&pnorm,  g_pnorm);
    cudaGetSymbolAddress((void**)&adj2,   g_adj2);
    cudaGetSymbolAddress((void**)&xi0,    g_xi0);
    cudaGetSymbolAddress((void**)&c0,     g_c0);
    cudaGetSymbolAddress((void**)&AH0,    g_AH0);
    cudaGetSymbolAddress((void**)&x1,     g_x1);
    cudaGetSymbolAddress((void**)&xi1,    g_xi1);
    cudaGetSymbolAddress((void**)&c1,     g_c1);
    cudaGetSymbolAddress((void**)&AH1,    g_AH1);
    cudaGetSymbolAddress((void**)&alpha1, g_alpha1);

    // ---- prep: split + transpose + swizzle w_alpha0 images ----
    prep_wsplit_kernel<<<256, 256>>>(w_alpha0);

    // ---- graph learning ----
    rowgemm_kernel<<<256, 128>>>(x, W_proj, b_proj, xhat);
    pair_softadj_kernel<<<1024, 256>>>(xhat, adj, learn_w, bnum, out_sadj, adj2, pnorm);
    glloss_part_kernel<<<512, 256>>>(out_sadj, pnorm);
    glloss_fin_kernel<<<4, 128>>>(bnum, out_gl);

    // ---- GCN layer 0 ----
    const int DUAL_SMEM = 18432 * 4;
    cudaFuncSetAttribute(rowgemm8_dual_kernel, cudaFuncAttributeMaxDynamicSharedMemorySize, DUAL_SMEM);
    rowgemm8_dual_kernel<<<128, 256, DUAL_SMEM>>>(x, w_vi0, w_vj0, bias_h0, b_alpha, xi0, c0);

    cudaFuncSetAttribute(layer0_mma_kernel, cudaFuncAttributeMaxDynamicSharedMemorySize, SM_TOTAL);
    layer0_mma_kernel<<<1024, 256, SM_TOTAL>>>(xi0, c0, rel, Wt, adj2, alpha1, AH0);

    rowgemm8_kernel<<<128, 256>>>(AH0, w_node0, x1);

    // ---- GCN layer 1 ----
    rowgemm8_dual_kernel<<<128, 256, DUAL_SMEM>>>(x1, w_vi1, w_vj1, bias_h1, nullptr, xi1, c1);
    layer1_kernel<<<1024, 128>>>(xi1, c1, alpha1, adj2, AH1);
    rowgemm8_kernel<<<128, 256>>>(AH1, w_node1, out_x2);
}

// round 7
// speedup vs baseline: 2.7362x; 1.2432x over previous
#include <cuda_runtime.h>
#include <cuda_fp16.h>
#include <cstdint>
#include <cstddef>

// Problem constants
#define PB 4
#define PN 256
#define PD 256
#define PL 128
#define POUT 256

// ============================ helpers ============================
__device__ __forceinline__ uint32_t smem_to_u32(const void* smem_ptr) {
    uint32_t addr;
    asm("{ .reg .u64 tmp; cvta.to.shared.u64 tmp, %1; cvt.u32.u64 %0, tmp; }"
        : "=r"(addr) : "l"(smem_ptr));
    return addr;
}

__device__ __forceinline__ void ldsm4(uint32_t* r, uint32_t addr) {
    asm volatile("ldmatrix.sync.aligned.m8n8.x4.shared.b16 {%0,%1,%2,%3}, [%4];"
        : "=r"(r[0]), "=r"(r[1]), "=r"(r[2]), "=r"(r[3]) : "r"(addr));
}

__device__ __forceinline__ void mma_f16(float* c, const uint32_t* a, uint32_t b0, uint32_t b1) {
    asm volatile(
        "mma.sync.aligned.m16n8k16.row.col.f32.f16.f16.f32 "
        "{%0,%1,%2,%3}, {%4,%5,%6,%7}, {%8,%9}, {%0,%1,%2,%3};"
        : "+f"(c[0]), "+f"(c[1]), "+f"(c[2]), "+f"(c[3])
        : "r"(a[0]), "r"(a[1]), "r"(a[2]), "r"(a[3]), "r"(b0), "r"(b1));
}

// ---------------- scratch (device globals; no runtime allocation) ----------------
__device__ float g_xhat [PB*PN*PL];
__device__ float g_pnorm[PB*PN*PN];
__device__ float g_adj2 [PB*PN*PN];
__device__ float g_xi0  [PB*PN*POUT];
__device__ float g_c0   [PB*PN*POUT];
__device__ float g_AH0  [PB*PN*POUT];
__device__ float g_x1   [PB*PN*POUT];
__device__ float g_xi1  [PB*PN*POUT];
__device__ float g_c1   [PB*PN*POUT];
__device__ float g_AH1  [PB*PN*POUT];
__device__ __half g_alpha1[(size_t)PB*PN*PN*POUT];       // 128 MB fp16
__device__ float g_part1[512];
__device__ float g_part2[512];
// Pre-converted w_alpha image: [kh:2][n:256][k:128] fp16, 256B rows,
// XOR-swizzled by (n&7)<<4 -> ldmatrix conflict-free, verbatim staging.
// kh stride = 256 rows * 256 B = 65536 BYTES.
__device__ __half g_wimg1[2*256*128];

// ---------------------------------------------------------------------------
// Prep: convert w_alpha0 (k=d:256, n:256) into fp16 transposed image.
// ---------------------------------------------------------------------------
__global__ void prep_w_kernel(const float* __restrict__ w_alpha)
{
    const int e = blockIdx.x * 256 + threadIdx.x;    // 65536
    const int k = e >> 8;
    const int n = e & 255;
    const __half hi = __float2half_rn(w_alpha[k * 256 + n]);
    const int kh = k >> 7, kk = k & 127;
    const uint32_t off = kh * 65536u + n * 256u + (uint32_t)((kk * 2) ^ ((n & 7) << 4));
    *reinterpret_cast<__half*>(reinterpret_cast<char*>(g_wimg1) + off) = hi;
}

// ---------------------------------------------------------------------------
// Simple row GEMM for xhat (K=128)
// ---------------------------------------------------------------------------
__global__ void rowgemm_kernel(const float* __restrict__ X, const float* __restrict__ W,
                               const float* __restrict__ bias_k, float* __restrict__ out)
{
    __shared__ float xs[4 * 256];
    const int r0 = blockIdx.x * 4;
    const int t  = threadIdx.x;
    for (int f = t; f < 4 * 256; f += 128) xs[f] = X[r0 * 256 + f];
    __syncthreads();

    float acc[4] = {0.f, 0.f, 0.f, 0.f};
#pragma unroll 8
    for (int d = 0; d < 256; ++d) {
        const float wv = __ldg(&W[d * 128 + t]);
#pragma unroll
        for (int r = 0; r < 4; ++r) acc[r] = fmaf(xs[r * 256 + d], wv, acc[r]);
    }
    const float bk = __ldg(&bias_k[t]);
#pragma unroll
    for (int r = 0; r < 4; ++r) out[(r0 + r) * 128 + t] = acc[r] + bk;
}

// ---------------------------------------------------------------------------
// SMEM-tiled row GEMM (K=256): 8 rows/block, 256 threads, relu output.
// ---------------------------------------------------------------------------
__global__ __launch_bounds__(256) void rowgemm8_kernel(
    const float* __restrict__ X, const float* __restrict__ W, float* __restrict__ out)
{
    __shared__ float xs[8 * 256];
    __shared__ float ws[32 * 256];
    const int r0 = blockIdx.x * 8;
    const int t  = threadIdx.x;
    for (int f = t; f < 8 * 256; f += 256) xs[f] = X[r0 * 256 + f];

    float acc[8];
#pragma unroll
    for (int r = 0; r < 8; ++r) acc[r] = 0.f;

    for (int dt = 0; dt < 8; ++dt) {
        __syncthreads();
        const float4* Wv = reinterpret_cast<const float4*>(W + dt * 32 * 256);
        float4* wsv = reinterpret_cast<float4*>(ws);
        for (int i = t; i < 2048; i += 256) wsv[i] = __ldg(&Wv[i]);
        __syncthreads();
#pragma unroll
        for (int d4 = 0; d4 < 32; d4 += 4) {
            float wv0 = ws[(d4 + 0) * 256 + t];
            float wv1 = ws[(d4 + 1) * 256 + t];
            float wv2 = ws[(d4 + 2) * 256 + t];
            float wv3 = ws[(d4 + 3) * 256 + t];
#pragma unroll
            for (int r = 0; r < 8; ++r) {
                const float4 xv = *reinterpret_cast<const float4*>(&xs[r * 256 + dt * 32 + d4]);
                acc[r] = fmaf(xv.x, wv0, acc[r]);
                acc[r] = fmaf(xv.y, wv1, acc[r]);
                acc[r] = fmaf(xv.z, wv2, acc[r]);
                acc[r] = fmaf(xv.w, wv3, acc[r]);
            }
        }
    }
#pragma unroll
    for (int r = 0; r < 8; ++r) out[(r0 + r) * 256 + t] = fmaxf(acc[r], 0.f);
}

// Dual variant: out1 = X@W1 (plain), out2 = X@W2 + bias_nk[row&255,:] (+bias_k).
__global__ __launch_bounds__(256) void rowgemm8_dual_kernel(
    const float* __restrict__ X, const float* __restrict__ W1, const float* __restrict__ W2,
    const float* __restrict__ bias_nk, const float* __restrict__ bias_k,
    float* __restrict__ out1, float* __restrict__ out2)
{
    extern __shared__ float dsm[];
    float* xs  = dsm;          // 2048
    float* ws1 = dsm + 2048;   // 8192
    float* ws2 = dsm + 10240;  // 8192
    const int r0 = blockIdx.x * 8;
    const int t  = threadIdx.x;
    for (int f = t; f < 8 * 256; f += 256) xs[f] = X[r0 * 256 + f];

    float a1[8], a2[8];
#pragma unroll
    for (int r = 0; r < 8; ++r) { a1[r] = 0.f; a2[r] = 0.f; }

    for (int dt = 0; dt < 8; ++dt) {
        __syncthreads();
        const float4* W1v = reinterpret_cast<const float4*>(W1 + dt * 32 * 256);
        const float4* W2v = reinterpret_cast<const float4*>(W2 + dt * 32 * 256);
        float4* w1s = reinterpret_cast<float4*>(ws1);
        float4* w2s = reinterpret_cast<float4*>(ws2);
        for (int i = t; i < 2048; i += 256) { w1s[i] = __ldg(&W1v[i]); w2s[i] = __ldg(&W2v[i]); }
        __syncthreads();
#pragma unroll
        for (int d4 = 0; d4 < 32; d4 += 4) {
            float u0 = ws1[(d4 + 0) * 256 + t], v0 = ws2[(d4 + 0) * 256 + t];
            float u1 = ws1[(d4 + 1) * 256 + t], v1 = ws2[(d4 + 1) * 256 + t];
            float u2 = ws1[(d4 + 2) * 256 + t], v2 = ws2[(d4 + 2) * 256 + t];
            float u3 = ws1[(d4 + 3) * 256 + t], v3 = ws2[(d4 + 3) * 256 + t];
#pragma unroll
            for (int r = 0; r < 8; ++r) {
                const float4 xv = *reinterpret_cast<const float4*>(&xs[r * 256 + dt * 32 + d4]);
                a1[r] = fmaf(xv.x, u0, a1[r]); a2[r] = fmaf(xv.x, v0, a2[r]);
                a1[r] = fmaf(xv.y, u1, a1[r]); a2[r] = fmaf(xv.y, v1, a2[r]);
                a1[r] = fmaf(xv.z, u2, a1[r]); a2[r] = fmaf(xv.z, v2, a2[r]);
                a1[r] = fmaf(xv.w, u3, a1[r]); a2[r] = fmaf(xv.w, v3, a2[r]);
            }
        }
    }
    const float bk = bias_k ? __ldg(&bias_k[t]) : 0.f;
#pragma unroll
    for (int r = 0; r < 8; ++r) {
        const int row = r0 + r;
        out1[row * 256 + t] = a1[r];
        out2[row * 256 + t] = a2[r] + bk + __ldg(&bias_nk[(row & (PN - 1)) * 256 + t]);
    }
}

// ---------------------------------------------------------------------------
// Fused graph-learning kernel.
// ---------------------------------------------------------------------------
__global__ void pair_softadj_kernel(const float* __restrict__ xhat,
                                    const float* __restrict__ adj,
                                    const float* __restrict__ learn_w,
                                    const int*   __restrict__ box_num,
                                    float* __restrict__ soft_adj_out,
                                    float* __restrict__ adj2,
                                    float* __restrict__ pair_norm)
{
    const int row = blockIdx.x;
    const int b = row >> 8;
    const int i = row & 255;
    const int t = threadIdx.x;
    const int warp = t >> 5, lane = t & 31;

    __shared__ float xi_s[128];
    __shared__ float w_s[128];
    __shared__ float sval[256];
    __shared__ float red[256];
    __shared__ float wsum_s, rmax_s;

    if (t < 128) { xi_s[t] = xhat[row * 128 + t]; w_s[t] = learn_w[t]; }
    __syncthreads();
    if (t == 0) {
        float s = 0.f;
        for (int d = 0; d < 128; ++d) s += w_s[d];
        wsum_s = s;
    }
    __syncthreads();

    const int bn = box_num[b];
    const bool vi = (i < bn);
    const float wsum = wsum_s;
    const float4 xi4 = reinterpret_cast<const float4*>(xi_s)[lane];
    const float4 w4  = reinterpret_cast<const float4*>(w_s)[lane];

    for (int j = warp; j < 256; j += 8) {
        const float4 xj4 = __ldg(reinterpret_cast<const float4*>(xhat + (b * 256 + j) * 128) + lane);
        const float d0 = xi4.x - xj4.x, d1 = xi4.y - xj4.y;
        const float d2 = xi4.z - xj4.z, d3 = xi4.w - xj4.w;
        float s = fabsf(d0) * w4.x + fabsf(d1) * w4.y + fabsf(d2) * w4.z + fabsf(d3) * w4.w;
        float q = d0 * d0 + d1 * d1 + d2 * d2 + d3 * d3;
#pragma unroll
        for (int off = 16; off; off >>= 1) {
            s += __shfl_down_sync(0xffffffffu, s, off);
            q += __shfl_down_sync(0xffffffffu, q, off);
        }
        if (lane == 0) {
            const float m = (vi && (j < bn)) ? 0.f : -1.f;
            float v = s + m * wsum;
            v = (v > 0.f) ? v : 0.01f * v;
            sval[j] = v;
            pair_norm[row * 256 + j] = sqrtf(q + 1e-12f);
        }
    }
    __syncthreads();

    const float v = sval[t];
    red[t] = v;
    __syncthreads();
    for (int sft = 128; sft; sft >>= 1) {
        if (t < sft) red[t] = fmaxf(red[t], red[t + sft]);
        __syncthreads();
    }
    if (t == 0) rmax_s = red[0];
    __syncthreads();

    const float a = adj[row * 256 + t];
    const float e = expf(v - rmax_s) * a;
    red[t] = e;
    __syncthreads();
    for (int sft = 128; sft; sft >>= 1) {
        if (t < sft) red[t] += red[t + sft];
        __syncthreads();
    }
    const float sa = e / red[0] + 1e-10f;
    soft_adj_out[row * 256 + t] = sa;
    adj2[row * 256 + t] = a * sa;
}

// ---------------------------------------------------------------------------
// gl_loss: phase 1 — 512 blocks (128 per batch), 512 elements each.
// ---------------------------------------------------------------------------
__global__ void glloss_part_kernel(const float* __restrict__ soft_adj,
                                   const float* __restrict__ pair_norm)
{
    const int blk = blockIdx.x;               // b*128 + part
    const int b = blk >> 7;
    const int t = threadIdx.x;                // 256 threads
    const int base = b * 65536 + (blk & 127) * 512;
    float s1 = 0.f, s2 = 0.f;
#pragma unroll
    for (int u = 0; u < 2; ++u) {
        const int idx = base + u * 256 + t;
        const float s = soft_adj[idx];
        s1 += expf(s + pair_norm[idx]);       // ETA = 1.0
        s2 += s * s;
    }
    __shared__ float r1[256], r2[256];
    r1[t] = s1; r2[t] = s2;
    __syncthreads();
    for (int sft = 128; sft; sft >>= 1) {
        if (t < sft) { r1[t] += r1[t + sft]; r2[t] += r2[t + sft]; }
        __syncthreads();
    }
    if (t == 0) { g_part1[blk] = r1[0]; g_part2[blk] = r2[0]; }
}

__global__ void glloss_fin_kernel(const int* __restrict__ box_num, float* __restrict__ gl_out)
{
    const int b = blockIdx.x;
    const int t = threadIdx.x;                // 128 threads
    __shared__ float r1[128], r2[128];
    r1[t] = g_part1[b * 128 + t];
    r2[t] = g_part2[b * 128 + t];
    __syncthreads();
    for (int sft = 64; sft; sft >>= 1) {
        if (t < sft) { r1[t] += r1[t + sft]; r2[t] += r2[t + sft]; }
        __syncthreads();
    }
    if (t == 0) {
        const float bnf = (float)box_num[b];
        gl_out[b] = r1[0] / (bnf * bnf) + 1e-4f * sqrtf(r2[0]);   // GAMMA = 1e-4
    }
}

// ---------------------------------------------------------------------------
// Fused GCN layer 0, fp16 HMMA single-pass (A fp16, B fp16).
// One block per (b,i); 256 threads (8 warps). Warp w owns j in [32w, 32w+32).
// Build full H (256j x 256k fp16) ONCE; then nc(2) x kh(2) MMA accumulation.
// alpha1 written as fp16.
// ---------------------------------------------------------------------------
// SMEM byte offsets
#define SM_A       0         // 256*512 = 131072 (fp16, 512B rows, xor-swizzled)
#define SM_B1      131072    // 32768
#define SM_REL     163840    // 6144
#define SM_WT      169984    // 6144
#define SM_ADJ     176128    // 1024
#define SM_AHRED   177152    // 8192
#define SM_XI      185344    // 1024
#define SM_TOTAL   186368

__global__ void __launch_bounds__(256, 1) layer0_mma_kernel(
    const float* __restrict__ xi0, const float* __restrict__ c0,
    const float* __restrict__ rel, const float* __restrict__ Wt,
    const float* __restrict__ adj2,
    __half* __restrict__ alpha1, float* __restrict__ AH0)
{
    extern __shared__ char sm[];
    const uint32_t sb = smem_to_u32(sm);
    float* rel_s = reinterpret_cast<float*>(sm + SM_REL);
    float* wt_s  = reinterpret_cast<float*>(sm + SM_WT);
    float* adj_s = reinterpret_cast<float*>(sm + SM_ADJ);
    float* ahred = reinterpret_cast<float*>(sm + SM_AHRED);
    float* xi_s  = reinterpret_cast<float*>(sm + SM_XI);

    const int t = threadIdx.x;
    const int wid = t >> 5;
    const int lane = t & 31;
    const int row = blockIdx.x;      // b*256 + i
    const int b = row >> 8;

    // stage row-invariant data
    const float* relrow = rel + (size_t)row * 256 * 6;
    for (int f = t; f < 1536; f += 256) { rel_s[f] = relrow[f]; wt_s[f] = Wt[f]; }
    adj_s[t] = adj2[row * 256 + t];
    xi_s[t]  = xi0[row * 256 + t];
    __syncthreads();

    const float* c0b = c0 + b * 65536;
    const int jg = wid;
    const int bl = lane;

    // ---- build full H (256j x 256k) as fp16, AH0 accumulation ----
#pragma unroll
    for (int kq = 0; kq < 4; ++kq) {
        const int p = bl + 32 * kq;       // k-pair index 0..127
        const int k = 2 * p;
        const float2 xiv = *reinterpret_cast<const float2*>(&xi_s[k]);
        float2 wtv[6];
#pragma unroll
        for (int c = 0; c < 6; ++c)
            wtv[c] = *reinterpret_cast<const float2*>(&wt_s[c * 256 + k]);

        float ah0 = 0.f, ah1 = 0.f;
        const float2* c02 = reinterpret_cast<const float2*>(c0b);
#pragma unroll 2
        for (int s = 0; s < 32; ++s) {
            const int j = jg * 32 + s;
            const float* rj = rel_s + j * 6;
            const float2 cv = __ldg(&c02[j * 128 + p]);
            float a0 = rj[0]*wtv[0].x + rj[1]*wtv[1].x + rj[2]*wtv[2].x
                     + rj[3]*wtv[3].x + rj[4]*wtv[4].x + rj[5]*wtv[5].x;
            float a1 = rj[0]*wtv[0].y + rj[1]*wtv[1].y + rj[2]*wtv[2].y
                     + rj[3]*wtv[3].y + rj[4]*wtv[4].y + rj[5]*wtv[5].y;
            const float h0 = fmaxf(xiv.x + cv.x + a0, 0.f);
            const float h1 = fmaxf(xiv.y + cv.y + a1, 0.f);
            const float aw = adj_s[j];
            ah0 = fmaf(aw, h0, ah0);
            ah1 = fmaf(aw, h1, ah1);
            __half2 hp;
            hp.x = __float2half_rn(h0);
            hp.y = __float2half_rn(h1);
            const uint32_t off = (uint32_t)j * 512u + ((uint32_t)(4 * p) ^ ((uint32_t)(j & 7) << 4));
            *reinterpret_cast<uint32_t*>(sm + SM_A + off) = *reinterpret_cast<uint32_t*>(&hp);
        }
        ahred[jg * 256 + k]     = ah0;
        ahred[jg * 256 + k + 1] = ah1;
    }
    __syncthreads();

    {
        float s = 0.f;
#pragma unroll
        for (int g = 0; g < 8; ++g) s += ahred[g * 256 + t];
        AH0[row * 256 + t] = s;
    }

    // --- per-lane ldmatrix address components ---
    const int jrowA = (wid * 32) + (lane & 15);
    const uint32_t acolByte = (uint32_t)((lane >> 4) * 16);
    const uint32_t jmask = (uint32_t)((jrowA & 7) << 4);
    const uint32_t aRowByte = (uint32_t)jrowA * 512u;
    const int nrow_l = (lane & 7) | ((lane & 16) >> 1);
    const uint32_t kbB = (uint32_t)(((lane >> 3) & 1) * 16);
    const uint32_t nmask = (uint32_t)((nrow_l & 7) << 4);
    const uint32_t bRowByte = (uint32_t)nrow_l * 256u;

#pragma unroll 1
    for (int nc = 0; nc < 2; ++nc) {
        float C[2][16][4];
#pragma unroll
        for (int m = 0; m < 2; ++m)
#pragma unroll
            for (int nt = 0; nt < 16; ++nt)
#pragma unroll
                for (int u = 0; u < 4; ++u) C[m][nt][u] = 0.f;

#pragma unroll 1
        for (int kh = 0; kh < 2; ++kh) {
            __syncthreads();   // B reuse guard
            // ---- stage B slice (verbatim pre-swizzled copy) ----
            // kh stride = 65536 BYTES ([n:256][k:128] fp16 = 256B rows x 256 rows).
            {
                const uint4* s1 = reinterpret_cast<const uint4*>(
                    reinterpret_cast<const char*>(g_wimg1) + kh * 65536 + nc * 32768);
                uint4* d1 = reinterpret_cast<uint4*>(sm + SM_B1);
                for (int i = t; i < 2048; i += 256) d1[i] = __ldg(&s1[i]);
            }
            __syncthreads();

            // ---- HMMA: C += A * B (single pass) ----
#pragma unroll 1
            for (int ks = 0; ks < 8; ++ks) {
                const uint32_t aoff = ((uint32_t)((kh * 8 + ks) * 32) + acolByte) ^ jmask;
                const uint32_t boff = ((uint32_t)(ks * 32) + kbB) ^ nmask;
                uint32_t Ah[2][4];
                ldsm4(Ah[0], sb + SM_A + aRowByte + aoff);
                ldsm4(Ah[1], sb + SM_A + 8192 + aRowByte + aoff);

                uint32_t bb[4];
#pragma unroll
                for (int p = 0; p < 8; ++p) {
                    ldsm4(bb, sb + SM_B1 + (uint32_t)p * 4096 + bRowByte + boff);
                    mma_f16(C[0][2 * p],     Ah[0], bb[0], bb[1]);
                    mma_f16(C[1][2 * p],     Ah[1], bb[0], bb[1]);
                    mma_f16(C[0][2 * p + 1], Ah[0], bb[2], bb[3]);
                    mma_f16(C[1][2 * p + 1], Ah[1], bb[2], bb[3]);
                }
            }
        }

        // ---- writeback C (relu) -> alpha1 fp16 ----
        {
            const int r = lane >> 2;
            const int cq = (lane & 3) * 2;
#pragma unroll
            for (int m = 0; m < 2; ++m) {
#pragma unroll
                for (int nt = 0; nt < 16; ++nt) {
                    const int j = wid * 32 + m * 16 + r;
                    const int n = nc * 128 + nt * 8 + cq;
                    __half* d0 = alpha1 + ((size_t)row * 256 + j) * 256 + n;
                    __half2 v0, v1;
                    v0.x = __float2half_rn(fmaxf(C[m][nt][0], 0.f));
                    v0.y = __float2half_rn(fmaxf(C[m][nt][1], 0.f));
                    v1.x = __float2half_rn(fmaxf(C[m][nt][2], 0.f));
                    v1.y = __float2half_rn(fmaxf(C[m][nt][3], 0.f));
                    *reinterpret_cast<__half2*>(d0) = v0;
                    *reinterpret_cast<__half2*>(d0 + 8 * 256) = v1;
                }
            }
        }
    }
}

// ---------------------------------------------------------------------------
// GCN layer 1: AH1[i,k] = sum_j adj2[i,j]*relu(xi1[i,k]+c1[j,k]+alpha1[i,j,k])
// alpha1 read as fp16 pairs.
// ---------------------------------------------------------------------------
__global__ void layer1_kernel(const float* __restrict__ xi1, const float* __restrict__ c1,
                              const __half* __restrict__ alpha1,
                              const float* __restrict__ adj2,
                              float* __restrict__ AH1)
{
    const int row = blockIdx.x;
    const int b = row >> 8;
    const int t = threadIdx.x;           // 0..127 -> cols 2t, 2t+1
    __shared__ float adj_s[256];
    adj_s[t]       = adj2[row * 256 + t];
    adj_s[t + 128] = adj2[row * 256 + t + 128];
    const float2 xik = *reinterpret_cast<const float2*>(xi1 + row * 256 + 2 * t);
    __syncthreads();

    const float2* c1b = reinterpret_cast<const float2*>(c1 + b * 65536);
    const __half2* al = reinterpret_cast<const __half2*>(alpha1 + (size_t)row * 65536);
    float ah0 = 0.f, ah1 = 0.f;
#pragma unroll 4
    for (int j = 0; j < 256; ++j) {
        const float2 c = __ldg(&c1b[j * 128 + t]);
        const float2 a = __half22float2(__ldg(&al[j * 128 + t]));
        const float h0 = fmaxf(xik.x + c.x + a.x, 0.f);
        const float h1 = fmaxf(xik.y + c.y + a.y, 0.f);
        const float w = adj_s[j];
        ah0 = fmaf(w, h0, ah0);
        ah1 = fmaf(w, h1, ah1);
    }
    float2 o; o.x = ah0; o.y = ah1;
    *reinterpret_cast<float2*>(AH1 + row * 256 + 2 * t) = o;
}

// ---------------------------------------------------------------------------
extern "C" void kernel_launch(void* const* d_in, const int* in_sizes, int n_in,
                              void* d_out, int out_size)
{
    (void)in_sizes; (void)n_in; (void)out_size;

    const float* x        = (const float*)d_in[0];
    const float* rel      = (const float*)d_in[1];
    const float* adj      = (const float*)d_in[2];
    const int*   bnum     = (const int*)  d_in[3];
    const float* Wt       = (const float*)d_in[4];
    const float* b_alpha  = (const float*)d_in[5];
    const float* W_proj   = (const float*)d_in[6];
    const float* b_proj   = (const float*)d_in[7];
    const float* learn_w  = (const float*)d_in[8];
    const float* w_alpha0 = (const float*)d_in[9];
    const float* w_vi0    = (const float*)d_in[10];
    const float* w_vj0    = (const float*)d_in[11];
    const float* bias_h0  = (const float*)d_in[12];
    const float* w_node0  = (const float*)d_in[13];
    /* d_in[14] = l1_w_alpha: unused (alpha2 discarded) */
    const float* w_vi1    = (const float*)d_in[15];
    const float* w_vj1    = (const float*)d_in[16];
    const float* bias_h1  = (const float*)d_in[17];
    const float* w_node1  = (const float*)d_in[18];

    float* out      = (float*)d_out;
    float* out_x2   = out;
    float* out_sadj = out + 262144;
    float* out_gl   = out + 524288;

    float *xhat, *pnorm, *adj2, *xi0, *c0, *AH0, *x1, *xi1, *c1, *AH1;
    __half* alpha1;
    cudaGetSymbolAddress((void**)&xhat,   g_xhat);
    cudaGetSymbolAddress((void**)&pnorm,  g_pnorm);
    cudaGetSymbolAddress((void**)&adj2,   g_adj2);
    cudaGetSymbolAddress((void**)&xi0,    g_xi0);
    cudaGetSymbolAddress((void**)&c0,     g_c0);
    cudaGetSymbolAddress((void**)&AH0,    g_AH0);
    cudaGetSymbolAddress((void**)&x1,     g_x1);
    cudaGetSymbolAddress((void**)&xi1,    g_xi1);
    cudaGetSymbolAddress((void**)&c1,     g_c1);
    cudaGetSymbolAddress((void**)&AH1,    g_AH1);
    cudaGetSymbolAddress((void**)&alpha1, g_alpha1);

    // ---- prep: convert + transpose + swizzle w_alpha0 image ----
    prep_w_kernel<<<256, 256>>>(w_alpha0);

    // ---- graph learning ----
    rowgemm_kernel<<<256, 128>>>(x, W_proj, b_proj, xhat);
    pair_softadj_kernel<<<1024, 256>>>(xhat, adj, learn_w, bnum, out_sadj, adj2, pnorm);
    glloss_part_kernel<<<512, 256>>>(out_sadj, pnorm);
    glloss_fin_kernel<<<4, 128>>>(bnum, out_gl);

    // ---- GCN layer 0 ----
    const int DUAL_SMEM = 18432 * 4;
    cudaFuncSetAttribute(rowgemm8_dual_kernel, cudaFuncAttributeMaxDynamicSharedMemorySize, DUAL_SMEM);
    rowgemm8_dual_kernel<<<128, 256, DUAL_SMEM>>>(x, w_vi0, w_vj0, bias_h0, b_alpha, xi0, c0);

    cudaFuncSetAttribute(layer0_mma_kernel, cudaFuncAttributeMaxDynamicSharedMemorySize, SM_TOTAL);
    layer0_mma_kernel<<<1024, 256, SM_TOTAL>>>(xi0, c0, rel, Wt, adj2, alpha1, AH0);

    rowgemm8_kernel<<<128, 256>>>(AH0, w_node0, x1);

    // ---- GCN layer 1 ----
    rowgemm8_dual_kernel<<<128, 256, DUAL_SMEM>>>(x1, w_vi1, w_vj1, bias_h1, nullptr, xi1, c1);
    layer1_kernel<<<1024, 128>>>(xi1, c1, alpha1, adj2, AH1);
    rowgemm8_kernel<<<128, 256>>>(AH1, w_node1, out_x2);
}

// round 8
// speedup vs baseline: 3.0848x; 1.1274x over previous
#include <cuda_runtime.h>
#include <cuda_fp16.h>
#include <cstdint>
#include <cstddef>

// Problem constants
#define PB 4
#define PN 256
#define PD 256
#define PL 128
#define POUT 256

// ============================ helpers ============================
__device__ __forceinline__ uint32_t smem_to_u32(const void* smem_ptr) {
    uint32_t addr;
    asm("{ .reg .u64 tmp; cvta.to.shared.u64 tmp, %1; cvt.u32.u64 %0, tmp; }"
        : "=r"(addr) : "l"(smem_ptr));
    return addr;
}

__device__ __forceinline__ void ldsm4(uint32_t* r, uint32_t addr) {
    asm volatile("ldmatrix.sync.aligned.m8n8.x4.shared.b16 {%0,%1,%2,%3}, [%4];"
        : "=r"(r[0]), "=r"(r[1]), "=r"(r[2]), "=r"(r[3]) : "r"(addr));
}

__device__ __forceinline__ void mma_f16(float* c, const uint32_t* a, uint32_t b0, uint32_t b1) {
    asm volatile(
        "mma.sync.aligned.m16n8k16.row.col.f32.f16.f16.f32 "
        "{%0,%1,%2,%3}, {%4,%5,%6,%7}, {%8,%9}, {%0,%1,%2,%3};"
        : "+f"(c[0]), "+f"(c[1]), "+f"(c[2]), "+f"(c[3])
        : "r"(a[0]), "r"(a[1]), "r"(a[2]), "r"(a[3]), "r"(b0), "r"(b1));
}

// ---------------- scratch (device globals; no runtime allocation) ----------------
__device__ float g_xhat [PB*PN*PL];
__device__ float g_pnorm[PB*PN*PN];
__device__ float g_adj2 [PB*PN*PN];
__device__ float g_xi0  [PB*PN*POUT];
__device__ float g_c0   [PB*PN*POUT];
__device__ float g_AH0  [PB*PN*POUT];
__device__ float g_x1   [PB*PN*POUT];
__device__ float g_xi1  [PB*PN*POUT];
__device__ float g_c1   [PB*PN*POUT];
__device__ float g_AH1  [PB*PN*POUT];
__device__ float g_part1[512];
__device__ float g_part2[512];
// Pre-converted w_alpha image: [kh:2][n:256][k:128] fp16, 256B rows,
// XOR-swizzled by (n&7)<<4 -> ldmatrix conflict-free, verbatim staging.
// kh stride = 256 rows * 256 B = 65536 BYTES.
__device__ __half g_wimg1[2*256*128];

// ---------------------------------------------------------------------------
// Prep: convert w_alpha0 (k=d:256, n:256) into fp16 transposed image.
// ---------------------------------------------------------------------------
__global__ void prep_w_kernel(const float* __restrict__ w_alpha)
{
    const int e = blockIdx.x * 256 + threadIdx.x;    // 65536
    const int k = e >> 8;
    const int n = e & 255;
    const __half hi = __float2half_rn(w_alpha[k * 256 + n]);
    const int kh = k >> 7, kk = k & 127;
    const uint32_t off = kh * 65536u + n * 256u + (uint32_t)((kk * 2) ^ ((n & 7) << 4));
    *reinterpret_cast<__half*>(reinterpret_cast<char*>(g_wimg1) + off) = hi;
}

// ---------------------------------------------------------------------------
// Simple row GEMM for xhat (K=128)
// ---------------------------------------------------------------------------
__global__ void rowgemm_kernel(const float* __restrict__ X, const float* __restrict__ W,
                               const float* __restrict__ bias_k, float* __restrict__ out)
{
    __shared__ float xs[4 * 256];
    const int r0 = blockIdx.x * 4;
    const int t  = threadIdx.x;
    for (int f = t; f < 4 * 256; f += 128) xs[f] = X[r0 * 256 + f];
    __syncthreads();

    float acc[4] = {0.f, 0.f, 0.f, 0.f};
#pragma unroll 8
    for (int d = 0; d < 256; ++d) {
        const float wv = __ldg(&W[d * 128 + t]);
#pragma unroll
        for (int r = 0; r < 4; ++r) acc[r] = fmaf(xs[r * 256 + d], wv, acc[r]);
    }
    const float bk = __ldg(&bias_k[t]);
#pragma unroll
    for (int r = 0; r < 4; ++r) out[(r0 + r) * 128 + t] = acc[r] + bk;
}

// ---------------------------------------------------------------------------
// SMEM-tiled row GEMM (K=256): 8 rows/block, 256 threads, relu output.
// ---------------------------------------------------------------------------
__global__ __launch_bounds__(256) void rowgemm8_kernel(
    const float* __restrict__ X, const float* __restrict__ W, float* __restrict__ out)
{
    __shared__ float xs[8 * 256];
    __shared__ float ws[32 * 256];
    const int r0 = blockIdx.x * 8;
    const int t  = threadIdx.x;
    for (int f = t; f < 8 * 256; f += 256) xs[f] = X[r0 * 256 + f];

    float acc[8];
#pragma unroll
    for (int r = 0; r < 8; ++r) acc[r] = 0.f;

    for (int dt = 0; dt < 8; ++dt) {
        __syncthreads();
        const float4* Wv = reinterpret_cast<const float4*>(W + dt * 32 * 256);
        float4* wsv = reinterpret_cast<float4*>(ws);
        for (int i = t; i < 2048; i += 256) wsv[i] = __ldg(&Wv[i]);
        __syncthreads();
#pragma unroll
        for (int d4 = 0; d4 < 32; d4 += 4) {
            float wv0 = ws[(d4 + 0) * 256 + t];
            float wv1 = ws[(d4 + 1) * 256 + t];
            float wv2 = ws[(d4 + 2) * 256 + t];
            float wv3 = ws[(d4 + 3) * 256 + t];
#pragma unroll
            for (int r = 0; r < 8; ++r) {
                const float4 xv = *reinterpret_cast<const float4*>(&xs[r * 256 + dt * 32 + d4]);
                acc[r] = fmaf(xv.x, wv0, acc[r]);
                acc[r] = fmaf(xv.y, wv1, acc[r]);
                acc[r] = fmaf(xv.z, wv2, acc[r]);
                acc[r] = fmaf(xv.w, wv3, acc[r]);
            }
        }
    }
#pragma unroll
    for (int r = 0; r < 8; ++r) out[(r0 + r) * 256 + t] = fmaxf(acc[r], 0.f);
}

// Dual variant: out1 = X@W1 (plain), out2 = X@W2 + bias_nk[row&255,:] (+bias_k).
__global__ __launch_bounds__(256) void rowgemm8_dual_kernel(
    const float* __restrict__ X, const float* __restrict__ W1, const float* __restrict__ W2,
    const float* __restrict__ bias_nk, const float* __restrict__ bias_k,
    float* __restrict__ out1, float* __restrict__ out2)
{
    extern __shared__ float dsm[];
    float* xs  = dsm;          // 2048
    float* ws1 = dsm + 2048;   // 8192
    float* ws2 = dsm + 10240;  // 8192
    const int r0 = blockIdx.x * 8;
    const int t  = threadIdx.x;
    for (int f = t; f < 8 * 256; f += 256) xs[f] = X[r0 * 256 + f];

    float a1[8], a2[8];
#pragma unroll
    for (int r = 0; r < 8; ++r) { a1[r] = 0.f; a2[r] = 0.f; }

    for (int dt = 0; dt < 8; ++dt) {
        __syncthreads();
        const float4* W1v = reinterpret_cast<const float4*>(W1 + dt * 32 * 256);
        const float4* W2v = reinterpret_cast<const float4*>(W2 + dt * 32 * 256);
        float4* w1s = reinterpret_cast<float4*>(ws1);
        float4* w2s = reinterpret_cast<float4*>(ws2);
        for (int i = t; i < 2048; i += 256) { w1s[i] = __ldg(&W1v[i]); w2s[i] = __ldg(&W2v[i]); }
        __syncthreads();
#pragma unroll
        for (int d4 = 0; d4 < 32; d4 += 4) {
            float u0 = ws1[(d4 + 0) * 256 + t], v0 = ws2[(d4 + 0) * 256 + t];
            float u1 = ws1[(d4 + 1) * 256 + t], v1 = ws2[(d4 + 1) * 256 + t];
            float u2 = ws1[(d4 + 2) * 256 + t], v2 = ws2[(d4 + 2) * 256 + t];
            float u3 = ws1[(d4 + 3) * 256 + t], v3 = ws2[(d4 + 3) * 256 + t];
#pragma unroll
            for (int r = 0; r < 8; ++r) {
                const float4 xv = *reinterpret_cast<const float4*>(&xs[r * 256 + dt * 32 + d4]);
                a1[r] = fmaf(xv.x, u0, a1[r]); a2[r] = fmaf(xv.x, v0, a2[r]);
                a1[r] = fmaf(xv.y, u1, a1[r]); a2[r] = fmaf(xv.y, v1, a2[r]);
                a1[r] = fmaf(xv.z, u2, a1[r]); a2[r] = fmaf(xv.z, v2, a2[r]);
                a1[r] = fmaf(xv.w, u3, a1[r]); a2[r] = fmaf(xv.w, v3, a2[r]);
            }
        }
    }
    const float bk = bias_k ? __ldg(&bias_k[t]) : 0.f;
#pragma unroll
    for (int r = 0; r < 8; ++r) {
        const int row = r0 + r;
        out1[row * 256 + t] = a1[r];
        out2[row * 256 + t] = a2[r] + bk + __ldg(&bias_nk[(row & (PN - 1)) * 256 + t]);
    }
}

// ---------------------------------------------------------------------------
// Fused graph-learning kernel.
// ---------------------------------------------------------------------------
__global__ void pair_softadj_kernel(const float* __restrict__ xhat,
                                    const float* __restrict__ adj,
                                    const float* __restrict__ learn_w,
                                    const int*   __restrict__ box_num,
                                    float* __restrict__ soft_adj_out,
                                    float* __restrict__ adj2,
                                    float* __restrict__ pair_norm)
{
    const int row = blockIdx.x;
    const int b = row >> 8;
    const int i = row & 255;
    const int t = threadIdx.x;
    const int warp = t >> 5, lane = t & 31;

    __shared__ float xi_s[128];
    __shared__ float w_s[128];
    __shared__ float sval[256];
    __shared__ float red[256];
    __shared__ float wsum_s, rmax_s;

    if (t < 128) { xi_s[t] = xhat[row * 128 + t]; w_s[t] = learn_w[t]; }
    __syncthreads();
    if (t == 0) {
        float s = 0.f;
        for (int d = 0; d < 128; ++d) s += w_s[d];
        wsum_s = s;
    }
    __syncthreads();

    const int bn = box_num[b];
    const bool vi = (i < bn);
    const float wsum = wsum_s;
    const float4 xi4 = reinterpret_cast<const float4*>(xi_s)[lane];
    const float4 w4  = reinterpret_cast<const float4*>(w_s)[lane];

    for (int j = warp; j < 256; j += 8) {
        const float4 xj4 = __ldg(reinterpret_cast<const float4*>(xhat + (b * 256 + j) * 128) + lane);
        const float d0 = xi4.x - xj4.x, d1 = xi4.y - xj4.y;
        const float d2 = xi4.z - xj4.z, d3 = xi4.w - xj4.w;
        float s = fabsf(d0) * w4.x + fabsf(d1) * w4.y + fabsf(d2) * w4.z + fabsf(d3) * w4.w;
        float q = d0 * d0 + d1 * d1 + d2 * d2 + d3 * d3;
#pragma unroll
        for (int off = 16; off; off >>= 1) {
            s += __shfl_down_sync(0xffffffffu, s, off);
            q += __shfl_down_sync(0xffffffffu, q, off);
        }
        if (lane == 0) {
            const float m = (vi && (j < bn)) ? 0.f : -1.f;
            float v = s + m * wsum;
            v = (v > 0.f) ? v : 0.01f * v;
            sval[j] = v;
            pair_norm[row * 256 + j] = sqrtf(q + 1e-12f);
        }
    }
    __syncthreads();

    const float v = sval[t];
    red[t] = v;
    __syncthreads();
    for (int sft = 128; sft; sft >>= 1) {
        if (t < sft) red[t] = fmaxf(red[t], red[t + sft]);
        __syncthreads();
    }
    if (t == 0) rmax_s = red[0];
    __syncthreads();

    const float a = adj[row * 256 + t];
    const float e = expf(v - rmax_s) * a;
    red[t] = e;
    __syncthreads();
    for (int sft = 128; sft; sft >>= 1) {
        if (t < sft) red[t] += red[t + sft];
        __syncthreads();
    }
    const float sa = e / red[0] + 1e-10f;
    soft_adj_out[row * 256 + t] = sa;
    adj2[row * 256 + t] = a * sa;
}

// ---------------------------------------------------------------------------
// gl_loss: phase 1 — 512 blocks (128 per batch), 512 elements each.
// ---------------------------------------------------------------------------
__global__ void glloss_part_kernel(const float* __restrict__ soft_adj,
                                   const float* __restrict__ pair_norm)
{
    const int blk = blockIdx.x;               // b*128 + part
    const int b = blk >> 7;
    const int t = threadIdx.x;                // 256 threads
    const int base = b * 65536 + (blk & 127) * 512;
    float s1 = 0.f, s2 = 0.f;
#pragma unroll
    for (int u = 0; u < 2; ++u) {
        const int idx = base + u * 256 + t;
        const float s = soft_adj[idx];
        s1 += expf(s + pair_norm[idx]);       // ETA = 1.0
        s2 += s * s;
    }
    __shared__ float r1[256], r2[256];
    r1[t] = s1; r2[t] = s2;
    __syncthreads();
    for (int sft = 128; sft; sft >>= 1) {
        if (t < sft) { r1[t] += r1[t + sft]; r2[t] += r2[t + sft]; }
        __syncthreads();
    }
    if (t == 0) { g_part1[blk] = r1[0]; g_part2[blk] = r2[0]; }
}

__global__ void glloss_fin_kernel(const int* __restrict__ box_num, float* __restrict__ gl_out)
{
    const int b = blockIdx.x;
    const int t = threadIdx.x;                // 128 threads
    __shared__ float r1[128], r2[128];
    r1[t] = g_part1[b * 128 + t];
    r2[t] = g_part2[b * 128 + t];
    __syncthreads();
    for (int sft = 64; sft; sft >>= 1) {
        if (t < sft) { r1[t] += r1[t + sft]; r2[t] += r2[t + sft]; }
        __syncthreads();
    }
    if (t == 0) {
        const float bnf = (float)box_num[b];
        gl_out[b] = r1[0] / (bnf * bnf) + 1e-4f * sqrtf(r2[0]);   // GAMMA = 1e-4
    }
}

// ---------------------------------------------------------------------------
// Kernel A: AH0 only. H built on the fly, never stored. Light smem -> high occ.
// One block per (b,i); 256 threads. AH0[i,k] = sum_j adj2[i,j]*relu(H[j,k]).
// ---------------------------------------------------------------------------
__global__ __launch_bounds__(256) void ah0_kernel(
    const float* __restrict__ xi0, const float* __restrict__ c0,
    const float* __restrict__ rel, const float* __restrict__ Wt,
    const float* __restrict__ adj2, float* __restrict__ AH0)
{
    __shared__ float rel_s[1536];
    __shared__ float wt_s[1536];
    __shared__ float adj_s[256];
    __shared__ float ahred[2048];
    __shared__ float xi_s[256];

    const int t = threadIdx.x;
    const int wid = t >> 5;
    const int lane = t & 31;
    const int row = blockIdx.x;
    const int b = row >> 8;

    const float* relrow = rel + (size_t)row * 256 * 6;
    for (int f = t; f < 1536; f += 256) { rel_s[f] = relrow[f]; wt_s[f] = Wt[f]; }
    adj_s[t] = adj2[row * 256 + t];
    xi_s[t]  = xi0[row * 256 + t];
    __syncthreads();

    const float2* c02 = reinterpret_cast<const float2*>(c0 + b * 65536);

#pragma unroll
    for (int kq = 0; kq < 4; ++kq) {
        const int p = lane + 32 * kq;     // k-pair 0..127
        const int k = 2 * p;
        const float2 xiv = *reinterpret_cast<const float2*>(&xi_s[k]);
        float2 wtv[6];
#pragma unroll
        for (int c = 0; c < 6; ++c)
            wtv[c] = *reinterpret_cast<const float2*>(&wt_s[c * 256 + k]);

        float ah0 = 0.f, ah1 = 0.f;
#pragma unroll 2
        for (int s = 0; s < 32; ++s) {
            const int j = wid * 32 + s;
            const float* rj = rel_s + j * 6;
            const float2 cv = __ldg(&c02[j * 128 + p]);
            float a0 = rj[0]*wtv[0].x + rj[1]*wtv[1].x + rj[2]*wtv[2].x
                     + rj[3]*wtv[3].x + rj[4]*wtv[4].x + rj[5]*wtv[5].x;
            float a1 = rj[0]*wtv[0].y + rj[1]*wtv[1].y + rj[2]*wtv[2].y
                     + rj[3]*wtv[3].y + rj[4]*wtv[4].y + rj[5]*wtv[5].y;
            const float aw = adj_s[j];
            ah0 = fmaf(aw, fmaxf(xiv.x + cv.x + a0, 0.f), ah0);
            ah1 = fmaf(aw, fmaxf(xiv.y + cv.y + a1, 0.f), ah1);
        }
        ahred[wid * 256 + k]     = ah0;
        ahred[wid * 256 + k + 1] = ah1;
    }
    __syncthreads();

    float s = 0.f;
#pragma unroll
    for (int g = 0; g < 8; ++g) s += ahred[g * 256 + t];
    AH0[row * 256 + t] = s;
}

// ---------------------------------------------------------------------------
// Kernel C: fused layer0 GEMM + layer1 reduction. alpha1 lives ONLY in regs.
// One block per (b,i); 256 threads (8 warps). Warp w owns j in [32w, 32w+32).
// Build H (256j x 256k fp16), HMMA C = H @ w_alpha, then immediately:
//   AH1[i,n] = sum_j adj2[i,j]*relu(xi1[i,n] + c1[j,n] + relu(C[j,n]))
// reduced over warp's 32 j via shfl_xor{4,8,16}, then cross-warp via SMEM.
// ---------------------------------------------------------------------------
// SMEM byte offsets
#define SM_A       0         // 256*512 = 131072 (fp16, 512B rows, xor-swizzled)
#define SM_B1      131072    // 32768
#define SM_REL     163840    // 6144
#define SM_WT      169984    // 6144
#define SM_ADJ     176128    // 1024
#define SM_AHRED   177152    // 8192 (ah1red: 8 warps x 256 n)
#define SM_XI      185344    // 1024
#define SM_XI1     186368    // 1024
#define SM_TOTAL   187392

__global__ void __launch_bounds__(256, 1) layer01_mma_kernel(
    const float* __restrict__ xi0, const float* __restrict__ c0,
    const float* __restrict__ rel, const float* __restrict__ Wt,
    const float* __restrict__ adj2,
    const float* __restrict__ xi1, const float* __restrict__ c1,
    float* __restrict__ AH1)
{
    extern __shared__ char sm[];
    const uint32_t sb = smem_to_u32(sm);
    float* rel_s  = reinterpret_cast<float*>(sm + SM_REL);
    float* wt_s   = reinterpret_cast<float*>(sm + SM_WT);
    float* adj_s  = reinterpret_cast<float*>(sm + SM_ADJ);
    float* ah1red = reinterpret_cast<float*>(sm + SM_AHRED);
    float* xi_s   = reinterpret_cast<float*>(sm + SM_XI);
    float* xi1_s  = reinterpret_cast<float*>(sm + SM_XI1);

    const int t = threadIdx.x;
    const int wid = t >> 5;
    const int lane = t & 31;
    const int row = blockIdx.x;      // b*256 + i
    const int b = row >> 8;

    // stage row-invariant data
    const float* relrow = rel + (size_t)row * 256 * 6;
    for (int f = t; f < 1536; f += 256) { rel_s[f] = relrow[f]; wt_s[f] = Wt[f]; }
    adj_s[t]  = adj2[row * 256 + t];
    xi_s[t]   = xi0[row * 256 + t];
    xi1_s[t]  = xi1[row * 256 + t];
    __syncthreads();

    const float* c0b = c0 + b * 65536;
    const float* c1b = c1 + b * 65536;

    // ---- build full H (256j x 256k) as fp16 ----
#pragma unroll
    for (int kq = 0; kq < 4; ++kq) {
        const int p = lane + 32 * kq;     // k-pair 0..127
        const int k = 2 * p;
        const float2 xiv = *reinterpret_cast<const float2*>(&xi_s[k]);
        float2 wtv[6];
#pragma unroll
        for (int c = 0; c < 6; ++c)
            wtv[c] = *reinterpret_cast<const float2*>(&wt_s[c * 256 + k]);

        const float2* c02 = reinterpret_cast<const float2*>(c0b);
#pragma unroll 2
        for (int s = 0; s < 32; ++s) {
            const int j = wid * 32 + s;
            const float* rj = rel_s + j * 6;
            const float2 cv = __ldg(&c02[j * 128 + p]);
            float a0 = rj[0]*wtv[0].x + rj[1]*wtv[1].x + rj[2]*wtv[2].x
                     + rj[3]*wtv[3].x + rj[4]*wtv[4].x + rj[5]*wtv[5].x;
            float a1 = rj[0]*wtv[0].y + rj[1]*wtv[1].y + rj[2]*wtv[2].y
                     + rj[3]*wtv[3].y + rj[4]*wtv[4].y + rj[5]*wtv[5].y;
            __half2 hp;
            hp.x = __float2half_rn(fmaxf(xiv.x + cv.x + a0, 0.f));
            hp.y = __float2half_rn(fmaxf(xiv.y + cv.y + a1, 0.f));
            const uint32_t off = (uint32_t)j * 512u + ((uint32_t)(4 * p) ^ ((uint32_t)(j & 7) << 4));
            *reinterpret_cast<uint32_t*>(sm + SM_A + off) = *reinterpret_cast<uint32_t*>(&hp);
        }
    }

    // --- per-lane ldmatrix address components ---
    const int jrowA = (wid * 32) + (lane & 15);
    const uint32_t acolByte = (uint32_t)((lane >> 4) * 16);
    const uint32_t jmask = (uint32_t)((jrowA & 7) << 4);
    const uint32_t aRowByte = (uint32_t)jrowA * 512u;
    const int nrow_l = (lane & 7) | ((lane & 16) >> 1);
    const uint32_t kbB = (uint32_t)(((lane >> 3) & 1) * 16);
    const uint32_t nmask = (uint32_t)((nrow_l & 7) << 4);
    const uint32_t bRowByte = (uint32_t)nrow_l * 256u;

    const int r  = lane >> 2;    // 0..7
    const int cq = lane & 3;     // 0..3

#pragma unroll 1
    for (int nc = 0; nc < 2; ++nc) {
        float C[2][16][4];
#pragma unroll
        for (int m = 0; m < 2; ++m)
#pragma unroll
            for (int nt = 0; nt < 16; ++nt)
#pragma unroll
                for (int u = 0; u < 4; ++u) C[m][nt][u] = 0.f;

#pragma unroll 1
        for (int kh = 0; kh < 2; ++kh) {
            __syncthreads();   // B reuse / A publish guard
            // ---- stage B slice (verbatim pre-swizzled copy) ----
            {
                const uint4* s1 = reinterpret_cast<const uint4*>(
                    reinterpret_cast<const char*>(g_wimg1) + kh * 65536 + nc * 32768);
                uint4* d1 = reinterpret_cast<uint4*>(sm + SM_B1);
                for (int i = t; i < 2048; i += 256) d1[i] = __ldg(&s1[i]);
            }
            __syncthreads();

            // ---- HMMA: C += A * B ----
#pragma unroll 1
            for (int ks = 0; ks < 8; ++ks) {
                const uint32_t aoff = ((uint32_t)((kh * 8 + ks) * 32) + acolByte) ^ jmask;
                const uint32_t boff = ((uint32_t)(ks * 32) + kbB) ^ nmask;
                uint32_t Ah[2][4];
                ldsm4(Ah[0], sb + SM_A + aRowByte + aoff);
                ldsm4(Ah[1], sb + SM_A + 8192 + aRowByte + aoff);

                uint32_t bb[4];
#pragma unroll
                for (int p = 0; p < 8; ++p) {
                    ldsm4(bb, sb + SM_B1 + (uint32_t)p * 4096 + bRowByte + boff);
                    mma_f16(C[0][2 * p],     Ah[0], bb[0], bb[1]);
                    mma_f16(C[1][2 * p],     Ah[1], bb[0], bb[1]);
                    mma_f16(C[0][2 * p + 1], Ah[0], bb[2], bb[3]);
                    mma_f16(C[1][2 * p + 1], Ah[1], bb[2], bb[3]);
                }
            }
        }

        // ---- fused layer1 epilogue: consume alpha1 = relu(C) in registers ----
        {
            float acc0[16], acc1[16];
#pragma unroll
            for (int nt = 0; nt < 16; ++nt) { acc0[nt] = 0.f; acc1[nt] = 0.f; }

#pragma unroll
            for (int m = 0; m < 2; ++m) {
                const int j1 = wid * 32 + m * 16 + r;
                const int j2 = j1 + 8;
                const float aw1 = adj_s[j1];
                const float aw2 = adj_s[j2];
#pragma unroll
                for (int nt = 0; nt < 16; ++nt) {
                    const int n0 = nc * 128 + nt * 8 + 2 * cq;
                    const float2 cA = __ldg(reinterpret_cast<const float2*>(c1b + j1 * 256 + n0));
                    const float2 cB = __ldg(reinterpret_cast<const float2*>(c1b + j2 * 256 + n0));
                    const float x0 = xi1_s[n0];
                    const float x1v = xi1_s[n0 + 1];
                    const float a0 = fmaxf(C[m][nt][0], 0.f);
                    const float a1 = fmaxf(C[m][nt][1], 0.f);
                    const float a2 = fmaxf(C[m][nt][2], 0.f);
                    const float a3 = fmaxf(C[m][nt][3], 0.f);
                    acc0[nt] = fmaf(aw1, fmaxf(x0 + cA.x + a0, 0.f), acc0[nt]);
                    acc1[nt] = fmaf(aw1, fmaxf(x1v + cA.y + a1, 0.f), acc1[nt]);
                    acc0[nt] = fmaf(aw2, fmaxf(x0 + cB.x + a2, 0.f), acc0[nt]);
                    acc1[nt] = fmaf(aw2, fmaxf(x1v + cB.y + a3, 0.f), acc1[nt]);
                }
            }

            // reduce over the warp's 32 j (lanes sharing cq: bits 2..4) and store
#pragma unroll
            for (int nt = 0; nt < 16; ++nt) {
                float v0 = acc0[nt], v1 = acc1[nt];
#pragma unroll
                for (int off = 4; off <= 16; off <<= 1) {
                    v0 += __shfl_xor_sync(0xffffffffu, v0, off);
                    v1 += __shfl_xor_sync(0xffffffffu, v1, off);
                }
                if (r == 0) {
                    const int n0 = nc * 128 + nt * 8 + 2 * cq;
                    ah1red[wid * 256 + n0]     = v0;
                    ah1red[wid * 256 + n0 + 1] = v1;
                }
            }
        }
    }
    __syncthreads();

    // cross-warp reduce -> AH1
    {
        float s = 0.f;
#pragma unroll
        for (int g = 0; g < 8; ++g) s += ah1red[g * 256 + t];
        AH1[row * 256 + t] = s;
    }
}

// ---------------------------------------------------------------------------
extern "C" void kernel_launch(void* const* d_in, const int* in_sizes, int n_in,
                              void* d_out, int out_size)
{
    (void)in_sizes; (void)n_in; (void)out_size;

    const float* x        = (const float*)d_in[0];
    const float* rel      = (const float*)d_in[1];
    const float* adj      = (const float*)d_in[2];
    const int*   bnum     = (const int*)  d_in[3];
    const float* Wt       = (const float*)d_in[4];
    const float* b_alpha  = (const float*)d_in[5];
    const float* W_proj   = (const float*)d_in[6];
    const float* b_proj   = (const float*)d_in[7];
    const float* learn_w  = (const float*)d_in[8];
    const float* w_alpha0 = (const float*)d_in[9];
    const float* w_vi0    = (const float*)d_in[10];
    const float* w_vj0    = (const float*)d_in[11];
    const float* bias_h0  = (const float*)d_in[12];
    const float* w_node0  = (const float*)d_in[13];
    /* d_in[14] = l1_w_alpha: unused (alpha2 discarded) */
    const float* w_vi1    = (const float*)d_in[15];
    const float* w_vj1    = (const float*)d_in[16];
    const float* bias_h1  = (const float*)d_in[17];
    const float* w_node1  = (const float*)d_in[18];

    float* out      = (float*)d_out;
    float* out_x2   = out;
    float* out_sadj = out + 262144;
    float* out_gl   = out + 524288;

    float *xhat, *pnorm, *adj2, *xi0, *c0, *AH0, *x1, *xi1, *c1, *AH1;
    cudaGetSymbolAddress((void**)&xhat,   g_xhat);
    cudaGetSymbolAddress((void**)&pnorm,  g_pnorm);
    cudaGetSymbolAddress((void**)&adj2,   g_adj2);
    cudaGetSymbolAddress((void**)&xi0,    g_xi0);
    cudaGetSymbolAddress((void**)&c0,     g_c0);
    cudaGetSymbolAddress((void**)&AH0,    g_AH0);
    cudaGetSymbolAddress((void**)&x1,     g_x1);
    cudaGetSymbolAddress((void**)&xi1,    g_xi1);
    cudaGetSymbolAddress((void**)&c1,     g_c1);
    cudaGetSymbolAddress((void**)&AH1,    g_AH1);

    // ---- prep: convert + transpose + swizzle w_alpha0 image ----
    prep_w_kernel<<<256, 256>>>(w_alpha0);

    // ---- graph learning ----
    rowgemm_kernel<<<256, 128>>>(x, W_proj, b_proj, xhat);
    pair_softadj_kernel<<<1024, 256>>>(xhat, adj, learn_w, bnum, out_sadj, adj2, pnorm);
    glloss_part_kernel<<<512, 256>>>(out_sadj, pnorm);
    glloss_fin_kernel<<<4, 128>>>(bnum, out_gl);

    // ---- GCN layer 0 inputs ----
    const int DUAL_SMEM = 18432 * 4;
    cudaFuncSetAttribute(rowgemm8_dual_kernel, cudaFuncAttributeMaxDynamicSharedMemorySize, DUAL_SMEM);
    rowgemm8_dual_kernel<<<128, 256, DUAL_SMEM>>>(x, w_vi0, w_vj0, bias_h0, b_alpha, xi0, c0);

    // ---- AH0 (H on the fly) -> x1 -> xi1/c1 ----
    ah0_kernel<<<1024, 256>>>(xi0, c0, rel, Wt, adj2, AH0);
    rowgemm8_kernel<<<128, 256>>>(AH0, w_node0, x1);
    rowgemm8_dual_kernel<<<128, 256, DUAL_SMEM>>>(x1, w_vi1, w_vj1, bias_h1, nullptr, xi1, c1);

    // ---- fused layer0 GEMM + layer1 reduction (alpha1 never leaves registers) ----
    cudaFuncSetAttribute(layer01_mma_kernel, cudaFuncAttributeMaxDynamicSharedMemorySize, SM_TOTAL);
    layer01_mma_kernel<<<1024, 256, SM_TOTAL>>>(xi0, c0, rel, Wt, adj2, xi1, c1, AH1);

    rowgemm8_kernel<<<128, 256>>>(AH1, w_node1, out_x2);
}

// round 9
// speedup vs baseline: 3.3206x; 1.0765x over previous
#include <cuda_runtime.h>
#include <cuda_fp16.h>
#include <cstdint>
#include <cstddef>

// Problem constants
#define PB 4
#define PN 256
#define PD 256
#define PL 128
#define POUT 256

// ============================ helpers ============================
__device__ __forceinline__ uint32_t smem_to_u32(const void* smem_ptr) {
    uint32_t addr;
    asm("{ .reg .u64 tmp; cvta.to.shared.u64 tmp, %1; cvt.u32.u64 %0, tmp; }"
        : "=r"(addr) : "l"(smem_ptr));
    return addr;
}

__device__ __forceinline__ void ldsm4(uint32_t* r, uint32_t addr) {
    asm volatile("ldmatrix.sync.aligned.m8n8.x4.shared.b16 {%0,%1,%2,%3}, [%4];"
        : "=r"(r[0]), "=r"(r[1]), "=r"(r[2]), "=r"(r[3]) : "r"(addr));
}

__device__ __forceinline__ void mma_f16(float* c, const uint32_t* a, uint32_t b0, uint32_t b1) {
    asm volatile(
        "mma.sync.aligned.m16n8k16.row.col.f32.f16.f16.f32 "
        "{%0,%1,%2,%3}, {%4,%5,%6,%7}, {%8,%9}, {%0,%1,%2,%3};"
        : "+f"(c[0]), "+f"(c[1]), "+f"(c[2]), "+f"(c[3])
        : "r"(a[0]), "r"(a[1]), "r"(a[2]), "r"(a[3]), "r"(b0), "r"(b1));
}

// ---------------- scratch (device globals; no runtime allocation) ----------------
__device__ float g_xhat [PB*PN*PL];
__device__ float g_pnorm[PB*PN*PN];
__device__ float g_adj2 [PB*PN*PN];
__device__ float g_xi0  [PB*PN*POUT];
__device__ float g_c0   [PB*PN*POUT];
__device__ float g_AH0  [PB*PN*POUT];
__device__ float g_x1   [PB*PN*POUT];
__device__ float g_xi1  [PB*PN*POUT];
__device__ float g_c1   [PB*PN*POUT];
__device__ float g_AH1  [PB*PN*POUT];
__device__ float g_part1[512];
__device__ float g_part2[512];
// Pre-converted w_alpha image: [kh:2][n:256][k:128] fp16, 256B rows,
// XOR-swizzled by (n&7)<<4 -> ldmatrix conflict-free, verbatim staging.
// kh stride = 256 rows * 256 B = 65536 BYTES.
__device__ __half g_wimg1[2*256*128];

// ---------------------------------------------------------------------------
// Prep: convert w_alpha0 (k=d:256, n:256) into fp16 transposed image.
// ---------------------------------------------------------------------------
__global__ void prep_w_kernel(const float* __restrict__ w_alpha)
{
    const int e = blockIdx.x * 256 + threadIdx.x;    // 65536
    const int k = e >> 8;
    const int n = e & 255;
    const __half hi = __float2half_rn(w_alpha[k * 256 + n]);
    const int kh = k >> 7, kk = k & 127;
    const uint32_t off = kh * 65536u + n * 256u + (uint32_t)((kk * 2) ^ ((n & 7) << 4));
    *reinterpret_cast<__half*>(reinterpret_cast<char*>(g_wimg1) + off) = hi;
}

// ---------------------------------------------------------------------------
// Simple row GEMM for xhat (K=128)
// ---------------------------------------------------------------------------
__global__ void rowgemm_kernel(const float* __restrict__ X, const float* __restrict__ W,
                               const float* __restrict__ bias_k, float* __restrict__ out)
{
    __shared__ float xs[4 * 256];
    const int r0 = blockIdx.x * 4;
    const int t  = threadIdx.x;
    for (int f = t; f < 4 * 256; f += 128) xs[f] = X[r0 * 256 + f];
    __syncthreads();

    float acc[4] = {0.f, 0.f, 0.f, 0.f};
#pragma unroll 8
    for (int d = 0; d < 256; ++d) {
        const float wv = __ldg(&W[d * 128 + t]);
#pragma unroll
        for (int r = 0; r < 4; ++r) acc[r] = fmaf(xs[r * 256 + d], wv, acc[r]);
    }
    const float bk = __ldg(&bias_k[t]);
#pragma unroll
    for (int r = 0; r < 4; ++r) out[(r0 + r) * 128 + t] = acc[r] + bk;
}

// ---------------------------------------------------------------------------
// SMEM-tiled row GEMM (K=256): 8 rows/block, 256 threads, relu output.
// ---------------------------------------------------------------------------
__global__ __launch_bounds__(256) void rowgemm8_kernel(
    const float* __restrict__ X, const float* __restrict__ W, float* __restrict__ out)
{
    __shared__ float xs[8 * 256];
    __shared__ float ws[32 * 256];
    const int r0 = blockIdx.x * 8;
    const int t  = threadIdx.x;
    for (int f = t; f < 8 * 256; f += 256) xs[f] = X[r0 * 256 + f];

    float acc[8];
#pragma unroll
    for (int r = 0; r < 8; ++r) acc[r] = 0.f;

    for (int dt = 0; dt < 8; ++dt) {
        __syncthreads();
        const float4* Wv = reinterpret_cast<const float4*>(W + dt * 32 * 256);
        float4* wsv = reinterpret_cast<float4*>(ws);
        for (int i = t; i < 2048; i += 256) wsv[i] = __ldg(&Wv[i]);
        __syncthreads();
#pragma unroll
        for (int d4 = 0; d4 < 32; d4 += 4) {
            float wv0 = ws[(d4 + 0) * 256 + t];
            float wv1 = ws[(d4 + 1) * 256 + t];
            float wv2 = ws[(d4 + 2) * 256 + t];
            float wv3 = ws[(d4 + 3) * 256 + t];
#pragma unroll
            for (int r = 0; r < 8; ++r) {
                const float4 xv = *reinterpret_cast<const float4*>(&xs[r * 256 + dt * 32 + d4]);
                acc[r] = fmaf(xv.x, wv0, acc[r]);
                acc[r] = fmaf(xv.y, wv1, acc[r]);
                acc[r] = fmaf(xv.z, wv2, acc[r]);
                acc[r] = fmaf(xv.w, wv3, acc[r]);
            }
        }
    }
#pragma unroll
    for (int r = 0; r < 8; ++r) out[(r0 + r) * 256 + t] = fmaxf(acc[r], 0.f);
}

// Dual variant: out1 = X@W1 (plain), out2 = X@W2 + bias_nk[row&255,:] (+bias_k).
__global__ __launch_bounds__(256) void rowgemm8_dual_kernel(
    const float* __restrict__ X, const float* __restrict__ W1, const float* __restrict__ W2,
    const float* __restrict__ bias_nk, const float* __restrict__ bias_k,
    float* __restrict__ out1, float* __restrict__ out2)
{
    extern __shared__ float dsm[];
    float* xs  = dsm;          // 2048
    float* ws1 = dsm + 2048;   // 8192
    float* ws2 = dsm + 10240;  // 8192
    const int r0 = blockIdx.x * 8;
    const int t  = threadIdx.x;
    for (int f = t; f < 8 * 256; f += 256) xs[f] = X[r0 * 256 + f];

    float a1[8], a2[8];
#pragma unroll
    for (int r = 0; r < 8; ++r) { a1[r] = 0.f; a2[r] = 0.f; }

    for (int dt = 0; dt < 8; ++dt) {
        __syncthreads();
        const float4* W1v = reinterpret_cast<const float4*>(W1 + dt * 32 * 256);
        const float4* W2v = reinterpret_cast<const float4*>(W2 + dt * 32 * 256);
        float4* w1s = reinterpret_cast<float4*>(ws1);
        float4* w2s = reinterpret_cast<float4*>(ws2);
        for (int i = t; i < 2048; i += 256) { w1s[i] = __ldg(&W1v[i]); w2s[i] = __ldg(&W2v[i]); }
        __syncthreads();
#pragma unroll
        for (int d4 = 0; d4 < 32; d4 += 4) {
            float u0 = ws1[(d4 + 0) * 256 + t], v0 = ws2[(d4 + 0) * 256 + t];
            float u1 = ws1[(d4 + 1) * 256 + t], v1 = ws2[(d4 + 1) * 256 + t];
            float u2 = ws1[(d4 + 2) * 256 + t], v2 = ws2[(d4 + 2) * 256 + t];
            float u3 = ws1[(d4 + 3) * 256 + t], v3 = ws2[(d4 + 3) * 256 + t];
#pragma unroll
            for (int r = 0; r < 8; ++r) {
                const float4 xv = *reinterpret_cast<const float4*>(&xs[r * 256 + dt * 32 + d4]);
                a1[r] = fmaf(xv.x, u0, a1[r]); a2[r] = fmaf(xv.x, v0, a2[r]);
                a1[r] = fmaf(xv.y, u1, a1[r]); a2[r] = fmaf(xv.y, v1, a2[r]);
                a1[r] = fmaf(xv.z, u2, a1[r]); a2[r] = fmaf(xv.z, v2, a2[r]);
                a1[r] = fmaf(xv.w, u3, a1[r]); a2[r] = fmaf(xv.w, v3, a2[r]);
            }
        }
    }
    const float bk = bias_k ? __ldg(&bias_k[t]) : 0.f;
#pragma unroll
    for (int r = 0; r < 8; ++r) {
        const int row = r0 + r;
        out1[row * 256 + t] = a1[r];
        out2[row * 256 + t] = a2[r] + bk + __ldg(&bias_nk[(row & (PN - 1)) * 256 + t]);
    }
}

// ---------------------------------------------------------------------------
// Fused graph-learning kernel.
// ---------------------------------------------------------------------------
__global__ void pair_softadj_kernel(const float* __restrict__ xhat,
                                    const float* __restrict__ adj,
                                    const float* __restrict__ learn_w,
                                    const int*   __restrict__ box_num,
                                    float* __restrict__ soft_adj_out,
                                    float* __restrict__ adj2,
                                    float* __restrict__ pair_norm)
{
    const int row = blockIdx.x;
    const int b = row >> 8;
    const int i = row & 255;
    const int t = threadIdx.x;
    const int warp = t >> 5, lane = t & 31;

    __shared__ float xi_s[128];
    __shared__ float w_s[128];
    __shared__ float sval[256];
    __shared__ float red[256];
    __shared__ float wsum_s, rmax_s;

    if (t < 128) { xi_s[t] = xhat[row * 128 + t]; w_s[t] = learn_w[t]; }
    __syncthreads();
    if (t == 0) {
        float s = 0.f;
        for (int d = 0; d < 128; ++d) s += w_s[d];
        wsum_s = s;
    }
    __syncthreads();

    const int bn = box_num[b];
    const bool vi = (i < bn);
    const float wsum = wsum_s;
    const float4 xi4 = reinterpret_cast<const float4*>(xi_s)[lane];
    const float4 w4  = reinterpret_cast<const float4*>(w_s)[lane];

    for (int j = warp; j < 256; j += 8) {
        const float4 xj4 = __ldg(reinterpret_cast<const float4*>(xhat + (b * 256 + j) * 128) + lane);
        const float d0 = xi4.x - xj4.x, d1 = xi4.y - xj4.y;
        const float d2 = xi4.z - xj4.z, d3 = xi4.w - xj4.w;
        float s = fabsf(d0) * w4.x + fabsf(d1) * w4.y + fabsf(d2) * w4.z + fabsf(d3) * w4.w;
        float q = d0 * d0 + d1 * d1 + d2 * d2 + d3 * d3;
#pragma unroll
        for (int off = 16; off; off >>= 1) {
            s += __shfl_down_sync(0xffffffffu, s, off);
            q += __shfl_down_sync(0xffffffffu, q, off);
        }
        if (lane == 0) {
            const float m = (vi && (j < bn)) ? 0.f : -1.f;
            float v = s + m * wsum;
            v = (v > 0.f) ? v : 0.01f * v;
            sval[j] = v;
            pair_norm[row * 256 + j] = sqrtf(q + 1e-12f);
        }
    }
    __syncthreads();

    const float v = sval[t];
    red[t] = v;
    __syncthreads();
    for (int sft = 128; sft; sft >>= 1) {
        if (t < sft) red[t] = fmaxf(red[t], red[t + sft]);
        __syncthreads();
    }
    if (t == 0) rmax_s = red[0];
    __syncthreads();

    const float a = adj[row * 256 + t];
    const float e = expf(v - rmax_s) * a;
    red[t] = e;
    __syncthreads();
    for (int sft = 128; sft; sft >>= 1) {
        if (t < sft) red[t] += red[t + sft];
        __syncthreads();
    }
    const float sa = e / red[0] + 1e-10f;
    soft_adj_out[row * 256 + t] = sa;
    adj2[row * 256 + t] = a * sa;
}

// ---------------------------------------------------------------------------
// gl_loss: phase 1 — 512 blocks (128 per batch), 512 elements each.
// ---------------------------------------------------------------------------
__global__ void glloss_part_kernel(const float* __restrict__ soft_adj,
                                   const float* __restrict__ pair_norm)
{
    const int blk = blockIdx.x;               // b*128 + part
    const int b = blk >> 7;
    const int t = threadIdx.x;                // 256 threads
    const int base = b * 65536 + (blk & 127) * 512;
    float s1 = 0.f, s2 = 0.f;
#pragma unroll
    for (int u = 0; u < 2; ++u) {
        const int idx = base + u * 256 + t;
        const float s = soft_adj[idx];
        s1 += expf(s + pair_norm[idx]);       // ETA = 1.0
        s2 += s * s;
    }
    __shared__ float r1[256], r2[256];
    r1[t] = s1; r2[t] = s2;
    __syncthreads();
    for (int sft = 128; sft; sft >>= 1) {
        if (t < sft) { r1[t] += r1[t + sft]; r2[t] += r2[t + sft]; }
        __syncthreads();
    }
    if (t == 0) { g_part1[blk] = r1[0]; g_part2[blk] = r2[0]; }
}

__global__ void glloss_fin_kernel(const int* __restrict__ box_num, float* __restrict__ gl_out)
{
    const int b = blockIdx.x;
    const int t = threadIdx.x;                // 128 threads
    __shared__ float r1[128], r2[128];
    r1[t] = g_part1[b * 128 + t];
    r2[t] = g_part2[b * 128 + t];
    __syncthreads();
    for (int sft = 64; sft; sft >>= 1) {
        if (t < sft) { r1[t] += r1[t + sft]; r2[t] += r2[t + sft]; }
        __syncthreads();
    }
    if (t == 0) {
        const float bnf = (float)box_num[b];
        gl_out[b] = r1[0] / (bnf * bnf) + 1e-4f * sqrtf(r2[0]);   // GAMMA = 1e-4
    }
}

// ---------------------------------------------------------------------------
// Kernel A: AH0 only. H built on the fly, never stored. Light smem -> high occ.
// ---------------------------------------------------------------------------
__global__ __launch_bounds__(256) void ah0_kernel(
    const float* __restrict__ xi0, const float* __restrict__ c0,
    const float* __restrict__ rel, const float* __restrict__ Wt,
    const float* __restrict__ adj2, float* __restrict__ AH0)
{
    __shared__ float rel_s[1536];
    __shared__ float wt_s[1536];
    __shared__ float adj_s[256];
    __shared__ float ahred[2048];
    __shared__ float xi_s[256];

    const int t = threadIdx.x;
    const int wid = t >> 5;
    const int lane = t & 31;
    const int row = blockIdx.x;
    const int b = row >> 8;

    const float* relrow = rel + (size_t)row * 256 * 6;
    for (int f = t; f < 1536; f += 256) { rel_s[f] = relrow[f]; wt_s[f] = Wt[f]; }
    adj_s[t] = adj2[row * 256 + t];
    xi_s[t]  = xi0[row * 256 + t];
    __syncthreads();

    const float2* c02 = reinterpret_cast<const float2*>(c0 + b * 65536);

#pragma unroll
    for (int kq = 0; kq < 4; ++kq) {
        const int p = lane + 32 * kq;     // k-pair 0..127
        const int k = 2 * p;
        const float2 xiv = *reinterpret_cast<const float2*>(&xi_s[k]);
        float2 wtv[6];
#pragma unroll
        for (int c = 0; c < 6; ++c)
            wtv[c] = *reinterpret_cast<const float2*>(&wt_s[c * 256 + k]);

        float ah0 = 0.f, ah1 = 0.f;
#pragma unroll 2
        for (int s = 0; s < 32; ++s) {
            const int j = wid * 32 + s;
            const float* rj = rel_s + j * 6;
            const float2 cv = __ldg(&c02[j * 128 + p]);
            float a0 = rj[0]*wtv[0].x + rj[1]*wtv[1].x + rj[2]*wtv[2].x
                     + rj[3]*wtv[3].x + rj[4]*wtv[4].x + rj[5]*wtv[5].x;
            float a1 = rj[0]*wtv[0].y + rj[1]*wtv[1].y + rj[2]*wtv[2].y
                     + rj[3]*wtv[3].y + rj[4]*wtv[4].y + rj[5]*wtv[5].y;
            const float aw = adj_s[j];
            ah0 = fmaf(aw, fmaxf(xiv.x + cv.x + a0, 0.f), ah0);
            ah1 = fmaf(aw, fmaxf(xiv.y + cv.y + a1, 0.f), ah1);
        }
        ahred[wid * 256 + k]     = ah0;
        ahred[wid * 256 + k + 1] = ah1;
    }
    __syncthreads();

    float s = 0.f;
#pragma unroll
    for (int g = 0; g < 8; ++g) s += ahred[g * 256 + t];
    AH0[row * 256 + t] = s;
}

// ---------------------------------------------------------------------------
// Kernel C: fused layer0 GEMM + layer1 reduction, j-halved for 2 blocks/SM.
// One block per (b,i); 256 threads (8 warps). Per jh half (128 j):
//   warp w builds+owns j rows [jh*128 + 16w, +16) (warp-local A tile),
//   HMMA C = H_half @ w_alpha (nc x kh), epilogue accumulates
//   AH1 partials (adj2-weighted relu) into smem via same-thread RMW.
// alpha1 never leaves registers. smem 110KB -> 2 blocks/SM.
// ---------------------------------------------------------------------------
// SMEM byte offsets
#define SM_A       0         // 128 j x 256 k fp16, 512B rows, xor-swizzled = 65536
#define SM_B1      65536     // 32768
#define SM_REL     98304     // 3072 (current jh half: 128 j x 6)
#define SM_ADJ     101376    // 1024
#define SM_AHRED   102400    // 8192 (8 warps x 256 n)
#define SM_XI      110592    // 1024
#define SM_XI1     111616    // 1024
#define SM_TOTAL   112640

__global__ void __launch_bounds__(256, 2) layer01_mma_kernel(
    const float* __restrict__ xi0, const float* __restrict__ c0,
    const float* __restrict__ rel, const float* __restrict__ Wt,
    const float* __restrict__ adj2,
    const float* __restrict__ xi1, const float* __restrict__ c1,
    float* __restrict__ AH1)
{
    extern __shared__ char sm[];
    const uint32_t sb = smem_to_u32(sm);
    float* rel_s  = reinterpret_cast<float*>(sm + SM_REL);
    float* adj_s  = reinterpret_cast<float*>(sm + SM_ADJ);
    float* ah1red = reinterpret_cast<float*>(sm + SM_AHRED);
    float* xi_s   = reinterpret_cast<float*>(sm + SM_XI);
    float* xi1_s  = reinterpret_cast<float*>(sm + SM_XI1);

    const int t = threadIdx.x;
    const int wid = t >> 5;
    const int lane = t & 31;
    const int row = blockIdx.x;      // b*256 + i
    const int b = row >> 8;

    adj_s[t]  = adj2[row * 256 + t];
    xi_s[t]   = xi0[row * 256 + t];
    xi1_s[t]  = xi1[row * 256 + t];
    for (int f = t; f < 2048; f += 256) ah1red[f] = 0.f;

    const float* c0b = c0 + b * 65536;
    const float* c1b = c1 + b * 65536;

    // --- per-lane ldmatrix address components (j-local, 128-row A tile) ---
    const int jrl = wid * 16 + (lane & 15);
    const uint32_t acolByte = (uint32_t)((lane >> 4) * 16);
    const uint32_t jmask = (uint32_t)((jrl & 7) << 4);
    const uint32_t aRowByte = (uint32_t)jrl * 512u;
    const int nrow_l = (lane & 7) | ((lane & 16) >> 1);
    const uint32_t kbB = (uint32_t)(((lane >> 3) & 1) * 16);
    const uint32_t nmask = (uint32_t)((nrow_l & 7) << 4);
    const uint32_t bRowByte = (uint32_t)nrow_l * 256u;

    const int r  = lane >> 2;    // 0..7
    const int cq = lane & 3;     // 0..3

#pragma unroll 1
    for (int jh = 0; jh < 2; ++jh) {
        __syncthreads();   // A/rel reuse guard (and initial staging visibility)

        // stage rel half (128 j x 6)
        const float* relrow = rel + ((size_t)row * 256 + jh * 128) * 6;
        for (int f = t; f < 768; f += 256) rel_s[f] = relrow[f];
        __syncthreads();

        // ---- build H half (128 j x 256 k) as fp16; warp w owns rows 16w..16w+15 ----
#pragma unroll
        for (int kq = 0; kq < 4; ++kq) {
            const int p = lane + 32 * kq;     // k-pair 0..127
            const int k = 2 * p;
            const float2 xiv = *reinterpret_cast<const float2*>(&xi_s[k]);
            float2 wtv[6];
#pragma unroll
            for (int c = 0; c < 6; ++c)
                wtv[c] = __ldg(reinterpret_cast<const float2*>(&Wt[c * 256 + k]));

            const float2* c02 = reinterpret_cast<const float2*>(c0b);
#pragma unroll 2
            for (int s = 0; s < 16; ++s) {
                const int jl = wid * 16 + s;
                const int j = jh * 128 + jl;
                const float* rj = rel_s + jl * 6;
                const float2 cv = __ldg(&c02[j * 128 + p]);
                float a0 = rj[0]*wtv[0].x + rj[1]*wtv[1].x + rj[2]*wtv[2].x
                         + rj[3]*wtv[3].x + rj[4]*wtv[4].x + rj[5]*wtv[5].x;
                float a1 = rj[0]*wtv[0].y + rj[1]*wtv[1].y + rj[2]*wtv[2].y
                         + rj[3]*wtv[3].y + rj[4]*wtv[4].y + rj[5]*wtv[5].y;
                __half2 hp;
                hp.x = __float2half_rn(fmaxf(xiv.x + cv.x + a0, 0.f));
                hp.y = __float2half_rn(fmaxf(xiv.y + cv.y + a1, 0.f));
                const uint32_t off = (uint32_t)jl * 512u + ((uint32_t)(4 * p) ^ ((uint32_t)(jl & 7) << 4));
                *reinterpret_cast<uint32_t*>(sm + SM_A + off) = *reinterpret_cast<uint32_t*>(&hp);
            }
        }

#pragma unroll 1
        for (int nc = 0; nc < 2; ++nc) {
            float C[16][4];
#pragma unroll
            for (int nt = 0; nt < 16; ++nt)
#pragma unroll
                for (int u = 0; u < 4; ++u) C[nt][u] = 0.f;

#pragma unroll 1
            for (int kh = 0; kh < 2; ++kh) {
                __syncthreads();   // B consumers done (also covers A build -> ldsm cross-lane)
                // ---- stage B slice (verbatim pre-swizzled copy) ----
                {
                    const uint4* s1 = reinterpret_cast<const uint4*>(
                        reinterpret_cast<const char*>(g_wimg1) + kh * 65536 + nc * 32768);
                    uint4* d1 = reinterpret_cast<uint4*>(sm + SM_B1);
                    for (int i = t; i < 2048; i += 256) d1[i] = __ldg(&s1[i]);
                }
                __syncthreads();

                // ---- HMMA: C += A * B ----
#pragma unroll 1
                for (int ks = 0; ks < 8; ++ks) {
                    const uint32_t aoff = ((uint32_t)((kh * 8 + ks) * 32) + acolByte) ^ jmask;
                    const uint32_t boff = ((uint32_t)(ks * 32) + kbB) ^ nmask;
                    uint32_t Ah[4];
                    ldsm4(Ah, sb + SM_A + aRowByte + aoff);

                    uint32_t bb[4];
#pragma unroll
                    for (int p = 0; p < 8; ++p) {
                        ldsm4(bb, sb + SM_B1 + (uint32_t)p * 4096 + bRowByte + boff);
                        mma_f16(C[2 * p],     Ah, bb[0], bb[1]);
                        mma_f16(C[2 * p + 1], Ah, bb[2], bb[3]);
                    }
                }
            }

            // ---- fused layer1 epilogue: consume alpha1 = relu(C) in registers ----
            {
                float acc0[16], acc1[16];
#pragma unroll
                for (int nt = 0; nt < 16; ++nt) { acc0[nt] = 0.f; acc1[nt] = 0.f; }

                const int j1 = jh * 128 + wid * 16 + r;
                const int j2 = j1 + 8;
                const float aw1 = adj_s[j1];
                const float aw2 = adj_s[j2];
#pragma unroll
                for (int nt = 0; nt < 16; ++nt) {
                    const int n0 = nc * 128 + nt * 8 + 2 * cq;
                    const float2 cA = __ldg(reinterpret_cast<const float2*>(c1b + j1 * 256 + n0));
                    const float2 cB = __ldg(reinterpret_cast<const float2*>(c1b + j2 * 256 + n0));
                    const float x0 = xi1_s[n0];
                    const float x1v = xi1_s[n0 + 1];
                    const float a0 = fmaxf(C[nt][0], 0.f);
                    const float a1 = fmaxf(C[nt][1], 0.f);
                    const float a2 = fmaxf(C[nt][2], 0.f);
                    const float a3 = fmaxf(C[nt][3], 0.f);
                    acc0[nt] = fmaf(aw1, fmaxf(x0 + cA.x + a0, 0.f), acc0[nt]);
                    acc1[nt] = fmaf(aw1, fmaxf(x1v + cA.y + a1, 0.f), acc1[nt]);
                    acc0[nt] = fmaf(aw2, fmaxf(x0 + cB.x + a2, 0.f), acc0[nt]);
                    acc1[nt] = fmaf(aw2, fmaxf(x1v + cB.y + a3, 0.f), acc1[nt]);
                }

                // reduce over the warp's 16 j (r-lanes, bits 2..4) and accumulate (same-thread RMW)
#pragma unroll
                for (int nt = 0; nt < 16; ++nt) {
                    float v0 = acc0[nt], v1 = acc1[nt];
#pragma unroll
                    for (int off = 4; off <= 16; off <<= 1) {
                        v0 += __shfl_xor_sync(0xffffffffu, v0, off);
                        v1 += __shfl_xor_sync(0xffffffffu, v1, off);
                    }
                    if (r == 0) {
                        const int n0 = nc * 128 + nt * 8 + 2 * cq;
                        ah1red[wid * 256 + n0]     += v0;
                        ah1red[wid * 256 + n0 + 1] += v1;
                    }
                }
            }
        }
    }
    __syncthreads();

    // cross-warp reduce -> AH1
    {
        float s = 0.f;
#pragma unroll
        for (int g = 0; g < 8; ++g) s += ah1red[g * 256 + t];
        AH1[row * 256 + t] = s;
    }
}

// ---------------------------------------------------------------------------
extern "C" void kernel_launch(void* const* d_in, const int* in_sizes, int n_in,
                              void* d_out, int out_size)
{
    (void)in_sizes; (void)n_in; (void)out_size;

    const float* x        = (const float*)d_in[0];
    const float* rel      = (const float*)d_in[1];
    const float* adj      = (const float*)d_in[2];
    const int*   bnum     = (const int*)  d_in[3];
    const float* Wt       = (const float*)d_in[4];
    const float* b_alpha  = (const float*)d_in[5];
    const float* W_proj   = (const float*)d_in[6];
    const float* b_proj   = (const float*)d_in[7];
    const float* learn_w  = (const float*)d_in[8];
    const float* w_alpha0 = (const float*)d_in[9];
    const float* w_vi0    = (const float*)d_in[10];
    const float* w_vj0    = (const float*)d_in[11];
    const float* bias_h0  = (const float*)d_in[12];
    const float* w_node0  = (const float*)d_in[13];
    /* d_in[14] = l1_w_alpha: unused (alpha2 discarded) */
    const float* w_vi1    = (const float*)d_in[15];
    const float* w_vj1    = (const float*)d_in[16];
    const float* bias_h1  = (const float*)d_in[17];
    const float* w_node1  = (const float*)d_in[18];

    float* out      = (float*)d_out;
    float* out_x2   = out;
    float* out_sadj = out + 262144;
    float* out_gl   = out + 524288;

    float *xhat, *pnorm, *adj2, *xi0, *c0, *AH0, *x1, *xi1, *c1, *AH1;
    cudaGetSymbolAddress((void**)&xhat,   g_xhat);
    cudaGetSymbolAddress((void**)&pnorm,  g_pnorm);
    cudaGetSymbolAddress((void**)&adj2,   g_adj2);
    cudaGetSymbolAddress((void**)&xi0,    g_xi0);
    cudaGetSymbolAddress((void**)&c0,     g_c0);
    cudaGetSymbolAddress((void**)&AH0,    g_AH0);
    cudaGetSymbolAddress((void**)&x1,     g_x1);
    cudaGetSymbolAddress((void**)&xi1,    g_xi1);
    cudaGetSymbolAddress((void**)&c1,     g_c1);
    cudaGetSymbolAddress((void**)&AH1,    g_AH1);

    // ---- prep: convert + transpose + swizzle w_alpha0 image ----
    prep_w_kernel<<<256, 256>>>(w_alpha0);

    // ---- graph learning ----
    rowgemm_kernel<<<256, 128>>>(x, W_proj, b_proj, xhat);
    pair_softadj_kernel<<<1024, 256>>>(xhat, adj, learn_w, bnum, out_sadj, adj2, pnorm);
    glloss_part_kernel<<<512, 256>>>(out_sadj, pnorm);
    glloss_fin_kernel<<<4, 128>>>(bnum, out_gl);

    // ---- GCN layer 0 inputs ----
    const int DUAL_SMEM = 18432 * 4;
    cudaFuncSetAttribute(rowgemm8_dual_kernel, cudaFuncAttributeMaxDynamicSharedMemorySize, DUAL_SMEM);
    rowgemm8_dual_kernel<<<128, 256, DUAL_SMEM>>>(x, w_vi0, w_vj0, bias_h0, b_alpha, xi0, c0);

    // ---- AH0 (H on the fly) -> x1 -> xi1/c1 ----
    ah0_kernel<<<1024, 256>>>(xi0, c0, rel, Wt, adj2, AH0);
    rowgemm8_kernel<<<128, 256>>>(AH0, w_node0, x1);
    rowgemm8_dual_kernel<<<128, 256, DUAL_SMEM>>>(x1, w_vi1, w_vj1, bias_h1, nullptr, xi1, c1);

    // ---- fused layer0 GEMM + layer1 reduction (alpha1 never leaves registers) ----
    cudaFuncSetAttribute(layer01_mma_kernel, cudaFuncAttributeMaxDynamicSharedMemorySize, SM_TOTAL);
    layer01_mma_kernel<<<1024, 256, SM_TOTAL>>>(xi0, c0, rel, Wt, adj2, xi1, c1, AH1);

    rowgemm8_kernel<<<128, 256>>>(AH1, w_node1, out_x2);
}

// round 10
// speedup vs baseline: 3.4177x; 1.0292x over previous
#include <cuda_runtime.h>
#include <cuda_fp16.h>
#include <cstdint>
#include <cstddef>

// Problem constants
#define PB 4
#define PN 256
#define PD 256
#define PL 128
#define POUT 256

// ============================ helpers ============================
__device__ __forceinline__ uint32_t smem_to_u32(const void* smem_ptr) {
    uint32_t addr;
    asm("{ .reg .u64 tmp; cvta.to.shared.u64 tmp, %1; cvt.u32.u64 %0, tmp; }"
        : "=r"(addr) : "l"(smem_ptr));
    return addr;
}

__device__ __forceinline__ void ldsm4(uint32_t* r, uint32_t addr) {
    asm volatile("ldmatrix.sync.aligned.m8n8.x4.shared.b16 {%0,%1,%2,%3}, [%4];"
        : "=r"(r[0]), "=r"(r[1]), "=r"(r[2]), "=r"(r[3]) : "r"(addr));
}

__device__ __forceinline__ void mma_f16(float* c, const uint32_t* a, uint32_t b0, uint32_t b1) {
    asm volatile(
        "mma.sync.aligned.m16n8k16.row.col.f32.f16.f16.f32 "
        "{%0,%1,%2,%3}, {%4,%5,%6,%7}, {%8,%9}, {%0,%1,%2,%3};"
        : "+f"(c[0]), "+f"(c[1]), "+f"(c[2]), "+f"(c[3])
        : "r"(a[0]), "r"(a[1]), "r"(a[2]), "r"(a[3]), "r"(b0), "r"(b1));
}

// ---------------- scratch (device globals; no runtime allocation) ----------------
__device__ float g_xhat [PB*PN*PL];
__device__ float g_pnorm[PB*PN*PN];
__device__ float g_adj2 [PB*PN*PN];
__device__ float g_xi0  [PB*PN*POUT];
__device__ float g_c0   [PB*PN*POUT];
__device__ float g_AH0  [PB*PN*POUT];
__device__ float g_xi1  [PB*PN*POUT];
__device__ float g_c1   [PB*PN*POUT];
__device__ float g_AH1a [PB*PN*POUT];
__device__ float g_AH1b [PB*PN*POUT];
__device__ float g_part1[512];
__device__ float g_part2[512];
// Pre-converted w_alpha image: [kh:2][n:256][k:128] fp16, 256B rows,
// XOR-swizzled by (n&7)<<4 -> ldmatrix conflict-free, verbatim staging.
// kh stride = 256 rows * 256 B = 65536 BYTES.
__device__ __half g_wimg1[2*256*128];

// ---------------------------------------------------------------------------
// Prep: convert w_alpha0 (k=d:256, n:256) into fp16 transposed image.
// ---------------------------------------------------------------------------
__global__ void prep_w_kernel(const float* __restrict__ w_alpha)
{
    const int e = blockIdx.x * 256 + threadIdx.x;    // 65536
    const int k = e >> 8;
    const int n = e & 255;
    const __half hi = __float2half_rn(w_alpha[k * 256 + n]);
    const int kh = k >> 7, kk = k & 127;
    const uint32_t off = kh * 65536u + n * 256u + (uint32_t)((kk * 2) ^ ((n & 7) << 4));
    *reinterpret_cast<__half*>(reinterpret_cast<char*>(g_wimg1) + off) = hi;
}

// ---------------------------------------------------------------------------
// Simple row GEMM for xhat (K=128)
// ---------------------------------------------------------------------------
__global__ void rowgemm_kernel(const float* __restrict__ X, const float* __restrict__ W,
                               const float* __restrict__ bias_k, float* __restrict__ out)
{
    __shared__ float xs[4 * 256];
    const int r0 = blockIdx.x * 4;
    const int t  = threadIdx.x;
    for (int f = t; f < 4 * 256; f += 128) xs[f] = X[r0 * 256 + f];
    __syncthreads();

    float acc[4] = {0.f, 0.f, 0.f, 0.f};
#pragma unroll 8
    for (int d = 0; d < 256; ++d) {
        const float wv = __ldg(&W[d * 128 + t]);
#pragma unroll
        for (int r = 0; r < 4; ++r) acc[r] = fmaf(xs[r * 256 + d], wv, acc[r]);
    }
    const float bk = __ldg(&bias_k[t]);
#pragma unroll
    for (int r = 0; r < 4; ++r) out[(r0 + r) * 128 + t] = acc[r] + bk;
}

// ---------------------------------------------------------------------------
// Dual row GEMM (layer-0 inputs): out1 = X@W1 ; out2 = X@W2 + bias_nk + bias_k
// ---------------------------------------------------------------------------
__global__ __launch_bounds__(256) void rowgemm8_dual_kernel(
    const float* __restrict__ X, const float* __restrict__ W1, const float* __restrict__ W2,
    const float* __restrict__ bias_nk, const float* __restrict__ bias_k,
    float* __restrict__ out1, float* __restrict__ out2)
{
    extern __shared__ float dsm[];
    float* xs  = dsm;          // 2048
    float* ws1 = dsm + 2048;   // 8192
    float* ws2 = dsm + 10240;  // 8192
    const int r0 = blockIdx.x * 8;
    const int t  = threadIdx.x;
    for (int f = t; f < 8 * 256; f += 256) xs[f] = X[r0 * 256 + f];

    float a1[8], a2[8];
#pragma unroll
    for (int r = 0; r < 8; ++r) { a1[r] = 0.f; a2[r] = 0.f; }

    for (int dt = 0; dt < 8; ++dt) {
        __syncthreads();
        const float4* W1v = reinterpret_cast<const float4*>(W1 + dt * 32 * 256);
        const float4* W2v = reinterpret_cast<const float4*>(W2 + dt * 32 * 256);
        float4* w1s = reinterpret_cast<float4*>(ws1);
        float4* w2s = reinterpret_cast<float4*>(ws2);
        for (int i = t; i < 2048; i += 256) { w1s[i] = __ldg(&W1v[i]); w2s[i] = __ldg(&W2v[i]); }
        __syncthreads();
#pragma unroll
        for (int d4 = 0; d4 < 32; d4 += 4) {
            float u0 = ws1[(d4 + 0) * 256 + t], v0 = ws2[(d4 + 0) * 256 + t];
            float u1 = ws1[(d4 + 1) * 256 + t], v1 = ws2[(d4 + 1) * 256 + t];
            float u2 = ws1[(d4 + 2) * 256 + t], v2 = ws2[(d4 + 2) * 256 + t];
            float u3 = ws1[(d4 + 3) * 256 + t], v3 = ws2[(d4 + 3) * 256 + t];
#pragma unroll
            for (int r = 0; r < 8; ++r) {
                const float4 xv = *reinterpret_cast<const float4*>(&xs[r * 256 + dt * 32 + d4]);
                a1[r] = fmaf(xv.x, u0, a1[r]); a2[r] = fmaf(xv.x, v0, a2[r]);
                a1[r] = fmaf(xv.y, u1, a1[r]); a2[r] = fmaf(xv.y, v1, a2[r]);
                a1[r] = fmaf(xv.z, u2, a1[r]); a2[r] = fmaf(xv.z, v2, a2[r]);
                a1[r] = fmaf(xv.w, u3, a1[r]); a2[r] = fmaf(xv.w, v3, a2[r]);
            }
        }
    }
    const float bk = bias_k ? __ldg(&bias_k[t]) : 0.f;
#pragma unroll
    for (int r = 0; r < 8; ++r) {
        const int row = r0 + r;
        out1[row * 256 + t] = a1[r];
        out2[row * 256 + t] = a2[r] + bk + __ldg(&bias_nk[(row & (PN - 1)) * 256 + t]);
    }
}

// ---------------------------------------------------------------------------
// Fused chain: x1 = relu(AH0 @ Wn0); xi1 = x1 @ Wvi1; c1 = x1 @ Wvj1 + bias_h1.
// All row-local. x1 never leaves SMEM.
// ---------------------------------------------------------------------------
__global__ __launch_bounds__(256) void chain_kernel(
    const float* __restrict__ AH0, const float* __restrict__ Wn0,
    const float* __restrict__ Wvi1, const float* __restrict__ Wvj1,
    const float* __restrict__ bias_h1,
    float* __restrict__ xi1, float* __restrict__ c1)
{
    extern __shared__ float dsm[];
    float* xs  = dsm;          // 2048
    float* ws1 = dsm + 2048;   // 8192
    float* ws2 = dsm + 10240;  // 8192
    const int r0 = blockIdx.x * 8;
    const int t  = threadIdx.x;
    for (int f = t; f < 8 * 256; f += 256) xs[f] = AH0[r0 * 256 + f];

    // ---- phase 1: x1 = relu(AH0 @ Wn0) ----
    float acc[8];
#pragma unroll
    for (int r = 0; r < 8; ++r) acc[r] = 0.f;

    for (int dt = 0; dt < 8; ++dt) {
        __syncthreads();
        const float4* Wv = reinterpret_cast<const float4*>(Wn0 + dt * 32 * 256);
        float4* wsv = reinterpret_cast<float4*>(ws1);
        for (int i = t; i < 2048; i += 256) wsv[i] = __ldg(&Wv[i]);
        __syncthreads();
#pragma unroll
        for (int d4 = 0; d4 < 32; d4 += 4) {
            float wv0 = ws1[(d4 + 0) * 256 + t];
            float wv1 = ws1[(d4 + 1) * 256 + t];
            float wv2 = ws1[(d4 + 2) * 256 + t];
            float wv3 = ws1[(d4 + 3) * 256 + t];
#pragma unroll
            for (int r = 0; r < 8; ++r) {
                const float4 xv = *reinterpret_cast<const float4*>(&xs[r * 256 + dt * 32 + d4]);
                acc[r] = fmaf(xv.x, wv0, acc[r]);
                acc[r] = fmaf(xv.y, wv1, acc[r]);
                acc[r] = fmaf(xv.z, wv2, acc[r]);
                acc[r] = fmaf(xv.w, wv3, acc[r]);
            }
        }
    }
    __syncthreads();
#pragma unroll
    for (int r = 0; r < 8; ++r) xs[r * 256 + t] = fmaxf(acc[r], 0.f);   // x1 in smem

    // ---- phase 2: xi1 = x1@Wvi1 ; c1 = x1@Wvj1 + bias_h1 ----
    float a1[8], a2[8];
#pragma unroll
    for (int r = 0; r < 8; ++r) { a1[r] = 0.f; a2[r] = 0.f; }

    for (int dt = 0; dt < 8; ++dt) {
        __syncthreads();
        const float4* W1v = reinterpret_cast<const float4*>(Wvi1 + dt * 32 * 256);
        const float4* W2v = reinterpret_cast<const float4*>(Wvj1 + dt * 32 * 256);
        float4* w1s = reinterpret_cast<float4*>(ws1);
        float4* w2s = reinterpret_cast<float4*>(ws2);
        for (int i = t; i < 2048; i += 256) { w1s[i] = __ldg(&W1v[i]); w2s[i] = __ldg(&W2v[i]); }
        __syncthreads();
#pragma unroll
        for (int d4 = 0; d4 < 32; d4 += 4) {
            float u0 = ws1[(d4 + 0) * 256 + t], v0 = ws2[(d4 + 0) * 256 + t];
            float u1 = ws1[(d4 + 1) * 256 + t], v1 = ws2[(d4 + 1) * 256 + t];
            float u2 = ws1[(d4 + 2) * 256 + t], v2 = ws2[(d4 + 2) * 256 + t];
            float u3 = ws1[(d4 + 3) * 256 + t], v3 = ws2[(d4 + 3) * 256 + t];
#pragma unroll
            for (int r = 0; r < 8; ++r) {
                const float4 xv = *reinterpret_cast<const float4*>(&xs[r * 256 + dt * 32 + d4]);
                a1[r] = fmaf(xv.x, u0, a1[r]); a2[r] = fmaf(xv.x, v0, a2[r]);
                a1[r] = fmaf(xv.y, u1, a1[r]); a2[r] = fmaf(xv.y, v1, a2[r]);
                a1[r] = fmaf(xv.z, u2, a1[r]); a2[r] = fmaf(xv.z, v2, a2[r]);
                a1[r] = fmaf(xv.w, u3, a1[r]); a2[r] = fmaf(xv.w, v3, a2[r]);
            }
        }
    }
#pragma unroll
    for (int r = 0; r < 8; ++r) {
        const int row = r0 + r;
        xi1[row * 256 + t] = a1[r];
        c1[row * 256 + t]  = a2[r] + __ldg(&bias_h1[(row & (PN - 1)) * 256 + t]);
    }
}

// ---------------------------------------------------------------------------
// Final: out = relu((A + B) @ W)  -- sums the two AH1 partial buffers on load.
// ---------------------------------------------------------------------------
__global__ __launch_bounds__(256) void rowgemm8_sum_kernel(
    const float* __restrict__ A, const float* __restrict__ B,
    const float* __restrict__ W, float* __restrict__ out)
{
    __shared__ float xs[8 * 256];
    __shared__ float ws[32 * 256];
    const int r0 = blockIdx.x * 8;
    const int t  = threadIdx.x;
    for (int f = t; f < 8 * 256; f += 256) xs[f] = A[r0 * 256 + f] + B[r0 * 256 + f];

    float acc[8];
#pragma unroll
    for (int r = 0; r < 8; ++r) acc[r] = 0.f;

    for (int dt = 0; dt < 8; ++dt) {
        __syncthreads();
        const float4* Wv = reinterpret_cast<const float4*>(W + dt * 32 * 256);
        float4* wsv = reinterpret_cast<float4*>(ws);
        for (int i = t; i < 2048; i += 256) wsv[i] = __ldg(&Wv[i]);
        __syncthreads();
#pragma unroll
        for (int d4 = 0; d4 < 32; d4 += 4) {
            float wv0 = ws[(d4 + 0) * 256 + t];
            float wv1 = ws[(d4 + 1) * 256 + t];
            float wv2 = ws[(d4 + 2) * 256 + t];
            float wv3 = ws[(d4 + 3) * 256 + t];
#pragma unroll
            for (int r = 0; r < 8; ++r) {
                const float4 xv = *reinterpret_cast<const float4*>(&xs[r * 256 + dt * 32 + d4]);
                acc[r] = fmaf(xv.x, wv0, acc[r]);
                acc[r] = fmaf(xv.y, wv1, acc[r]);
                acc[r] = fmaf(xv.z, wv2, acc[r]);
                acc[r] = fmaf(xv.w, wv3, acc[r]);
            }
        }
    }
#pragma unroll
    for (int r = 0; r < 8; ++r) out[(r0 + r) * 256 + t] = fmaxf(acc[r], 0.f);
}

// ---------------------------------------------------------------------------
// Fused graph-learning kernel.
// ---------------------------------------------------------------------------
__global__ void pair_softadj_kernel(const float* __restrict__ xhat,
                                    const float* __restrict__ adj,
                                    const float* __restrict__ learn_w,
                                    const int*   __restrict__ box_num,
                                    float* __restrict__ soft_adj_out,
                                    float* __restrict__ adj2,
                                    float* __restrict__ pair_norm)
{
    const int row = blockIdx.x;
    const int b = row >> 8;
    const int i = row & 255;
    const int t = threadIdx.x;
    const int warp = t >> 5, lane = t & 31;

    __shared__ float xi_s[128];
    __shared__ float w_s[128];
    __shared__ float sval[256];
    __shared__ float red[256];
    __shared__ float wsum_s, rmax_s;

    if (t < 128) { xi_s[t] = xhat[row * 128 + t]; w_s[t] = learn_w[t]; }
    __syncthreads();
    if (t == 0) {
        float s = 0.f;
        for (int d = 0; d < 128; ++d) s += w_s[d];
        wsum_s = s;
    }
    __syncthreads();

    const int bn = box_num[b];
    const bool vi = (i < bn);
    const float wsum = wsum_s;
    const float4 xi4 = reinterpret_cast<const float4*>(xi_s)[lane];
    const float4 w4  = reinterpret_cast<const float4*>(w_s)[lane];

    for (int j = warp; j < 256; j += 8) {
        const float4 xj4 = __ldg(reinterpret_cast<const float4*>(xhat + (b * 256 + j) * 128) + lane);
        const float d0 = xi4.x - xj4.x, d1 = xi4.y - xj4.y;
        const float d2 = xi4.z - xj4.z, d3 = xi4.w - xj4.w;
        float s = fabsf(d0) * w4.x + fabsf(d1) * w4.y + fabsf(d2) * w4.z + fabsf(d3) * w4.w;
        float q = d0 * d0 + d1 * d1 + d2 * d2 + d3 * d3;
#pragma unroll
        for (int off = 16; off; off >>= 1) {
            s += __shfl_down_sync(0xffffffffu, s, off);
            q += __shfl_down_sync(0xffffffffu, q, off);
        }
        if (lane == 0) {
            const float m = (vi && (j < bn)) ? 0.f : -1.f;
            float v = s + m * wsum;
            v = (v > 0.f) ? v : 0.01f * v;
            sval[j] = v;
            pair_norm[row * 256 + j] = sqrtf(q + 1e-12f);
        }
    }
    __syncthreads();

    const float v = sval[t];
    red[t] = v;
    __syncthreads();
    for (int sft = 128; sft; sft >>= 1) {
        if (t < sft) red[t] = fmaxf(red[t], red[t + sft]);
        __syncthreads();
    }
    if (t == 0) rmax_s = red[0];
    __syncthreads();

    const float a = adj[row * 256 + t];
    const float e = expf(v - rmax_s) * a;
    red[t] = e;
    __syncthreads();
    for (int sft = 128; sft; sft >>= 1) {
        if (t < sft) red[t] += red[t + sft];
        __syncthreads();
    }
    const float sa = e / red[0] + 1e-10f;
    soft_adj_out[row * 256 + t] = sa;
    adj2[row * 256 + t] = a * sa;
}

// ---------------------------------------------------------------------------
// gl_loss two-phase reduction.
// ---------------------------------------------------------------------------
__global__ void glloss_part_kernel(const float* __restrict__ soft_adj,
                                   const float* __restrict__ pair_norm)
{
    const int blk = blockIdx.x;
    const int b = blk >> 7;
    const int t = threadIdx.x;
    const int base = b * 65536 + (blk & 127) * 512;
    float s1 = 0.f, s2 = 0.f;
#pragma unroll
    for (int u = 0; u < 2; ++u) {
        const int idx = base + u * 256 + t;
        const float s = soft_adj[idx];
        s1 += expf(s + pair_norm[idx]);
        s2 += s * s;
    }
    __shared__ float r1[256], r2[256];
    r1[t] = s1; r2[t] = s2;
    __syncthreads();
    for (int sft = 128; sft; sft >>= 1) {
        if (t < sft) { r1[t] += r1[t + sft]; r2[t] += r2[t + sft]; }
        __syncthreads();
    }
    if (t == 0) { g_part1[blk] = r1[0]; g_part2[blk] = r2[0]; }
}

__global__ void glloss_fin_kernel(const int* __restrict__ box_num, float* __restrict__ gl_out)
{
    const int b = blockIdx.x;
    const int t = threadIdx.x;
    __shared__ float r1[128], r2[128];
    r1[t] = g_part1[b * 128 + t];
    r2[t] = g_part2[b * 128 + t];
    __syncthreads();
    for (int sft = 64; sft; sft >>= 1) {
        if (t < sft) { r1[t] += r1[t + sft]; r2[t] += r2[t + sft]; }
        __syncthreads();
    }
    if (t == 0) {
        const float bnf = (float)box_num[b];
        gl_out[b] = r1[0] / (bnf * bnf) + 1e-4f * sqrtf(r2[0]);
    }
}

// ---------------------------------------------------------------------------
// Kernel A: AH0 only. H built on the fly, never stored.
// ---------------------------------------------------------------------------
__global__ __launch_bounds__(256) void ah0_kernel(
    const float* __restrict__ xi0, const float* __restrict__ c0,
    const float* __restrict__ rel, const float* __restrict__ Wt,
    const float* __restrict__ adj2, float* __restrict__ AH0)
{
    __shared__ float rel_s[1536];
    __shared__ float wt_s[1536];
    __shared__ float adj_s[256];
    __shared__ float ahred[2048];
    __shared__ float xi_s[256];

    const int t = threadIdx.x;
    const int wid = t >> 5;
    const int lane = t & 31;
    const int row = blockIdx.x;
    const int b = row >> 8;

    const float* relrow = rel + (size_t)row * 256 * 6;
    for (int f = t; f < 1536; f += 256) { rel_s[f] = relrow[f]; wt_s[f] = Wt[f]; }
    adj_s[t] = adj2[row * 256 + t];
    xi_s[t]  = xi0[row * 256 + t];
    __syncthreads();

    const float2* c02 = reinterpret_cast<const float2*>(c0 + b * 65536);

#pragma unroll
    for (int kq = 0; kq < 4; ++kq) {
        const int p = lane + 32 * kq;
        const int k = 2 * p;
        const float2 xiv = *reinterpret_cast<const float2*>(&xi_s[k]);
        float2 wtv[6];
#pragma unroll
        for (int c = 0; c < 6; ++c)
            wtv[c] = *reinterpret_cast<const float2*>(&wt_s[c * 256 + k]);

        float ah0 = 0.f, ah1 = 0.f;
#pragma unroll 2
        for (int s = 0; s < 32; ++s) {
            const int j = wid * 32 + s;
            const float* rj = rel_s + j * 6;
            const float2 cv = __ldg(&c02[j * 128 + p]);
            float a0 = rj[0]*wtv[0].x + rj[1]*wtv[1].x + rj[2]*wtv[2].x
                     + rj[3]*wtv[3].x + rj[4]*wtv[4].x + rj[5]*wtv[5].x;
            float a1 = rj[0]*wtv[0].y + rj[1]*wtv[1].y + rj[2]*wtv[2].y
                     + rj[3]*wtv[3].y + rj[4]*wtv[4].y + rj[5]*wtv[5].y;
            const float aw = adj_s[j];
            ah0 = fmaf(aw, fmaxf(xiv.x + cv.x + a0, 0.f), ah0);
            ah1 = fmaf(aw, fmaxf(xiv.y + cv.y + a1, 0.f), ah1);
        }
        ahred[wid * 256 + k]     = ah0;
        ahred[wid * 256 + k + 1] = ah1;
    }
    __syncthreads();

    float s = 0.f;
#pragma unroll
    for (int g = 0; g < 8; ++g) s += ahred[g * 256 + t];
    AH0[row * 256 + t] = s;
}

// ---------------------------------------------------------------------------
// Kernel C: fused layer0 GEMM + layer1 reduction, one jh half PER BLOCK.
// Grid (1024, 2): blockIdx.x = (b,i) row, blockIdx.y = jh half.
// Warp w builds+owns j rows [jh*128 + 16w, +16); HMMA C = H_half @ w_alpha;
// epilogue computes AH1 partials for this half -> AH1part[jh].
// alpha1 never leaves registers. smem 110KB -> 2 blocks/SM.
// ---------------------------------------------------------------------------
// SMEM byte offsets
#define SM_A       0         // 128 j x 256 k fp16, 512B rows, xor-swizzled = 65536
#define SM_B1      65536     // 32768
#define SM_REL     98304     // 3072
#define SM_ADJ     101376    // 1024
#define SM_AHRED   102400    // 8192 (8 warps x 256 n)
#define SM_XI      110592    // 1024
#define SM_XI1     111616    // 1024
#define SM_TOTAL   112640

__global__ void __launch_bounds__(256, 2) layer01_mma_kernel(
    const float* __restrict__ xi0, const float* __restrict__ c0,
    const float* __restrict__ rel, const float* __restrict__ Wt,
    const float* __restrict__ adj2,
    const float* __restrict__ xi1, const float* __restrict__ c1,
    float* __restrict__ AH1a, float* __restrict__ AH1b)
{
    extern __shared__ char sm[];
    const uint32_t sb = smem_to_u32(sm);
    float* rel_s  = reinterpret_cast<float*>(sm + SM_REL);
    float* adj_s  = reinterpret_cast<float*>(sm + SM_ADJ);
    float* ah1red = reinterpret_cast<float*>(sm + SM_AHRED);
    float* xi_s   = reinterpret_cast<float*>(sm + SM_XI);
    float* xi1_s  = reinterpret_cast<float*>(sm + SM_XI1);

    const int t = threadIdx.x;
    const int wid = t >> 5;
    const int lane = t & 31;
    const int row = blockIdx.x;      // b*256 + i
    const int jh  = blockIdx.y;      // 0 or 1
    const int b = row >> 8;

    adj_s[t]  = adj2[row * 256 + t];
    xi_s[t]   = xi0[row * 256 + t];
    xi1_s[t]  = xi1[row * 256 + t];
    const float* relrow = rel + ((size_t)row * 256 + jh * 128) * 6;
    for (int f = t; f < 768; f += 256) rel_s[f] = relrow[f];
    __syncthreads();

    const float* c0b = c0 + b * 65536;
    const float* c1b = c1 + b * 65536;

    // --- per-lane ldmatrix address components (j-local, 128-row A tile) ---
    const int jrl = wid * 16 + (lane & 15);
    const uint32_t acolByte = (uint32_t)((lane >> 4) * 16);
    const uint32_t jmask = (uint32_t)((jrl & 7) << 4);
    const uint32_t aRowByte = (uint32_t)jrl * 512u;
    const int nrow_l = (lane & 7) | ((lane & 16) >> 1);
    const uint32_t kbB = (uint32_t)(((lane >> 3) & 1) * 16);
    const uint32_t nmask = (uint32_t)((nrow_l & 7) << 4);
    const uint32_t bRowByte = (uint32_t)nrow_l * 256u;

    const int r  = lane >> 2;    // 0..7
    const int cq = lane & 3;     // 0..3

    // ---- build H half (128 j x 256 k) as fp16; warp w owns rows 16w..16w+15 ----
#pragma unroll
    for (int kq = 0; kq < 4; ++kq) {
        const int p = lane + 32 * kq;     // k-pair 0..127
        const int k = 2 * p;
        const float2 xiv = *reinterpret_cast<const float2*>(&xi_s[k]);
        float2 wtv[6];
#pragma unroll
        for (int c = 0; c < 6; ++c)
            wtv[c] = __ldg(reinterpret_cast<const float2*>(&Wt[c * 256 + k]));

        const float2* c02 = reinterpret_cast<const float2*>(c0b);
#pragma unroll 2
        for (int s = 0; s < 16; ++s) {
            const int jl = wid * 16 + s;
            const int j = jh * 128 + jl;
            const float* rj = rel_s + jl * 6;
            const float2 cv = __ldg(&c02[j * 128 + p]);
            float a0 = rj[0]*wtv[0].x + rj[1]*wtv[1].x + rj[2]*wtv[2].x
                     + rj[3]*wtv[3].x + rj[4]*wtv[4].x + rj[5]*wtv[5].x;
            float a1 = rj[0]*wtv[0].y + rj[1]*wtv[1].y + rj[2]*wtv[2].y
                     + rj[3]*wtv[3].y + rj[4]*wtv[4].y + rj[5]*wtv[5].y;
            __half2 hp;
            hp.x = __float2half_rn(fmaxf(xiv.x + cv.x + a0, 0.f));
            hp.y = __float2half_rn(fmaxf(xiv.y + cv.y + a1, 0.f));
            const uint32_t off = (uint32_t)jl * 512u + ((uint32_t)(4 * p) ^ ((uint32_t)(jl & 7) << 4));
            *reinterpret_cast<uint32_t*>(sm + SM_A + off) = *reinterpret_cast<uint32_t*>(&hp);
        }
    }

#pragma unroll 1
    for (int nc = 0; nc < 2; ++nc) {
        float C[16][4];
#pragma unroll
        for (int nt = 0; nt < 16; ++nt)
#pragma unroll
            for (int u = 0; u < 4; ++u) C[nt][u] = 0.f;

#pragma unroll 1
        for (int kh = 0; kh < 2; ++kh) {
            __syncthreads();   // prior B consumers done (first iter: A build visibility)
            // ---- stage B slice (verbatim pre-swizzled copy) ----
            {
                const uint4* s1 = reinterpret_cast<const uint4*>(
                    reinterpret_cast<const char*>(g_wimg1) + kh * 65536 + nc * 32768);
                uint4* d1 = reinterpret_cast<uint4*>(sm + SM_B1);
                for (int i = t; i < 2048; i += 256) d1[i] = __ldg(&s1[i]);
            }
            __syncthreads();

            // ---- HMMA: C += A * B ----
#pragma unroll 1
            for (int ks = 0; ks < 8; ++ks) {
                const uint32_t aoff = ((uint32_t)((kh * 8 + ks) * 32) + acolByte) ^ jmask;
                const uint32_t boff = ((uint32_t)(ks * 32) + kbB) ^ nmask;
                uint32_t Ah[4];
                ldsm4(Ah, sb + SM_A + aRowByte + aoff);

                uint32_t bb[4];
#pragma unroll
                for (int p = 0; p < 8; ++p) {
                    ldsm4(bb, sb + SM_B1 + (uint32_t)p * 4096 + bRowByte + boff);
                    mma_f16(C[2 * p],     Ah, bb[0], bb[1]);
                    mma_f16(C[2 * p + 1], Ah, bb[2], bb[3]);
                }
            }
        }

        // ---- fused layer1 epilogue: consume alpha1 = relu(C) in registers ----
        {
            float acc0[16], acc1[16];
#pragma unroll
            for (int nt = 0; nt < 16; ++nt) { acc0[nt] = 0.f; acc1[nt] = 0.f; }

            const int j1 = jh * 128 + wid * 16 + r;
            const int j2 = j1 + 8;
            const float aw1 = adj_s[j1];
            const float aw2 = adj_s[j2];
#pragma unroll
            for (int nt = 0; nt < 16; ++nt) {
                const int n0 = nc * 128 + nt * 8 + 2 * cq;
                const float2 cA = __ldg(reinterpret_cast<const float2*>(c1b + j1 * 256 + n0));
                const float2 cB = __ldg(reinterpret_cast<const float2*>(c1b + j2 * 256 + n0));
                const float x0 = xi1_s[n0];
                const float x1v = xi1_s[n0 + 1];
                const float a0 = fmaxf(C[nt][0], 0.f);
                const float a1 = fmaxf(C[nt][1], 0.f);
                const float a2 = fmaxf(C[nt][2], 0.f);
                const float a3 = fmaxf(C[nt][3], 0.f);
                acc0[nt] = fmaf(aw1, fmaxf(x0 + cA.x + a0, 0.f), acc0[nt]);
                acc1[nt] = fmaf(aw1, fmaxf(x1v + cA.y + a1, 0.f), acc1[nt]);
                acc0[nt] = fmaf(aw2, fmaxf(x0 + cB.x + a2, 0.f), acc0[nt]);
                acc1[nt] = fmaf(aw2, fmaxf(x1v + cB.y + a3, 0.f), acc1[nt]);
            }

            // reduce over the warp's 16 j (r-lanes, bits 2..4); n ranges disjoint per nc -> plain store
#pragma unroll
            for (int nt = 0; nt < 16; ++nt) {
                float v0 = acc0[nt], v1 = acc1[nt];
#pragma unroll
                for (int off = 4; off <= 16; off <<= 1) {
                    v0 += __shfl_xor_sync(0xffffffffu, v0, off);
                    v1 += __shfl_xor_sync(0xffffffffu, v1, off);
                }
                if (r == 0) {
                    const int n0 = nc * 128 + nt * 8 + 2 * cq;
                    ah1red[wid * 256 + n0]     = v0;
                    ah1red[wid * 256 + n0 + 1] = v1;
                }
            }
        }
    }
    __syncthreads();

    // cross-warp reduce -> AH1part[jh]
    {
        float s = 0.f;
#pragma unroll
        for (int g = 0; g < 8; ++g) s += ah1red[g * 256 + t];
        float* dst = jh ? AH1b : AH1a;
        dst[row * 256 + t] = s;
    }
}

// ---------------------------------------------------------------------------
extern "C" void kernel_launch(void* const* d_in, const int* in_sizes, int n_in,
                              void* d_out, int out_size)
{
    (void)in_sizes; (void)n_in; (void)out_size;

    const float* x        = (const float*)d_in[0];
    const float* rel      = (const float*)d_in[1];
    const float* adj      = (const float*)d_in[2];
    const int*   bnum     = (const int*)  d_in[3];
    const float* Wt       = (const float*)d_in[4];
    const float* b_alpha  = (const float*)d_in[5];
    const float* W_proj   = (const float*)d_in[6];
    const float* b_proj   = (const float*)d_in[7];
    const float* learn_w  = (const float*)d_in[8];
    const float* w_alpha0 = (const float*)d_in[9];
    const float* w_vi0    = (const float*)d_in[10];
    const float* w_vj0    = (const float*)d_in[11];
    const float* bias_h0  = (const float*)d_in[12];
    const float* w_node0  = (const float*)d_in[13];
    /* d_in[14] = l1_w_alpha: unused (alpha2 discarded) */
    const float* w_vi1    = (const float*)d_in[15];
    const float* w_vj1    = (const float*)d_in[16];
    const float* bias_h1  = (const float*)d_in[17];
    const float* w_node1  = (const float*)d_in[18];

    float* out      = (float*)d_out;
    float* out_x2   = out;
    float* out_sadj = out + 262144;
    float* out_gl   = out + 524288;

    float *xhat, *pnorm, *adj2, *xi0, *c0, *AH0, *xi1, *c1, *AH1a, *AH1b;
    cudaGetSymbolAddress((void**)&xhat,  g_xhat);
    cudaGetSymbolAddress((void**)&pnorm, g_pnorm);
    cudaGetSymbolAddress((void**)&adj2,  g_adj2);
    cudaGetSymbolAddress((void**)&xi0,   g_xi0);
    cudaGetSymbolAddress((void**)&c0,    g_c0);
    cudaGetSymbolAddress((void**)&AH0,   g_AH0);
    cudaGetSymbolAddress((void**)&xi1,   g_xi1);
    cudaGetSymbolAddress((void**)&c1,    g_c1);
    cudaGetSymbolAddress((void**)&AH1a,  g_AH1a);
    cudaGetSymbolAddress((void**)&AH1b,  g_AH1b);

    // ---- prep: convert + transpose + swizzle w_alpha0 image ----
    prep_w_kernel<<<256, 256>>>(w_alpha0);

    // ---- graph learning ----
    rowgemm_kernel<<<256, 128>>>(x, W_proj, b_proj, xhat);
    pair_softadj_kernel<<<1024, 256>>>(xhat, adj, learn_w, bnum, out_sadj, adj2, pnorm);
    glloss_part_kernel<<<512, 256>>>(out_sadj, pnorm);
    glloss_fin_kernel<<<4, 128>>>(bnum, out_gl);

    // ---- GCN layer 0 inputs ----
    const int DUAL_SMEM = 18432 * 4;
    cudaFuncSetAttribute(rowgemm8_dual_kernel, cudaFuncAttributeMaxDynamicSharedMemorySize, DUAL_SMEM);
    rowgemm8_dual_kernel<<<128, 256, DUAL_SMEM>>>(x, w_vi0, w_vj0, bias_h0, b_alpha, xi0, c0);

    // ---- AH0 (H on the fly) -> fused chain: x1 -> xi1, c1 ----
    ah0_kernel<<<1024, 256>>>(xi0, c0, rel, Wt, adj2, AH0);
    cudaFuncSetAttribute(chain_kernel, cudaFuncAttributeMaxDynamicSharedMemorySize, DUAL_SMEM);
    chain_kernel<<<128, 256, DUAL_SMEM>>>(AH0, w_node0, w_vi1, w_vj1, bias_h1, xi1, c1);

    // ---- fused layer0 GEMM + layer1 reduction, jh-split grid ----
    cudaFuncSetAttribute(layer01_mma_kernel, cudaFuncAttributeMaxDynamicSharedMemorySize, SM_TOTAL);
    layer01_mma_kernel<<<dim3(1024, 2), 256, SM_TOTAL>>>(xi0, c0, rel, Wt, adj2, xi1, c1, AH1a, AH1b);

    rowgemm8_sum_kernel<<<128, 256>>>(AH1a, AH1b, w_node1, out_x2);
}

// round 11
// speedup vs baseline: 3.6595x; 1.0708x over previous
#include <cuda_runtime.h>
#include <cuda_fp16.h>
#include <cstdint>
#include <cstddef>

// Problem constants
#define PB 4
#define PN 256
#define PD 256
#define PL 128
#define POUT 256

// ============================ helpers ============================
__device__ __forceinline__ uint32_t smem_to_u32(const void* smem_ptr) {
    uint32_t addr;
    asm("{ .reg .u64 tmp; cvta.to.shared.u64 tmp, %1; cvt.u32.u64 %0, tmp; }"
        : "=r"(addr) : "l"(smem_ptr));
    return addr;
}

__device__ __forceinline__ void ldsm4(uint32_t* r, uint32_t addr) {
    asm volatile("ldmatrix.sync.aligned.m8n8.x4.shared.b16 {%0,%1,%2,%3}, [%4];"
        : "=r"(r[0]), "=r"(r[1]), "=r"(r[2]), "=r"(r[3]) : "r"(addr));
}

__device__ __forceinline__ void mma_f16(float* c, const uint32_t* a, uint32_t b0, uint32_t b1) {
    asm volatile(
        "mma.sync.aligned.m16n8k16.row.col.f32.f16.f16.f32 "
        "{%0,%1,%2,%3}, {%4,%5,%6,%7}, {%8,%9}, {%0,%1,%2,%3};"
        : "+f"(c[0]), "+f"(c[1]), "+f"(c[2]), "+f"(c[3])
        : "r"(a[0]), "r"(a[1]), "r"(a[2]), "r"(a[3]), "r"(b0), "r"(b1));
}

// ---- packed f32x2 ops (sm_100+ baseline PTX) ----
typedef unsigned long long ull_t;
__device__ __forceinline__ ull_t pk2(float lo, float hi) {
    ull_t r;
    asm("mov.b64 %0, {%1, %2};" : "=l"(r)
        : "r"(__float_as_uint(lo)), "r"(__float_as_uint(hi)));
    return r;
}
__device__ __forceinline__ void upk2(ull_t v, float& lo, float& hi) {
    uint32_t a, b;
    asm("mov.b64 {%0, %1}, %2;" : "=r"(a), "=r"(b) : "l"(v));
    lo = __uint_as_float(a); hi = __uint_as_float(b);
}
__device__ __forceinline__ ull_t fma2(ull_t a, ull_t b, ull_t c) {
    ull_t d;
    asm("fma.rn.f32x2 %0, %1, %2, %3;" : "=l"(d) : "l"(a), "l"(b), "l"(c));
    return d;
}
__device__ __forceinline__ ull_t add2(ull_t a, ull_t b) {
    ull_t d;
    asm("add.rn.f32x2 %0, %1, %2;" : "=l"(d) : "l"(a), "l"(b));
    return d;
}

// ---------------- scratch (device globals; no runtime allocation) ----------------
__device__ float g_xhat [PB*PN*PL];
__device__ float g_pnorm[PB*PN*PN];
__device__ float g_adj2 [PB*PN*PN];
__device__ float g_xi0  [PB*PN*POUT];
__device__ float g_c0   [PB*PN*POUT];
__device__ float g_AH0  [PB*PN*POUT];
__device__ float g_xi1  [PB*PN*POUT];
__device__ float g_c1   [PB*PN*POUT];
__device__ float g_AH1a [PB*PN*POUT];
__device__ float g_AH1b [PB*PN*POUT];
__device__ float g_part1[512];
__device__ float g_part2[512];
// Pre-converted w_alpha image: [kh:2][n:256][k:128] fp16, 256B rows,
// XOR-swizzled by (n&7)<<4 -> ldmatrix conflict-free, verbatim staging.
// kh stride = 65536 BYTES.
__device__ __half g_wimg1[2*256*128];

// ---------------------------------------------------------------------------
// Simple row GEMM for xhat (K=128)
// ---------------------------------------------------------------------------
__global__ void rowgemm_kernel(const float* __restrict__ X, const float* __restrict__ W,
                               const float* __restrict__ bias_k, float* __restrict__ out)
{
    __shared__ float xs[4 * 256];
    const int r0 = blockIdx.x * 4;
    const int t  = threadIdx.x;
    for (int f = t; f < 4 * 256; f += 128) xs[f] = X[r0 * 256 + f];
    __syncthreads();

    float acc[4] = {0.f, 0.f, 0.f, 0.f};
#pragma unroll 8
    for (int d = 0; d < 256; ++d) {
        const float wv = __ldg(&W[d * 128 + t]);
#pragma unroll
        for (int r = 0; r < 4; ++r) acc[r] = fmaf(xs[r * 256 + d], wv, acc[r]);
    }
    const float bk = __ldg(&bias_k[t]);
#pragma unroll
    for (int r = 0; r < 4; ++r) out[(r0 + r) * 128 + t] = acc[r] + bk;
}

// ---------------------------------------------------------------------------
// Dual row GEMM (layer-0 inputs) + FUSED w_alpha image prep (independent work).
// out1 = X@W1 ; out2 = X@W2 + bias_nk + bias_k
// ---------------------------------------------------------------------------
__global__ __launch_bounds__(256) void rowgemm8_dual_prep_kernel(
    const float* __restrict__ X, const float* __restrict__ W1, const float* __restrict__ W2,
    const float* __restrict__ bias_nk, const float* __restrict__ bias_k,
    const float* __restrict__ w_alpha,
    float* __restrict__ out1, float* __restrict__ out2)
{
    extern __shared__ float dsm[];
    float* xs  = dsm;          // 2048
    float* ws1 = dsm + 2048;   // 8192
    float* ws2 = dsm + 10240;  // 8192
    const int r0 = blockIdx.x * 8;
    const int t  = threadIdx.x;

    // ---- fused prep: convert w_alpha (k=d:256, n:256) into fp16 transposed image ----
    {
        const int base = (blockIdx.x * 256 + t) * 2;
#pragma unroll
        for (int u = 0; u < 2; ++u) {
            const int e = base + u;          // 0..65535
            const int k = e >> 8;
            const int n = e & 255;
            const __half hi = __float2half_rn(__ldg(&w_alpha[k * 256 + n]));
            const int kh = k >> 7, kk = k & 127;
            const uint32_t off = kh * 65536u + n * 256u + (uint32_t)((kk * 2) ^ ((n & 7) << 4));
            *reinterpret_cast<__half*>(reinterpret_cast<char*>(g_wimg1) + off) = hi;
        }
    }

    for (int f = t; f < 8 * 256; f += 256) xs[f] = X[r0 * 256 + f];

    float a1[8], a2[8];
#pragma unroll
    for (int r = 0; r < 8; ++r) { a1[r] = 0.f; a2[r] = 0.f; }

    for (int dt = 0; dt < 8; ++dt) {
        __syncthreads();
        const float4* W1v = reinterpret_cast<const float4*>(W1 + dt * 32 * 256);
        const float4* W2v = reinterpret_cast<const float4*>(W2 + dt * 32 * 256);
        float4* w1s = reinterpret_cast<float4*>(ws1);
        float4* w2s = reinterpret_cast<float4*>(ws2);
        for (int i = t; i < 2048; i += 256) { w1s[i] = __ldg(&W1v[i]); w2s[i] = __ldg(&W2v[i]); }
        __syncthreads();
#pragma unroll
        for (int d4 = 0; d4 < 32; d4 += 4) {
            float u0 = ws1[(d4 + 0) * 256 + t], v0 = ws2[(d4 + 0) * 256 + t];
            float u1 = ws1[(d4 + 1) * 256 + t], v1 = ws2[(d4 + 1) * 256 + t];
            float u2 = ws1[(d4 + 2) * 256 + t], v2 = ws2[(d4 + 2) * 256 + t];
            float u3 = ws1[(d4 + 3) * 256 + t], v3 = ws2[(d4 + 3) * 256 + t];
#pragma unroll
            for (int r = 0; r < 8; ++r) {
                const float4 xv = *reinterpret_cast<const float4*>(&xs[r * 256 + dt * 32 + d4]);
                a1[r] = fmaf(xv.x, u0, a1[r]); a2[r] = fmaf(xv.x, v0, a2[r]);
                a1[r] = fmaf(xv.y, u1, a1[r]); a2[r] = fmaf(xv.y, v1, a2[r]);
                a1[r] = fmaf(xv.z, u2, a1[r]); a2[r] = fmaf(xv.z, v2, a2[r]);
                a1[r] = fmaf(xv.w, u3, a1[r]); a2[r] = fmaf(xv.w, v3, a2[r]);
            }
        }
    }
    const float bk = bias_k ? __ldg(&bias_k[t]) : 0.f;
#pragma unroll
    for (int r = 0; r < 8; ++r) {
        const int row = r0 + r;
        out1[row * 256 + t] = a1[r];
        out2[row * 256 + t] = a2[r] + bk + __ldg(&bias_nk[(row & (PN - 1)) * 256 + t]);
    }
}

// ---------------------------------------------------------------------------
// Fused chain: x1 = relu(AH0 @ Wn0); xi1 = x1 @ Wvi1; c1 = x1 @ Wvj1 + bias_h1.
// ---------------------------------------------------------------------------
__global__ __launch_bounds__(256) void chain_kernel(
    const float* __restrict__ AH0, const float* __restrict__ Wn0,
    const float* __restrict__ Wvi1, const float* __restrict__ Wvj1,
    const float* __restrict__ bias_h1,
    float* __restrict__ xi1, float* __restrict__ c1)
{
    extern __shared__ float dsm[];
    float* xs  = dsm;          // 2048
    float* ws1 = dsm + 2048;   // 8192
    float* ws2 = dsm + 10240;  // 8192
    const int r0 = blockIdx.x * 8;
    const int t  = threadIdx.x;
    for (int f = t; f < 8 * 256; f += 256) xs[f] = AH0[r0 * 256 + f];

    float acc[8];
#pragma unroll
    for (int r = 0; r < 8; ++r) acc[r] = 0.f;

    for (int dt = 0; dt < 8; ++dt) {
        __syncthreads();
        const float4* Wv = reinterpret_cast<const float4*>(Wn0 + dt * 32 * 256);
        float4* wsv = reinterpret_cast<float4*>(ws1);
        for (int i = t; i < 2048; i += 256) wsv[i] = __ldg(&Wv[i]);
        __syncthreads();
#pragma unroll
        for (int d4 = 0; d4 < 32; d4 += 4) {
            float wv0 = ws1[(d4 + 0) * 256 + t];
            float wv1 = ws1[(d4 + 1) * 256 + t];
            float wv2 = ws1[(d4 + 2) * 256 + t];
            float wv3 = ws1[(d4 + 3) * 256 + t];
#pragma unroll
            for (int r = 0; r < 8; ++r) {
                const float4 xv = *reinterpret_cast<const float4*>(&xs[r * 256 + dt * 32 + d4]);
                acc[r] = fmaf(xv.x, wv0, acc[r]);
                acc[r] = fmaf(xv.y, wv1, acc[r]);
                acc[r] = fmaf(xv.z, wv2, acc[r]);
                acc[r] = fmaf(xv.w, wv3, acc[r]);
            }
        }
    }
    __syncthreads();
#pragma unroll
    for (int r = 0; r < 8; ++r) xs[r * 256 + t] = fmaxf(acc[r], 0.f);   // x1 in smem

    float a1[8], a2[8];
#pragma unroll
    for (int r = 0; r < 8; ++r) { a1[r] = 0.f; a2[r] = 0.f; }

    for (int dt = 0; dt < 8; ++dt) {
        __syncthreads();
        const float4* W1v = reinterpret_cast<const float4*>(Wvi1 + dt * 32 * 256);
        const float4* W2v = reinterpret_cast<const float4*>(Wvj1 + dt * 32 * 256);
        float4* w1s = reinterpret_cast<float4*>(ws1);
        float4* w2s = reinterpret_cast<float4*>(ws2);
        for (int i = t; i < 2048; i += 256) { w1s[i] = __ldg(&W1v[i]); w2s[i] = __ldg(&W2v[i]); }
        __syncthreads();
#pragma unroll
        for (int d4 = 0; d4 < 32; d4 += 4) {
            float u0 = ws1[(d4 + 0) * 256 + t], v0 = ws2[(d4 + 0) * 256 + t];
            float u1 = ws1[(d4 + 1) * 256 + t], v1 = ws2[(d4 + 1) * 256 + t];
            float u2 = ws1[(d4 + 2) * 256 + t], v2 = ws2[(d4 + 2) * 256 + t];
            float u3 = ws1[(d4 + 3) * 256 + t], v3 = ws2[(d4 + 3) * 256 + t];
#pragma unroll
            for (int r = 0; r < 8; ++r) {
                const float4 xv = *reinterpret_cast<const float4*>(&xs[r * 256 + dt * 32 + d4]);
                a1[r] = fmaf(xv.x, u0, a1[r]); a2[r] = fmaf(xv.x, v0, a2[r]);
                a1[r] = fmaf(xv.y, u1, a1[r]); a2[r] = fmaf(xv.y, v1, a2[r]);
                a1[r] = fmaf(xv.z, u2, a1[r]); a2[r] = fmaf(xv.z, v2, a2[r]);
                a1[r] = fmaf(xv.w, u3, a1[r]); a2[r] = fmaf(xv.w, v3, a2[r]);
            }
        }
    }
#pragma unroll
    for (int r = 0; r < 8; ++r) {
        const int row = r0 + r;
        xi1[row * 256 + t] = a1[r];
        c1[row * 256 + t]  = a2[r] + __ldg(&bias_h1[(row & (PN - 1)) * 256 + t]);
    }
}

// ---------------------------------------------------------------------------
// Final: out = relu((A + B) @ W)
// ---------------------------------------------------------------------------
__global__ __launch_bounds__(256) void rowgemm8_sum_kernel(
    const float* __restrict__ A, const float* __restrict__ B,
    const float* __restrict__ W, float* __restrict__ out)
{
    __shared__ float xs[8 * 256];
    __shared__ float ws[32 * 256];
    const int r0 = blockIdx.x * 8;
    const int t  = threadIdx.x;
    for (int f = t; f < 8 * 256; f += 256) xs[f] = A[r0 * 256 + f] + B[r0 * 256 + f];

    float acc[8];
#pragma unroll
    for (int r = 0; r < 8; ++r) acc[r] = 0.f;

    for (int dt = 0; dt < 8; ++dt) {
        __syncthreads();
        const float4* Wv = reinterpret_cast<const float4*>(W + dt * 32 * 256);
        float4* wsv = reinterpret_cast<float4*>(ws);
        for (int i = t; i < 2048; i += 256) wsv[i] = __ldg(&Wv[i]);
        __syncthreads();
#pragma unroll
        for (int d4 = 0; d4 < 32; d4 += 4) {
            float wv0 = ws[(d4 + 0) * 256 + t];
            float wv1 = ws[(d4 + 1) * 256 + t];
            float wv2 = ws[(d4 + 2) * 256 + t];
            float wv3 = ws[(d4 + 3) * 256 + t];
#pragma unroll
            for (int r = 0; r < 8; ++r) {
                const float4 xv = *reinterpret_cast<const float4*>(&xs[r * 256 + dt * 32 + d4]);
                acc[r] = fmaf(xv.x, wv0, acc[r]);
                acc[r] = fmaf(xv.y, wv1, acc[r]);
                acc[r] = fmaf(xv.z, wv2, acc[r]);
                acc[r] = fmaf(xv.w, wv3, acc[r]);
            }
        }
    }
#pragma unroll
    for (int r = 0; r < 8; ++r) out[(r0 + r) * 256 + t] = fmaxf(acc[r], 0.f);
}

// ---------------------------------------------------------------------------
// Fused graph-learning kernel.
// ---------------------------------------------------------------------------
__global__ void pair_softadj_kernel(const float* __restrict__ xhat,
                                    const float* __restrict__ adj,
                                    const float* __restrict__ learn_w,
                                    const int*   __restrict__ box_num,
                                    float* __restrict__ soft_adj_out,
                                    float* __restrict__ adj2,
                                    float* __restrict__ pair_norm)
{
    const int row = blockIdx.x;
    const int b = row >> 8;
    const int i = row & 255;
    const int t = threadIdx.x;
    const int warp = t >> 5, lane = t & 31;

    __shared__ float xi_s[128];
    __shared__ float w_s[128];
    __shared__ float sval[256];
    __shared__ float red[256];
    __shared__ float wsum_s, rmax_s;

    if (t < 128) { xi_s[t] = xhat[row * 128 + t]; w_s[t] = learn_w[t]; }
    __syncthreads();
    if (t == 0) {
        float s = 0.f;
        for (int d = 0; d < 128; ++d) s += w_s[d];
        wsum_s = s;
    }
    __syncthreads();

    const int bn = box_num[b];
    const bool vi = (i < bn);
    const float wsum = wsum_s;
    const float4 xi4 = reinterpret_cast<const float4*>(xi_s)[lane];
    const float4 w4  = reinterpret_cast<const float4*>(w_s)[lane];

    for (int j = warp; j < 256; j += 8) {
        const float4 xj4 = __ldg(reinterpret_cast<const float4*>(xhat + (b * 256 + j) * 128) + lane);
        const float d0 = xi4.x - xj4.x, d1 = xi4.y - xj4.y;
        const float d2 = xi4.z - xj4.z, d3 = xi4.w - xj4.w;
        float s = fabsf(d0) * w4.x + fabsf(d1) * w4.y + fabsf(d2) * w4.z + fabsf(d3) * w4.w;
        float q = d0 * d0 + d1 * d1 + d2 * d2 + d3 * d3;
#pragma unroll
        for (int off = 16; off; off >>= 1) {
            s += __shfl_down_sync(0xffffffffu, s, off);
            q += __shfl_down_sync(0xffffffffu, q, off);
        }
        if (lane == 0) {
            const float m = (vi && (j < bn)) ? 0.f : -1.f;
            float v = s + m * wsum;
            v = (v > 0.f) ? v : 0.01f * v;
            sval[j] = v;
            pair_norm[row * 256 + j] = sqrtf(q + 1e-12f);
        }
    }
    __syncthreads();

    const float v = sval[t];
    red[t] = v;
    __syncthreads();
    for (int sft = 128; sft; sft >>= 1) {
        if (t < sft) red[t] = fmaxf(red[t], red[t + sft]);
        __syncthreads();
    }
    if (t == 0) rmax_s = red[0];
    __syncthreads();

    const float a = adj[row * 256 + t];
    const float e = expf(v - rmax_s) * a;
    red[t] = e;
    __syncthreads();
    for (int sft = 128; sft; sft >>= 1) {
        if (t < sft) red[t] += red[t + sft];
        __syncthreads();
    }
    const float sa = e / red[0] + 1e-10f;
    soft_adj_out[row * 256 + t] = sa;
    adj2[row * 256 + t] = a * sa;
}

// ---------------------------------------------------------------------------
// gl_loss two-phase reduction.
// ---------------------------------------------------------------------------
__global__ void glloss_part_kernel(const float* __restrict__ soft_adj,
                                   const float* __restrict__ pair_norm)
{
    const int blk = blockIdx.x;
    const int b = blk >> 7;
    const int t = threadIdx.x;
    const int base = b * 65536 + (blk & 127) * 512;
    float s1 = 0.f, s2 = 0.f;
#pragma unroll
    for (int u = 0; u < 2; ++u) {
        const int idx = base + u * 256 + t;
        const float s = soft_adj[idx];
        s1 += expf(s + pair_norm[idx]);
        s2 += s * s;
    }
    __shared__ float r1[256], r2[256];
    r1[t] = s1; r2[t] = s2;
    __syncthreads();
    for (int sft = 128; sft; sft >>= 1) {
        if (t < sft) { r1[t] += r1[t + sft]; r2[t] += r2[t + sft]; }
        __syncthreads();
    }
    if (t == 0) { g_part1[blk] = r1[0]; g_part2[blk] = r2[0]; }
}

__global__ void glloss_fin_kernel(const int* __restrict__ box_num, float* __restrict__ gl_out)
{
    const int b = blockIdx.x;
    const int t = threadIdx.x;
    __shared__ float r1[128], r2[128];
    r1[t] = g_part1[b * 128 + t];
    r2[t] = g_part2[b * 128 + t];
    __syncthreads();
    for (int sft = 64; sft; sft >>= 1) {
        if (t < sft) { r1[t] += r1[t + sft]; r2[t] += r2[t + sft]; }
        __syncthreads();
    }
    if (t == 0) {
        const float bnf = (float)box_num[b];
        gl_out[b] = r1[0] / (bnf * bnf) + 1e-4f * sqrtf(r2[0]);
    }
}

// ---------------------------------------------------------------------------
// Kernel A: AH0 only. H built on the fly (packed f32x2, 4-wide), never stored.
// ---------------------------------------------------------------------------
__global__ __launch_bounds__(256) void ah0_kernel(
    const float* __restrict__ xi0, const float* __restrict__ c0,
    const float* __restrict__ rel, const float* __restrict__ Wt,
    const float* __restrict__ adj2, float* __restrict__ AH0)
{
    __shared__ __align__(16) float rel_s[1536];
    __shared__ __align__(16) float wt_s[1536];
    __shared__ __align__(16) float adj_s[256];
    __shared__ __align__(16) float ahred[2048];
    __shared__ __align__(16) float xi_s[256];

    const int t = threadIdx.x;
    const int wid = t >> 5;
    const int lane = t & 31;
    const int row = blockIdx.x;
    const int b = row >> 8;

    const float* relrow = rel + (size_t)row * 256 * 6;
    for (int f = t; f < 1536; f += 256) { rel_s[f] = relrow[f]; wt_s[f] = Wt[f]; }
    adj_s[t] = adj2[row * 256 + t];
    xi_s[t]  = xi0[row * 256 + t];
    __syncthreads();

    const ulonglong2* c04 = reinterpret_cast<const ulonglong2*>(c0 + b * 65536);

#pragma unroll
    for (int kq2 = 0; kq2 < 2; ++kq2) {
        const int q = lane + 32 * kq2;     // k-quad index 0..63, covers k = 4q..4q+3
        const ulonglong2 xiv = *reinterpret_cast<const ulonglong2*>(&xi_s[4 * q]);
        ull_t wt2[6][2];
#pragma unroll
        for (int c = 0; c < 6; ++c) {
            const ulonglong2 w = *reinterpret_cast<const ulonglong2*>(&wt_s[c * 256 + 4 * q]);
            wt2[c][0] = w.x; wt2[c][1] = w.y;
        }

        float ah0 = 0.f, ah1 = 0.f, ah2 = 0.f, ah3 = 0.f;
#pragma unroll 2
        for (int s = 0; s < 32; ++s) {
            const int j = wid * 32 + s;
            const float* rj = rel_s + j * 6;
            ull_t rp[6];
#pragma unroll
            for (int c = 0; c < 6; ++c) rp[c] = pk2(rj[c], rj[c]);
            const ulonglong2 cv = __ldg(&c04[j * 64 + q]);
            ull_t t0 = add2(xiv.x, cv.x);
            ull_t t1 = add2(xiv.y, cv.y);
#pragma unroll
            for (int c = 0; c < 6; ++c) {
                t0 = fma2(rp[c], wt2[c][0], t0);
                t1 = fma2(rp[c], wt2[c][1], t1);
            }
            float h0, h1, h2, h3;
            upk2(t0, h0, h1);
            upk2(t1, h2, h3);
            const float aw = adj_s[j];
            ah0 = fmaf(aw, fmaxf(h0, 0.f), ah0);
            ah1 = fmaf(aw, fmaxf(h1, 0.f), ah1);
            ah2 = fmaf(aw, fmaxf(h2, 0.f), ah2);
            ah3 = fmaf(aw, fmaxf(h3, 0.f), ah3);
        }
        float4 o; o.x = ah0; o.y = ah1; o.z = ah2; o.w = ah3;
        *reinterpret_cast<float4*>(&ahred[wid * 256 + 4 * q]) = o;
    }
    __syncthreads();

    float s = 0.f;
#pragma unroll
    for (int g = 0; g < 8; ++g) s += ahred[g * 256 + t];
    AH0[row * 256 + t] = s;
}

// ---------------------------------------------------------------------------
// Kernel C: fused layer0 GEMM + layer1 reduction, one jh half PER BLOCK.
// Grid (1024, 2). H build uses packed f32x2 + 4-wide loads/stores.
// ---------------------------------------------------------------------------
// SMEM byte offsets
#define SM_A       0         // 128 j x 256 k fp16, 512B rows, xor-swizzled = 65536
#define SM_B1      65536     // 32768
#define SM_REL     98304     // 3072
#define SM_ADJ     101376    // 1024
#define SM_AHRED   102400    // 8192 (8 warps x 256 n)
#define SM_XI      110592    // 1024
#define SM_XI1     111616    // 1024
#define SM_TOTAL   112640

__global__ void __launch_bounds__(256, 2) layer01_mma_kernel(
    const float* __restrict__ xi0, const float* __restrict__ c0,
    const float* __restrict__ rel, const float* __restrict__ Wt,
    const float* __restrict__ adj2,
    const float* __restrict__ xi1, const float* __restrict__ c1,
    float* __restrict__ AH1a, float* __restrict__ AH1b)
{
    extern __shared__ char sm[];
    const uint32_t sb = smem_to_u32(sm);
    float* rel_s  = reinterpret_cast<float*>(sm + SM_REL);
    float* adj_s  = reinterpret_cast<float*>(sm + SM_ADJ);
    float* ah1red = reinterpret_cast<float*>(sm + SM_AHRED);
    float* xi_s   = reinterpret_cast<float*>(sm + SM_XI);
    float* xi1_s  = reinterpret_cast<float*>(sm + SM_XI1);

    const int t = threadIdx.x;
    const int wid = t >> 5;
    const int lane = t & 31;
    const int row = blockIdx.x;      // b*256 + i
    const int jh  = blockIdx.y;      // 0 or 1
    const int b = row >> 8;

    adj_s[t]  = adj2[row * 256 + t];
    xi_s[t]   = xi0[row * 256 + t];
    xi1_s[t]  = xi1[row * 256 + t];
    const float* relrow = rel + ((size_t)row * 256 + jh * 128) * 6;
    for (int f = t; f < 768; f += 256) rel_s[f] = relrow[f];
    __syncthreads();

    const float* c0b = c0 + b * 65536;
    const float* c1b = c1 + b * 65536;
    const ulonglong2* c04 = reinterpret_cast<const ulonglong2*>(c0b);

    // --- per-lane ldmatrix address components ---
    const int jrl = wid * 16 + (lane & 15);
    const uint32_t acolByte = (uint32_t)((lane >> 4) * 16);
    const uint32_t jmask = (uint32_t)((jrl & 7) << 4);
    const uint32_t aRowByte = (uint32_t)jrl * 512u;
    const int nrow_l = (lane & 7) | ((lane & 16) >> 1);
    const uint32_t kbB = (uint32_t)(((lane >> 3) & 1) * 16);
    const uint32_t nmask = (uint32_t)((nrow_l & 7) << 4);
    const uint32_t bRowByte = (uint32_t)nrow_l * 256u;

    const int r  = lane >> 2;    // 0..7
    const int cq = lane & 3;     // 0..3

    // ---- build H half (128 j x 256 k) as fp16; packed math, 4 k per iter ----
#pragma unroll
    for (int kq2 = 0; kq2 < 2; ++kq2) {
        const int q = lane + 32 * kq2;     // k-quad 0..63
        const ulonglong2 xiv = *reinterpret_cast<const ulonglong2*>(&xi_s[4 * q]);
        ull_t wt2[6][2];
#pragma unroll
        for (int c = 0; c < 6; ++c) {
            const float2 wa = __ldg(reinterpret_cast<const float2*>(&Wt[c * 256 + 4 * q]));
            const float2 wb = __ldg(reinterpret_cast<const float2*>(&Wt[c * 256 + 4 * q + 2]));
            wt2[c][0] = pk2(wa.x, wa.y);
            wt2[c][1] = pk2(wb.x, wb.y);
        }

#pragma unroll 2
        for (int s = 0; s < 16; ++s) {
            const int jl = wid * 16 + s;
            const int j = jh * 128 + jl;
            const float* rj = rel_s + jl * 6;
            ull_t rp[6];
#pragma unroll
            for (int c = 0; c < 6; ++c) rp[c] = pk2(rj[c], rj[c]);
            const ulonglong2 cv = __ldg(&c04[j * 64 + q]);
            ull_t t0 = add2(xiv.x, cv.x);
            ull_t t1 = add2(xiv.y, cv.y);
#pragma unroll
            for (int c = 0; c < 6; ++c) {
                t0 = fma2(rp[c], wt2[c][0], t0);
                t1 = fma2(rp[c], wt2[c][1], t1);
            }
            float h0, h1, h2, h3;
            upk2(t0, h0, h1);
            upk2(t1, h2, h3);
            __half2 ha = __floats2half2_rn(fmaxf(h0, 0.f), fmaxf(h1, 0.f));
            __half2 hb = __floats2half2_rn(fmaxf(h2, 0.f), fmaxf(h3, 0.f));
            uint2 hv;
            hv.x = *reinterpret_cast<uint32_t*>(&ha);
            hv.y = *reinterpret_cast<uint32_t*>(&hb);
            const uint32_t off = (uint32_t)jl * 512u + ((uint32_t)(8 * q) ^ ((uint32_t)(jl & 7) << 4));
            *reinterpret_cast<uint2*>(sm + SM_A + off) = hv;
        }
    }

#pragma unroll 1
    for (int nc = 0; nc < 2; ++nc) {
        float C[16][4];
#pragma unroll
        for (int nt = 0; nt < 16; ++nt)
#pragma unroll
            for (int u = 0; u < 4; ++u) C[nt][u] = 0.f;

#pragma unroll 1
        for (int kh = 0; kh < 2; ++kh) {
            __syncthreads();   // prior B consumers done (first iter: A build visibility)
            // ---- stage B slice (verbatim pre-swizzled copy) ----
            {
                const uint4* s1 = reinterpret_cast<const uint4*>(
                    reinterpret_cast<const char*>(g_wimg1) + kh * 65536 + nc * 32768);
                uint4* d1 = reinterpret_cast<uint4*>(sm + SM_B1);
                for (int i = t; i < 2048; i += 256) d1[i] = __ldg(&s1[i]);
            }
            __syncthreads();

            // ---- HMMA: C += A * B ----
#pragma unroll 1
            for (int ks = 0; ks < 8; ++ks) {
                const uint32_t aoff = ((uint32_t)((kh * 8 + ks) * 32) + acolByte) ^ jmask;
                const uint32_t boff = ((uint32_t)(ks * 32) + kbB) ^ nmask;
                uint32_t Ah[4];
                ldsm4(Ah, sb + SM_A + aRowByte + aoff);

                uint32_t bb[4];
#pragma unroll
                for (int p = 0; p < 8; ++p) {
                    ldsm4(bb, sb + SM_B1 + (uint32_t)p * 4096 + bRowByte + boff);
                    mma_f16(C[2 * p],     Ah, bb[0], bb[1]);
                    mma_f16(C[2 * p + 1], Ah, bb[2], bb[3]);
                }
            }
        }

        // ---- fused layer1 epilogue: consume alpha1 = relu(C) in registers ----
        {
            float acc0[16], acc1[16];
#pragma unroll
            for (int nt = 0; nt < 16; ++nt) { acc0[nt] = 0.f; acc1[nt] = 0.f; }

            const int j1 = jh * 128 + wid * 16 + r;
            const int j2 = j1 + 8;
            const float aw1 = adj_s[j1];
            const float aw2 = adj_s[j2];
#pragma unroll
            for (int nt = 0; nt < 16; ++nt) {
                const int n0 = nc * 128 + nt * 8 + 2 * cq;
                const float2 cA = __ldg(reinterpret_cast<const float2*>(c1b + j1 * 256 + n0));
                const float2 cB = __ldg(reinterpret_cast<const float2*>(c1b + j2 * 256 + n0));
                const float x0 = xi1_s[n0];
                const float x1v = xi1_s[n0 + 1];
                const float a0 = fmaxf(C[nt][0], 0.f);
                const float a1 = fmaxf(C[nt][1], 0.f);
                const float a2 = fmaxf(C[nt][2], 0.f);
                const float a3 = fmaxf(C[nt][3], 0.f);
                acc0[nt] = fmaf(aw1, fmaxf(x0 + cA.x + a0, 0.f), acc0[nt]);
                acc1[nt] = fmaf(aw1, fmaxf(x1v + cA.y + a1, 0.f), acc1[nt]);
                acc0[nt] = fmaf(aw2, fmaxf(x0 + cB.x + a2, 0.f), acc0[nt]);
                acc1[nt] = fmaf(aw2, fmaxf(x1v + cB.y + a3, 0.f), acc1[nt]);
            }

#pragma unroll
            for (int nt = 0; nt < 16; ++nt) {
                float v0 = acc0[nt], v1 = acc1[nt];
#pragma unroll
                for (int off = 4; off <= 16; off <<= 1) {
                    v0 += __shfl_xor_sync(0xffffffffu, v0, off);
                    v1 += __shfl_xor_sync(0xffffffffu, v1, off);
                }
                if (r == 0) {
                    const int n0 = nc * 128 + nt * 8 + 2 * cq;
                    ah1red[wid * 256 + n0]     = v0;
                    ah1red[wid * 256 + n0 + 1] = v1;
                }
            }
        }
    }
    __syncthreads();

    // cross-warp reduce -> AH1part[jh]
    {
        float s = 0.f;
#pragma unroll
        for (int g = 0; g < 8; ++g) s += ah1red[g * 256 + t];
        float* dst = jh ? AH1b : AH1a;
        dst[row * 256 + t] = s;
    }
}

// ---------------------------------------------------------------------------
extern "C" void kernel_launch(void* const* d_in, const int* in_sizes, int n_in,
                              void* d_out, int out_size)
{
    (void)in_sizes; (void)n_in; (void)out_size;

    const float* x        = (const float*)d_in[0];
    const float* rel      = (const float*)d_in[1];
    const float* adj      = (const float*)d_in[2];
    const int*   bnum     = (const int*)  d_in[3];
    const float* Wt       = (const float*)d_in[4];
    const float* b_alpha  = (const float*)d_in[5];
    const float* W_proj   = (const float*)d_in[6];
    const float* b_proj   = (const float*)d_in[7];
    const float* learn_w  = (const float*)d_in[8];
    const float* w_alpha0 = (const float*)d_in[9];
    const float* w_vi0    = (const float*)d_in[10];
    const float* w_vj0    = (const float*)d_in[11];
    const float* bias_h0  = (const float*)d_in[12];
    const float* w_node0  = (const float*)d_in[13];
    /* d_in[14] = l1_w_alpha: unused (alpha2 discarded) */
    const float* w_vi1    = (const float*)d_in[15];
    const float* w_vj1    = (const float*)d_in[16];
    const float* bias_h1  = (const float*)d_in[17];
    const float* w_node1  = (const float*)d_in[18];

    float* out      = (float*)d_out;
    float* out_x2   = out;
    float* out_sadj = out + 262144;
    float* out_gl   = out + 524288;

    float *xhat, *pnorm, *adj2, *xi0, *c0, *AH0, *xi1, *c1, *AH1a, *AH1b;
    cudaGetSymbolAddress((void**)&xhat,  g_xhat);
    cudaGetSymbolAddress((void**)&pnorm, g_pnorm);
    cudaGetSymbolAddress((void**)&adj2,  g_adj2);
    cudaGetSymbolAddress((void**)&xi0,   g_xi0);
    cudaGetSymbolAddress((void**)&c0,    g_c0);
    cudaGetSymbolAddress((void**)&AH0,   g_AH0);
    cudaGetSymbolAddress((void**)&xi1,   g_xi1);
    cudaGetSymbolAddress((void**)&c1,    g_c1);
    cudaGetSymbolAddress((void**)&AH1a,  g_AH1a);
    cudaGetSymbolAddress((void**)&AH1b,  g_AH1b);

    const int DUAL_SMEM = 18432 * 4;

    // Launch order chosen so layer01_mma is the 6th launch (ncu -s 5 -c 1).
    // 1: dual GEMM + fused w_alpha image prep
    cudaFuncSetAttribute(rowgemm8_dual_prep_kernel, cudaFuncAttributeMaxDynamicSharedMemorySize, DUAL_SMEM);
    rowgemm8_dual_prep_kernel<<<128, 256, DUAL_SMEM>>>(x, w_vi0, w_vj0, bias_h0, b_alpha, w_alpha0, xi0, c0);

    // 2-3: graph learning front
    rowgemm_kernel<<<256, 128>>>(x, W_proj, b_proj, xhat);
    pair_softadj_kernel<<<1024, 256>>>(xhat, adj, learn_w, bnum, out_sadj, adj2, pnorm);

    // 4: AH0 ; 5: chain ; 6: fused layer0 GEMM + layer1 reduction
    ah0_kernel<<<1024, 256>>>(xi0, c0, rel, Wt, adj2, AH0);
    cudaFuncSetAttribute(chain_kernel, cudaFuncAttributeMaxDynamicSharedMemorySize, DUAL_SMEM);
    chain_kernel<<<128, 256, DUAL_SMEM>>>(AH0, w_node0, w_vi1, w_vj1, bias_h1, xi1, c1);

    cudaFuncSetAttribute(layer01_mma_kernel, cudaFuncAttributeMaxDynamicSharedMemorySize, SM_TOTAL);
    layer01_mma_kernel<<<dim3(1024, 2), 256, SM_TOTAL>>>(xi0, c0, rel, Wt, adj2, xi1, c1, AH1a, AH1b);

    // 7-8: gl_loss (no downstream consumers) ; 9: final GEMM
    glloss_part_kernel<<<512, 256>>>(out_sadj, pnorm);
    glloss_fin_kernel<<<4, 128>>>(bnum, out_gl);
    rowgemm8_sum_kernel<<<128, 256>>>(AH1a, AH1b, w_node1, out_x2);
}

// round 12
// speedup vs baseline: 3.7614x; 1.0278x over previous
#include <cuda_runtime.h>
#include <cuda_fp16.h>
#include <cstdint>
#include <cstddef>

// Problem constants
#define PB 4
#define PN 256
#define PD 256
#define PL 128
#define POUT 256

// ============================ helpers ============================
__device__ __forceinline__ uint32_t smem_to_u32(const void* smem_ptr) {
    uint32_t addr;
    asm("{ .reg .u64 tmp; cvta.to.shared.u64 tmp, %1; cvt.u32.u64 %0, tmp; }"
        : "=r"(addr) : "l"(smem_ptr));
    return addr;
}

__device__ __forceinline__ void ldsm4(uint32_t* r, uint32_t addr) {
    asm volatile("ldmatrix.sync.aligned.m8n8.x4.shared.b16 {%0,%1,%2,%3}, [%4];"
        : "=r"(r[0]), "=r"(r[1]), "=r"(r[2]), "=r"(r[3]) : "r"(addr));
}

__device__ __forceinline__ void mma_f16(float* c, const uint32_t* a, uint32_t b0, uint32_t b1) {
    asm volatile(
        "mma.sync.aligned.m16n8k16.row.col.f32.f16.f16.f32 "
        "{%0,%1,%2,%3}, {%4,%5,%6,%7}, {%8,%9}, {%0,%1,%2,%3};"
        : "+f"(c[0]), "+f"(c[1]), "+f"(c[2]), "+f"(c[3])
        : "r"(a[0]), "r"(a[1]), "r"(a[2]), "r"(a[3]), "r"(b0), "r"(b1));
}

// ---- packed f32x2 ops (sm_100+ baseline PTX) ----
typedef unsigned long long ull_t;
__device__ __forceinline__ ull_t pk2(float lo, float hi) {
    ull_t r;
    asm("mov.b64 %0, {%1, %2};" : "=l"(r)
        : "r"(__float_as_uint(lo)), "r"(__float_as_uint(hi)));
    return r;
}
__device__ __forceinline__ void upk2(ull_t v, float& lo, float& hi) {
    uint32_t a, b;
    asm("mov.b64 {%0, %1}, %2;" : "=r"(a), "=r"(b) : "l"(v));
    lo = __uint_as_float(a); hi = __uint_as_float(b);
}
__device__ __forceinline__ ull_t fma2(ull_t a, ull_t b, ull_t c) {
    ull_t d;
    asm("fma.rn.f32x2 %0, %1, %2, %3;" : "=l"(d) : "l"(a), "l"(b), "l"(c));
    return d;
}
__device__ __forceinline__ ull_t add2(ull_t a, ull_t b) {
    ull_t d;
    asm("add.rn.f32x2 %0, %1, %2;" : "=l"(d) : "l"(a), "l"(b));
    return d;
}

// ---------------- scratch (device globals; no runtime allocation) ----------------
__device__ float g_xhat [PB*PN*PL];
__device__ float g_pnorm[PB*PN*PN];
__device__ float g_adj2 [PB*PN*PN];
__device__ float g_xi0  [PB*PN*POUT];
__device__ float g_c0   [PB*PN*POUT];
__device__ float g_AH0  [PB*PN*POUT];
__device__ float g_xi1  [PB*PN*POUT];
__device__ float g_c1   [PB*PN*POUT];
__device__ float g_AH1a [PB*PN*POUT];
__device__ float g_AH1b [PB*PN*POUT];
__device__ float g_part1[512];
__device__ float g_part2[512];
// Pre-converted w_alpha image: [kh:2][n:256][k:128] fp16, 256B rows,
// XOR-swizzled by (n&7)<<4 -> ldmatrix conflict-free, verbatim staging.
// kh stride = 65536 BYTES.
__device__ __half g_wimg1[2*256*128];

// ---------------------------------------------------------------------------
// Simple row GEMM for xhat (K=128)
// ---------------------------------------------------------------------------
__global__ void rowgemm_kernel(const float* __restrict__ X, const float* __restrict__ W,
                               const float* __restrict__ bias_k, float* __restrict__ out)
{
    __shared__ float xs[4 * 256];
    const int r0 = blockIdx.x * 4;
    const int t  = threadIdx.x;
    for (int f = t; f < 4 * 256; f += 128) xs[f] = X[r0 * 256 + f];
    __syncthreads();

    float acc[4] = {0.f, 0.f, 0.f, 0.f};
#pragma unroll 8
    for (int d = 0; d < 256; ++d) {
        const float wv = __ldg(&W[d * 128 + t]);
#pragma unroll
        for (int r = 0; r < 4; ++r) acc[r] = fmaf(xs[r * 256 + d], wv, acc[r]);
    }
    const float bk = __ldg(&bias_k[t]);
#pragma unroll
    for (int r = 0; r < 4; ++r) out[(r0 + r) * 128 + t] = acc[r] + bk;
}

// ---------------------------------------------------------------------------
// Dual row GEMM (layer-0 inputs) + FUSED w_alpha image prep.
// ---------------------------------------------------------------------------
__global__ __launch_bounds__(256) void rowgemm8_dual_prep_kernel(
    const float* __restrict__ X, const float* __restrict__ W1, const float* __restrict__ W2,
    const float* __restrict__ bias_nk, const float* __restrict__ bias_k,
    const float* __restrict__ w_alpha,
    float* __restrict__ out1, float* __restrict__ out2)
{
    extern __shared__ float dsm[];
    float* xs  = dsm;          // 2048
    float* ws1 = dsm + 2048;   // 8192
    float* ws2 = dsm + 10240;  // 8192
    const int r0 = blockIdx.x * 8;
    const int t  = threadIdx.x;

    // ---- fused prep: convert w_alpha (k=d:256, n:256) into fp16 transposed image ----
    {
        const int base = (blockIdx.x * 256 + t) * 2;
#pragma unroll
        for (int u = 0; u < 2; ++u) {
            const int e = base + u;
            const int k = e >> 8;
            const int n = e & 255;
            const __half hi = __float2half_rn(__ldg(&w_alpha[k * 256 + n]));
            const int kh = k >> 7, kk = k & 127;
            const uint32_t off = kh * 65536u + n * 256u + (uint32_t)((kk * 2) ^ ((n & 7) << 4));
            *reinterpret_cast<__half*>(reinterpret_cast<char*>(g_wimg1) + off) = hi;
        }
    }

    for (int f = t; f < 8 * 256; f += 256) xs[f] = X[r0 * 256 + f];

    float a1[8], a2[8];
#pragma unroll
    for (int r = 0; r < 8; ++r) { a1[r] = 0.f; a2[r] = 0.f; }

    for (int dt = 0; dt < 8; ++dt) {
        __syncthreads();
        const float4* W1v = reinterpret_cast<const float4*>(W1 + dt * 32 * 256);
        const float4* W2v = reinterpret_cast<const float4*>(W2 + dt * 32 * 256);
        float4* w1s = reinterpret_cast<float4*>(ws1);
        float4* w2s = reinterpret_cast<float4*>(ws2);
        for (int i = t; i < 2048; i += 256) { w1s[i] = __ldg(&W1v[i]); w2s[i] = __ldg(&W2v[i]); }
        __syncthreads();
#pragma unroll
        for (int d4 = 0; d4 < 32; d4 += 4) {
            float u0 = ws1[(d4 + 0) * 256 + t], v0 = ws2[(d4 + 0) * 256 + t];
            float u1 = ws1[(d4 + 1) * 256 + t], v1 = ws2[(d4 + 1) * 256 + t];
            float u2 = ws1[(d4 + 2) * 256 + t], v2 = ws2[(d4 + 2) * 256 + t];
            float u3 = ws1[(d4 + 3) * 256 + t], v3 = ws2[(d4 + 3) * 256 + t];
#pragma unroll
            for (int r = 0; r < 8; ++r) {
                const float4 xv = *reinterpret_cast<const float4*>(&xs[r * 256 + dt * 32 + d4]);
                a1[r] = fmaf(xv.x, u0, a1[r]); a2[r] = fmaf(xv.x, v0, a2[r]);
                a1[r] = fmaf(xv.y, u1, a1[r]); a2[r] = fmaf(xv.y, v1, a2[r]);
                a1[r] = fmaf(xv.z, u2, a1[r]); a2[r] = fmaf(xv.z, v2, a2[r]);
                a1[r] = fmaf(xv.w, u3, a1[r]); a2[r] = fmaf(xv.w, v3, a2[r]);
            }
        }
    }
    const float bk = bias_k ? __ldg(&bias_k[t]) : 0.f;
#pragma unroll
    for (int r = 0; r < 8; ++r) {
        const int row = r0 + r;
        out1[row * 256 + t] = a1[r];
        out2[row * 256 + t] = a2[r] + bk + __ldg(&bias_nk[(row & (PN - 1)) * 256 + t]);
    }
}

// ---------------------------------------------------------------------------
// Fused chain: x1 = relu(AH0 @ Wn0); xi1 = x1 @ Wvi1; c1 = x1 @ Wvj1 + bias_h1.
// ---------------------------------------------------------------------------
__global__ __launch_bounds__(256) void chain_kernel(
    const float* __restrict__ AH0, const float* __restrict__ Wn0,
    const float* __restrict__ Wvi1, const float* __restrict__ Wvj1,
    const float* __restrict__ bias_h1,
    float* __restrict__ xi1, float* __restrict__ c1)
{
    extern __shared__ float dsm[];
    float* xs  = dsm;          // 2048
    float* ws1 = dsm + 2048;   // 8192
    float* ws2 = dsm + 10240;  // 8192
    const int r0 = blockIdx.x * 8;
    const int t  = threadIdx.x;
    for (int f = t; f < 8 * 256; f += 256) xs[f] = AH0[r0 * 256 + f];

    float acc[8];
#pragma unroll
    for (int r = 0; r < 8; ++r) acc[r] = 0.f;

    for (int dt = 0; dt < 8; ++dt) {
        __syncthreads();
        const float4* Wv = reinterpret_cast<const float4*>(Wn0 + dt * 32 * 256);
        float4* wsv = reinterpret_cast<float4*>(ws1);
        for (int i = t; i < 2048; i += 256) wsv[i] = __ldg(&Wv[i]);
        __syncthreads();
#pragma unroll
        for (int d4 = 0; d4 < 32; d4 += 4) {
            float wv0 = ws1[(d4 + 0) * 256 + t];
            float wv1 = ws1[(d4 + 1) * 256 + t];
            float wv2 = ws1[(d4 + 2) * 256 + t];
            float wv3 = ws1[(d4 + 3) * 256 + t];
#pragma unroll
            for (int r = 0; r < 8; ++r) {
                const float4 xv = *reinterpret_cast<const float4*>(&xs[r * 256 + dt * 32 + d4]);
                acc[r] = fmaf(xv.x, wv0, acc[r]);
                acc[r] = fmaf(xv.y, wv1, acc[r]);
                acc[r] = fmaf(xv.z, wv2, acc[r]);
                acc[r] = fmaf(xv.w, wv3, acc[r]);
            }
        }
    }
    __syncthreads();
#pragma unroll
    for (int r = 0; r < 8; ++r) xs[r * 256 + t] = fmaxf(acc[r], 0.f);   // x1 in smem

    float a1[8], a2[8];
#pragma unroll
    for (int r = 0; r < 8; ++r) { a1[r] = 0.f; a2[r] = 0.f; }

    for (int dt = 0; dt < 8; ++dt) {
        __syncthreads();
        const float4* W1v = reinterpret_cast<const float4*>(Wvi1 + dt * 32 * 256);
        const float4* W2v = reinterpret_cast<const float4*>(Wvj1 + dt * 32 * 256);
        float4* w1s = reinterpret_cast<float4*>(ws1);
        float4* w2s = reinterpret_cast<float4*>(ws2);
        for (int i = t; i < 2048; i += 256) { w1s[i] = __ldg(&W1v[i]); w2s[i] = __ldg(&W2v[i]); }
        __syncthreads();
#pragma unroll
        for (int d4 = 0; d4 < 32; d4 += 4) {
            float u0 = ws1[(d4 + 0) * 256 + t], v0 = ws2[(d4 + 0) * 256 + t];
            float u1 = ws1[(d4 + 1) * 256 + t], v1 = ws2[(d4 + 1) * 256 + t];
            float u2 = ws1[(d4 + 2) * 256 + t], v2 = ws2[(d4 + 2) * 256 + t];
            float u3 = ws1[(d4 + 3) * 256 + t], v3 = ws2[(d4 + 3) * 256 + t];
#pragma unroll
            for (int r = 0; r < 8; ++r) {
                const float4 xv = *reinterpret_cast<const float4*>(&xs[r * 256 + dt * 32 + d4]);
                a1[r] = fmaf(xv.x, u0, a1[r]); a2[r] = fmaf(xv.x, v0, a2[r]);
                a1[r] = fmaf(xv.y, u1, a1[r]); a2[r] = fmaf(xv.y, v1, a2[r]);
                a1[r] = fmaf(xv.z, u2, a1[r]); a2[r] = fmaf(xv.z, v2, a2[r]);
                a1[r] = fmaf(xv.w, u3, a1[r]); a2[r] = fmaf(xv.w, v3, a2[r]);
            }
        }
    }
#pragma unroll
    for (int r = 0; r < 8; ++r) {
        const int row = r0 + r;
        xi1[row * 256 + t] = a1[r];
        c1[row * 256 + t]  = a2[r] + __ldg(&bias_h1[(row & (PN - 1)) * 256 + t]);
    }
}

// ---------------------------------------------------------------------------
// Final: out = relu((A + B) @ W)
// ---------------------------------------------------------------------------
__global__ __launch_bounds__(256) void rowgemm8_sum_kernel(
    const float* __restrict__ A, const float* __restrict__ B,
    const float* __restrict__ W, float* __restrict__ out)
{
    __shared__ float xs[8 * 256];
    __shared__ float ws[32 * 256];
    const int r0 = blockIdx.x * 8;
    const int t  = threadIdx.x;
    for (int f = t; f < 8 * 256; f += 256) xs[f] = A[r0 * 256 + f] + B[r0 * 256 + f];

    float acc[8];
#pragma unroll
    for (int r = 0; r < 8; ++r) acc[r] = 0.f;

    for (int dt = 0; dt < 8; ++dt) {
        __syncthreads();
        const float4* Wv = reinterpret_cast<const float4*>(W + dt * 32 * 256);
        float4* wsv = reinterpret_cast<float4*>(ws);
        for (int i = t; i < 2048; i += 256) wsv[i] = __ldg(&Wv[i]);
        __syncthreads();
#pragma unroll
        for (int d4 = 0; d4 < 32; d4 += 4) {
            float wv0 = ws[(d4 + 0) * 256 + t];
            float wv1 = ws[(d4 + 1) * 256 + t];
            float wv2 = ws[(d4 + 2) * 256 + t];
            float wv3 = ws[(d4 + 3) * 256 + t];
#pragma unroll
            for (int r = 0; r < 8; ++r) {
                const float4 xv = *reinterpret_cast<const float4*>(&xs[r * 256 + dt * 32 + d4]);
                acc[r] = fmaf(xv.x, wv0, acc[r]);
                acc[r] = fmaf(xv.y, wv1, acc[r]);
                acc[r] = fmaf(xv.z, wv2, acc[r]);
                acc[r] = fmaf(xv.w, wv3, acc[r]);
            }
        }
    }
#pragma unroll
    for (int r = 0; r < 8; ++r) out[(r0 + r) * 256 + t] = fmaxf(acc[r], 0.f);
}

// ---------------------------------------------------------------------------
// Fused graph-learning kernel.
// ---------------------------------------------------------------------------
__global__ void pair_softadj_kernel(const float* __restrict__ xhat,
                                    const float* __restrict__ adj,
                                    const float* __restrict__ learn_w,
                                    const int*   __restrict__ box_num,
                                    float* __restrict__ soft_adj_out,
                                    float* __restrict__ adj2,
                                    float* __restrict__ pair_norm)
{
    const int row = blockIdx.x;
    const int b = row >> 8;
    const int i = row & 255;
    const int t = threadIdx.x;
    const int warp = t >> 5, lane = t & 31;

    __shared__ float xi_s[128];
    __shared__ float w_s[128];
    __shared__ float sval[256];
    __shared__ float red[256];
    __shared__ float wsum_s, rmax_s;

    if (t < 128) { xi_s[t] = xhat[row * 128 + t]; w_s[t] = learn_w[t]; }
    __syncthreads();
    if (t == 0) {
        float s = 0.f;
        for (int d = 0; d < 128; ++d) s += w_s[d];
        wsum_s = s;
    }
    __syncthreads();

    const int bn = box_num[b];
    const bool vi = (i < bn);
    const float wsum = wsum_s;
    const float4 xi4 = reinterpret_cast<const float4*>(xi_s)[lane];
    const float4 w4  = reinterpret_cast<const float4*>(w_s)[lane];

    for (int j = warp; j < 256; j += 8) {
        const float4 xj4 = __ldg(reinterpret_cast<const float4*>(xhat + (b * 256 + j) * 128) + lane);
        const float d0 = xi4.x - xj4.x, d1 = xi4.y - xj4.y;
        const float d2 = xi4.z - xj4.z, d3 = xi4.w - xj4.w;
        float s = fabsf(d0) * w4.x + fabsf(d1) * w4.y + fabsf(d2) * w4.z + fabsf(d3) * w4.w;
        float q = d0 * d0 + d1 * d1 + d2 * d2 + d3 * d3;
#pragma unroll
        for (int off = 16; off; off >>= 1) {
            s += __shfl_down_sync(0xffffffffu, s, off);
            q += __shfl_down_sync(0xffffffffu, q, off);
        }
        if (lane == 0) {
            const float m = (vi && (j < bn)) ? 0.f : -1.f;
            float v = s + m * wsum;
            v = (v > 0.f) ? v : 0.01f * v;
            sval[j] = v;
            pair_norm[row * 256 + j] = sqrtf(q + 1e-12f);
        }
    }
    __syncthreads();

    const float v = sval[t];
    red[t] = v;
    __syncthreads();
    for (int sft = 128; sft; sft >>= 1) {
        if (t < sft) red[t] = fmaxf(red[t], red[t + sft]);
        __syncthreads();
    }
    if (t == 0) rmax_s = red[0];
    __syncthreads();

    const float a = adj[row * 256 + t];
    const float e = expf(v - rmax_s) * a;
    red[t] = e;
    __syncthreads();
    for (int sft = 128; sft; sft >>= 1) {
        if (t < sft) red[t] += red[t + sft];
        __syncthreads();
    }
    const float sa = e / red[0] + 1e-10f;
    soft_adj_out[row * 256 + t] = sa;
    adj2[row * 256 + t] = a * sa;
}

// ---------------------------------------------------------------------------
// gl_loss two-phase reduction.
// ---------------------------------------------------------------------------
__global__ void glloss_part_kernel(const float* __restrict__ soft_adj,
                                   const float* __restrict__ pair_norm)
{
    const int blk = blockIdx.x;
    const int b = blk >> 7;
    const int t = threadIdx.x;
    const int base = b * 65536 + (blk & 127) * 512;
    float s1 = 0.f, s2 = 0.f;
#pragma unroll
    for (int u = 0; u < 2; ++u) {
        const int idx = base + u * 256 + t;
        const float s = soft_adj[idx];
        s1 += expf(s + pair_norm[idx]);
        s2 += s * s;
    }
    __shared__ float r1[256], r2[256];
    r1[t] = s1; r2[t] = s2;
    __syncthreads();
    for (int sft = 128; sft; sft >>= 1) {
        if (t < sft) { r1[t] += r1[t + sft]; r2[t] += r2[t + sft]; }
        __syncthreads();
    }
    if (t == 0) { g_part1[blk] = r1[0]; g_part2[blk] = r2[0]; }
}

__global__ void glloss_fin_kernel(const int* __restrict__ box_num, float* __restrict__ gl_out)
{
    const int b = blockIdx.x;
    const int t = threadIdx.x;
    __shared__ float r1[128], r2[128];
    r1[t] = g_part1[b * 128 + t];
    r2[t] = g_part2[b * 128 + t];
    __syncthreads();
    for (int sft = 64; sft; sft >>= 1) {
        if (t < sft) { r1[t] += r1[t + sft]; r2[t] += r2[t + sft]; }
        __syncthreads();
    }
    if (t == 0) {
        const float bnf = (float)box_num[b];
        gl_out[b] = r1[0] / (bnf * bnf) + 1e-4f * sqrtf(r2[0]);
    }
}

// ---------------------------------------------------------------------------
// Kernel A: AH0 only. H on the fly; c0 loads front-batched 4x for MLP.
// ---------------------------------------------------------------------------
__global__ __launch_bounds__(256) void ah0_kernel(
    const float* __restrict__ xi0, const float* __restrict__ c0,
    const float* __restrict__ rel, const float* __restrict__ Wt,
    const float* __restrict__ adj2, float* __restrict__ AH0)
{
    __shared__ __align__(16) float rel_s[1536];
    __shared__ __align__(16) float wt_s[1536];
    __shared__ __align__(16) float adj_s[256];
    __shared__ __align__(16) float ahred[2048];
    __shared__ __align__(16) float xi_s[256];

    const int t = threadIdx.x;
    const int wid = t >> 5;
    const int lane = t & 31;
    const int row = blockIdx.x;
    const int b = row >> 8;

    const float* relrow = rel + (size_t)row * 256 * 6;
    for (int f = t; f < 1536; f += 256) { rel_s[f] = relrow[f]; wt_s[f] = Wt[f]; }
    adj_s[t] = adj2[row * 256 + t];
    xi_s[t]  = xi0[row * 256 + t];
    __syncthreads();

    const ulonglong2* c04 = reinterpret_cast<const ulonglong2*>(c0 + b * 65536);

#pragma unroll
    for (int kq2 = 0; kq2 < 2; ++kq2) {
        const int q = lane + 32 * kq2;     // k-quad index 0..63
        const ulonglong2 xiv = *reinterpret_cast<const ulonglong2*>(&xi_s[4 * q]);
        ull_t wt2[6][2];
#pragma unroll
        for (int c = 0; c < 6; ++c) {
            const ulonglong2 w = *reinterpret_cast<const ulonglong2*>(&wt_s[c * 256 + 4 * q]);
            wt2[c][0] = w.x; wt2[c][1] = w.y;
        }

        float ah0 = 0.f, ah1 = 0.f, ah2 = 0.f, ah3 = 0.f;
#pragma unroll 1
        for (int s = 0; s < 32; s += 4) {
            // front-batch 4 independent c0 loads (MLP=4)
            ulonglong2 cv[4];
#pragma unroll
            for (int u = 0; u < 4; ++u)
                cv[u] = __ldg(&c04[(wid * 32 + s + u) * 64 + q]);
#pragma unroll
            for (int u = 0; u < 4; ++u) {
                const int j = wid * 32 + s + u;
                const float* rj = rel_s + j * 6;
                ull_t t0 = add2(xiv.x, cv[u].x);
                ull_t t1 = add2(xiv.y, cv[u].y);
#pragma unroll
                for (int c = 0; c < 6; ++c) {
                    const ull_t rp = pk2(rj[c], rj[c]);
                    t0 = fma2(rp, wt2[c][0], t0);
                    t1 = fma2(rp, wt2[c][1], t1);
                }
                float h0, h1, h2, h3;
                upk2(t0, h0, h1);
                upk2(t1, h2, h3);
                const float aw = adj_s[j];
                ah0 = fmaf(aw, fmaxf(h0, 0.f), ah0);
                ah1 = fmaf(aw, fmaxf(h1, 0.f), ah1);
                ah2 = fmaf(aw, fmaxf(h2, 0.f), ah2);
                ah3 = fmaf(aw, fmaxf(h3, 0.f), ah3);
            }
        }
        float4 o; o.x = ah0; o.y = ah1; o.z = ah2; o.w = ah3;
        *reinterpret_cast<float4*>(&ahred[wid * 256 + 4 * q]) = o;
    }
    __syncthreads();

    float s = 0.f;
#pragma unroll
    for (int g = 0; g < 8; ++g) s += ahred[g * 256 + t];
    AH0[row * 256 + t] = s;
}

// ---------------------------------------------------------------------------
// Kernel C: fused layer0 GEMM + layer1 reduction, one jh half PER BLOCK.
// Grid (1024, 2). H build: packed f32x2 + c0 loads front-batched 4x.
// ---------------------------------------------------------------------------
// SMEM byte offsets
#define SM_A       0         // 128 j x 256 k fp16, 512B rows, xor-swizzled = 65536
#define SM_B1      65536     // 32768
#define SM_REL     98304     // 3072
#define SM_ADJ     101376    // 1024
#define SM_AHRED   102400    // 8192 (8 warps x 256 n)
#define SM_XI      110592    // 1024
#define SM_XI1     111616    // 1024
#define SM_TOTAL   112640

__global__ void __launch_bounds__(256, 2) layer01_mma_kernel(
    const float* __restrict__ xi0, const float* __restrict__ c0,
    const float* __restrict__ rel, const float* __restrict__ Wt,
    const float* __restrict__ adj2,
    const float* __restrict__ xi1, const float* __restrict__ c1,
    float* __restrict__ AH1a, float* __restrict__ AH1b)
{
    extern __shared__ char sm[];
    const uint32_t sb = smem_to_u32(sm);
    float* rel_s  = reinterpret_cast<float*>(sm + SM_REL);
    float* adj_s  = reinterpret_cast<float*>(sm + SM_ADJ);
    float* ah1red = reinterpret_cast<float*>(sm + SM_AHRED);
    float* xi_s   = reinterpret_cast<float*>(sm + SM_XI);
    float* xi1_s  = reinterpret_cast<float*>(sm + SM_XI1);

    const int t = threadIdx.x;
    const int wid = t >> 5;
    const int lane = t & 31;
    const int row = blockIdx.x;      // b*256 + i
    const int jh  = blockIdx.y;      // 0 or 1
    const int b = row >> 8;

    adj_s[t]  = adj2[row * 256 + t];
    xi_s[t]   = xi0[row * 256 + t];
    xi1_s[t]  = xi1[row * 256 + t];
    const float* relrow = rel + ((size_t)row * 256 + jh * 128) * 6;
    for (int f = t; f < 768; f += 256) rel_s[f] = relrow[f];
    __syncthreads();

    const float* c0b = c0 + b * 65536;
    const float* c1b = c1 + b * 65536;
    const ulonglong2* c04 = reinterpret_cast<const ulonglong2*>(c0b);

    // --- per-lane ldmatrix address components ---
    const int jrl = wid * 16 + (lane & 15);
    const uint32_t acolByte = (uint32_t)((lane >> 4) * 16);
    const uint32_t jmask = (uint32_t)((jrl & 7) << 4);
    const uint32_t aRowByte = (uint32_t)jrl * 512u;
    const int nrow_l = (lane & 7) | ((lane & 16) >> 1);
    const uint32_t kbB = (uint32_t)(((lane >> 3) & 1) * 16);
    const uint32_t nmask = (uint32_t)((nrow_l & 7) << 4);
    const uint32_t bRowByte = (uint32_t)nrow_l * 256u;

    const int r  = lane >> 2;    // 0..7
    const int cq = lane & 3;     // 0..3

    // ---- build H half (128 j x 256 k) as fp16; 4 k per iter, MLP=4 ----
#pragma unroll
    for (int kq2 = 0; kq2 < 2; ++kq2) {
        const int q = lane + 32 * kq2;     // k-quad 0..63
        const ulonglong2 xiv = *reinterpret_cast<const ulonglong2*>(&xi_s[4 * q]);
        ull_t wt2[6][2];
#pragma unroll
        for (int c = 0; c < 6; ++c) {
            const float2 wa = __ldg(reinterpret_cast<const float2*>(&Wt[c * 256 + 4 * q]));
            const float2 wb = __ldg(reinterpret_cast<const float2*>(&Wt[c * 256 + 4 * q + 2]));
            wt2[c][0] = pk2(wa.x, wa.y);
            wt2[c][1] = pk2(wb.x, wb.y);
        }

#pragma unroll 1
        for (int s = 0; s < 16; s += 4) {
            ulonglong2 cv[4];
#pragma unroll
            for (int u = 0; u < 4; ++u) {
                const int j = jh * 128 + wid * 16 + s + u;
                cv[u] = __ldg(&c04[j * 64 + q]);
            }
#pragma unroll
            for (int u = 0; u < 4; ++u) {
                const int jl = wid * 16 + s + u;
                const float* rj = rel_s + jl * 6;
                ull_t t0 = add2(xiv.x, cv[u].x);
                ull_t t1 = add2(xiv.y, cv[u].y);
#pragma unroll
                for (int c = 0; c < 6; ++c) {
                    const ull_t rp = pk2(rj[c], rj[c]);
                    t0 = fma2(rp, wt2[c][0], t0);
                    t1 = fma2(rp, wt2[c][1], t1);
                }
                float h0, h1, h2, h3;
                upk2(t0, h0, h1);
                upk2(t1, h2, h3);
                __half2 ha = __floats2half2_rn(fmaxf(h0, 0.f), fmaxf(h1, 0.f));
                __half2 hb = __floats2half2_rn(fmaxf(h2, 0.f), fmaxf(h3, 0.f));
                uint2 hv;
                hv.x = *reinterpret_cast<uint32_t*>(&ha);
                hv.y = *reinterpret_cast<uint32_t*>(&hb);
                const uint32_t off = (uint32_t)jl * 512u + ((uint32_t)(8 * q) ^ ((uint32_t)(jl & 7) << 4));
                *reinterpret_cast<uint2*>(sm + SM_A + off) = hv;
            }
        }
    }

#pragma unroll 1
    for (int nc = 0; nc < 2; ++nc) {
        float C[16][4];
#pragma unroll
        for (int nt = 0; nt < 16; ++nt)
#pragma unroll
            for (int u = 0; u < 4; ++u) C[nt][u] = 0.f;

#pragma unroll 1
        for (int kh = 0; kh < 2; ++kh) {
            __syncthreads();   // prior B consumers done (first iter: A build visibility)
            {
                const uint4* s1 = reinterpret_cast<const uint4*>(
                    reinterpret_cast<const char*>(g_wimg1) + kh * 65536 + nc * 32768);
                uint4* d1 = reinterpret_cast<uint4*>(sm + SM_B1);
                for (int i = t; i < 2048; i += 256) d1[i] = __ldg(&s1[i]);
            }
            __syncthreads();

            // ---- HMMA: C += A * B ----
#pragma unroll 1
            for (int ks = 0; ks < 8; ++ks) {
                const uint32_t aoff = ((uint32_t)((kh * 8 + ks) * 32) + acolByte) ^ jmask;
                const uint32_t boff = ((uint32_t)(ks * 32) + kbB) ^ nmask;
                uint32_t Ah[4];
                ldsm4(Ah, sb + SM_A + aRowByte + aoff);

                uint32_t bb[4];
#pragma unroll
                for (int p = 0; p < 8; ++p) {
                    ldsm4(bb, sb + SM_B1 + (uint32_t)p * 4096 + bRowByte + boff);
                    mma_f16(C[2 * p],     Ah, bb[0], bb[1]);
                    mma_f16(C[2 * p + 1], Ah, bb[2], bb[3]);
                }
            }
        }

        // ---- fused layer1 epilogue: consume alpha1 = relu(C) in registers ----
        {
            float acc0[16], acc1[16];
#pragma unroll
            for (int nt = 0; nt < 16; ++nt) { acc0[nt] = 0.f; acc1[nt] = 0.f; }

            const int j1 = jh * 128 + wid * 16 + r;
            const int j2 = j1 + 8;
            const float aw1 = adj_s[j1];
            const float aw2 = adj_s[j2];

            // front-batch c1 loads in groups of 4 nt (8 loads in flight)
#pragma unroll
            for (int ntb = 0; ntb < 16; ntb += 4) {
                float2 cA[4], cB[4];
#pragma unroll
                for (int u = 0; u < 4; ++u) {
                    const int n0 = nc * 128 + (ntb + u) * 8 + 2 * cq;
                    cA[u] = __ldg(reinterpret_cast<const float2*>(c1b + j1 * 256 + n0));
                    cB[u] = __ldg(reinterpret_cast<const float2*>(c1b + j2 * 256 + n0));
                }
#pragma unroll
                for (int u = 0; u < 4; ++u) {
                    const int nt = ntb + u;
                    const int n0 = nc * 128 + nt * 8 + 2 * cq;
                    const float x0 = xi1_s[n0];
                    const float x1v = xi1_s[n0 + 1];
                    const float a0 = fmaxf(C[nt][0], 0.f);
                    const float a1 = fmaxf(C[nt][1], 0.f);
                    const float a2 = fmaxf(C[nt][2], 0.f);
                    const float a3 = fmaxf(C[nt][3], 0.f);
                    acc0[nt] = fmaf(aw1, fmaxf(x0 + cA[u].x + a0, 0.f), acc0[nt]);
                    acc1[nt] = fmaf(aw1, fmaxf(x1v + cA[u].y + a1, 0.f), acc1[nt]);
                    acc0[nt] = fmaf(aw2, fmaxf(x0 + cB[u].x + a2, 0.f), acc0[nt]);
                    acc1[nt] = fmaf(aw2, fmaxf(x1v + cB[u].y + a3, 0.f), acc1[nt]);
                }
            }

#pragma unroll
            for (int nt = 0; nt < 16; ++nt) {
                float v0 = acc0[nt], v1 = acc1[nt];
#pragma unroll
                for (int off = 4; off <= 16; off <<= 1) {
                    v0 += __shfl_xor_sync(0xffffffffu, v0, off);
                    v1 += __shfl_xor_sync(0xffffffffu, v1, off);
                }
                if (r == 0) {
                    const int n0 = nc * 128 + nt * 8 + 2 * cq;
                    ah1red[wid * 256 + n0]     = v0;
                    ah1red[wid * 256 + n0 + 1] = v1;
                }
            }
        }
    }
    __syncthreads();

    // cross-warp reduce -> AH1part[jh]
    {
        float s = 0.f;
#pragma unroll
        for (int g = 0; g < 8; ++g) s += ah1red[g * 256 + t];
        float* dst = jh ? AH1b : AH1a;
        dst[row * 256 + t] = s;
    }
}

// ---------------------------------------------------------------------------
extern "C" void kernel_launch(void* const* d_in, const int* in_sizes, int n_in,
                              void* d_out, int out_size)
{
    (void)in_sizes; (void)n_in; (void)out_size;

    const float* x        = (const float*)d_in[0];
    const float* rel      = (const float*)d_in[1];
    const float* adj      = (const float*)d_in[2];
    const int*   bnum     = (const int*)  d_in[3];
    const float* Wt       = (const float*)d_in[4];
    const float* b_alpha  = (const float*)d_in[5];
    const float* W_proj   = (const float*)d_in[6];
    const float* b_proj   = (const float*)d_in[7];
    const float* learn_w  = (const float*)d_in[8];
    const float* w_alpha0 = (const float*)d_in[9];
    const float* w_vi0    = (const float*)d_in[10];
    const float* w_vj0    = (const float*)d_in[11];
    const float* bias_h0  = (const float*)d_in[12];
    const float* w_node0  = (const float*)d_in[13];
    /* d_in[14] = l1_w_alpha: unused (alpha2 discarded) */
    const float* w_vi1    = (const float*)d_in[15];
    const float* w_vj1    = (const float*)d_in[16];
    const float* bias_h1  = (const float*)d_in[17];
    const float* w_node1  = (const float*)d_in[18];

    float* out      = (float*)d_out;
    float* out_x2   = out;
    float* out_sadj = out + 262144;
    float* out_gl   = out + 524288;

    float *xhat, *pnorm, *adj2, *xi0, *c0, *AH0, *xi1, *c1, *AH1a, *AH1b;
    cudaGetSymbolAddress((void**)&xhat,  g_xhat);
    cudaGetSymbolAddress((void**)&pnorm, g_pnorm);
    cudaGetSymbolAddress((void**)&adj2,  g_adj2);
    cudaGetSymbolAddress((void**)&xi0,   g_xi0);
    cudaGetSymbolAddress((void**)&c0,    g_c0);
    cudaGetSymbolAddress((void**)&AH0,   g_AH0);
    cudaGetSymbolAddress((void**)&xi1,   g_xi1);
    cudaGetSymbolAddress((void**)&c1,    g_c1);
    cudaGetSymbolAddress((void**)&AH1a,  g_AH1a);
    cudaGetSymbolAddress((void**)&AH1b,  g_AH1b);

    const int DUAL_SMEM = 18432 * 4;

    // Launch order: layer01_mma is the 6th launch (ncu -s 5 -c 1).
    cudaFuncSetAttribute(rowgemm8_dual_prep_kernel, cudaFuncAttributeMaxDynamicSharedMemorySize, DUAL_SMEM);
    rowgemm8_dual_prep_kernel<<<128, 256, DUAL_SMEM>>>(x, w_vi0, w_vj0, bias_h0, b_alpha, w_alpha0, xi0, c0);

    rowgemm_kernel<<<256, 128>>>(x, W_proj, b_proj, xhat);
    pair_softadj_kernel<<<1024, 256>>>(xhat, adj, learn_w, bnum, out_sadj, adj2, pnorm);

    ah0_kernel<<<1024, 256>>>(xi0, c0, rel, Wt, adj2, AH0);
    cudaFuncSetAttribute(chain_kernel, cudaFuncAttributeMaxDynamicSharedMemorySize, DUAL_SMEM);
    chain_kernel<<<128, 256, DUAL_SMEM>>>(AH0, w_node0, w_vi1, w_vj1, bias_h1, xi1, c1);

    cudaFuncSetAttribute(layer01_mma_kernel, cudaFuncAttributeMaxDynamicSharedMemorySize, SM_TOTAL);
    layer01_mma_kernel<<<dim3(1024, 2), 256, SM_TOTAL>>>(xi0, c0, rel, Wt, adj2, xi1, c1, AH1a, AH1b);

    glloss_part_kernel<<<512, 256>>>(out_sadj, pnorm);
    glloss_fin_kernel<<<4, 128>>>(bnum, out_gl);
    rowgemm8_sum_kernel<<<128, 256>>>(AH1a, AH1b, w_node1, out_x2);
}

// round 13
// speedup vs baseline: 3.7653x; 1.0010x over previous
#include <cuda_runtime.h>
#include <cuda_fp16.h>
#include <cstdint>
#include <cstddef>

// Problem constants
#define PB 4
#define PN 256
#define PD 256
#define PL 128
#define POUT 256

// ============================ helpers ============================
__device__ __forceinline__ uint32_t smem_to_u32(const void* smem_ptr) {
    uint32_t addr;
    asm("{ .reg .u64 tmp; cvta.to.shared.u64 tmp, %1; cvt.u32.u64 %0, tmp; }"
        : "=r"(addr) : "l"(smem_ptr));
    return addr;
}

__device__ __forceinline__ void ldsm4(uint32_t* r, uint32_t addr) {
    asm volatile("ldmatrix.sync.aligned.m8n8.x4.shared.b16 {%0,%1,%2,%3}, [%4];"
        : "=r"(r[0]), "=r"(r[1]), "=r"(r[2]), "=r"(r[3]) : "r"(addr));
}

__device__ __forceinline__ void mma_f16(float* c, const uint32_t* a, uint32_t b0, uint32_t b1) {
    asm volatile(
        "mma.sync.aligned.m16n8k16.row.col.f32.f16.f16.f32 "
        "{%0,%1,%2,%3}, {%4,%5,%6,%7}, {%8,%9}, {%0,%1,%2,%3};"
        : "+f"(c[0]), "+f"(c[1]), "+f"(c[2]), "+f"(c[3])
        : "r"(a[0]), "r"(a[1]), "r"(a[2]), "r"(a[3]), "r"(b0), "r"(b1));
}

// ---- packed f32x2 ops (sm_100+ baseline PTX) ----
typedef unsigned long long ull_t;
__device__ __forceinline__ ull_t pk2(float lo, float hi) {
    ull_t r;
    asm("mov.b64 %0, {%1, %2};" : "=l"(r)
        : "r"(__float_as_uint(lo)), "r"(__float_as_uint(hi)));
    return r;
}
__device__ __forceinline__ void upk2(ull_t v, float& lo, float& hi) {
    uint32_t a, b;
    asm("mov.b64 {%0, %1}, %2;" : "=r"(a), "=r"(b) : "l"(v));
    lo = __uint_as_float(a); hi = __uint_as_float(b);
}
__device__ __forceinline__ ull_t fma2(ull_t a, ull_t b, ull_t c) {
    ull_t d;
    asm("fma.rn.f32x2 %0, %1, %2, %3;" : "=l"(d) : "l"(a), "l"(b), "l"(c));
    return d;
}
__device__ __forceinline__ ull_t add2(ull_t a, ull_t b) {
    ull_t d;
    asm("add.rn.f32x2 %0, %1, %2;" : "=l"(d) : "l"(a), "l"(b));
    return d;
}
__device__ __forceinline__ ull_t h2_to_pk(uint32_t h2bits) {
    const __half2 h = *reinterpret_cast<const __half2*>(&h2bits);
    const float2 f = __half22float2(h);
    return pk2(f.x, f.y);
}

// ---------------- scratch (device globals; no runtime allocation) ----------------
__device__ float g_xhat [PB*PN*PL];
__device__ float g_pnorm[PB*PN*PN];
__device__ float g_adj2 [PB*PN*PN];
__device__ float g_xi0  [PB*PN*POUT];
__device__ __half g_c0  [PB*PN*POUT];   // fp16 pair-constant (layer 0)
__device__ float g_AH0  [PB*PN*POUT];
__device__ float g_xi1  [PB*PN*POUT];
__device__ __half g_c1  [PB*PN*POUT];   // fp16 pair-constant (layer 1)
__device__ float g_AH1a [PB*PN*POUT];
__device__ float g_AH1b [PB*PN*POUT];
__device__ float g_part1[512];
__device__ float g_part2[512];
// Pre-converted w_alpha image: [kh:2][n:256][k:128] fp16, 256B rows,
// XOR-swizzled by (n&7)<<4 -> ldmatrix conflict-free, verbatim staging.
// kh stride = 65536 BYTES.
__device__ __half g_wimg1[2*256*128];

// ---------------------------------------------------------------------------
// Simple row GEMM for xhat (K=128)
// ---------------------------------------------------------------------------
__global__ void rowgemm_kernel(const float* __restrict__ X, const float* __restrict__ W,
                               const float* __restrict__ bias_k, float* __restrict__ out)
{
    __shared__ float xs[4 * 256];
    const int r0 = blockIdx.x * 4;
    const int t  = threadIdx.x;
    for (int f = t; f < 4 * 256; f += 128) xs[f] = X[r0 * 256 + f];
    __syncthreads();

    float acc[4] = {0.f, 0.f, 0.f, 0.f};
#pragma unroll 8
    for (int d = 0; d < 256; ++d) {
        const float wv = __ldg(&W[d * 128 + t]);
#pragma unroll
        for (int r = 0; r < 4; ++r) acc[r] = fmaf(xs[r * 256 + d], wv, acc[r]);
    }
    const float bk = __ldg(&bias_k[t]);
#pragma unroll
    for (int r = 0; r < 4; ++r) out[(r0 + r) * 128 + t] = acc[r] + bk;
}

// ---------------------------------------------------------------------------
// Dual row GEMM (layer-0 inputs) + FUSED w_alpha image prep.
// out1 = X@W1 (fp32 xi0) ; out2 = fp16(X@W2 + bias_nk + bias_k) (c0)
// ---------------------------------------------------------------------------
__global__ __launch_bounds__(256) void rowgemm8_dual_prep_kernel(
    const float* __restrict__ X, const float* __restrict__ W1, const float* __restrict__ W2,
    const float* __restrict__ bias_nk, const float* __restrict__ bias_k,
    const float* __restrict__ w_alpha,
    float* __restrict__ out1, __half* __restrict__ out2)
{
    extern __shared__ float dsm[];
    float* xs  = dsm;          // 2048
    float* ws1 = dsm + 2048;   // 8192
    float* ws2 = dsm + 10240;  // 8192
    const int r0 = blockIdx.x * 8;
    const int t  = threadIdx.x;

    // ---- fused prep: convert w_alpha (k=d:256, n:256) into fp16 transposed image ----
    {
        const int base = (blockIdx.x * 256 + t) * 2;
#pragma unroll
        for (int u = 0; u < 2; ++u) {
            const int e = base + u;
            const int k = e >> 8;
            const int n = e & 255;
            const __half hi = __float2half_rn(__ldg(&w_alpha[k * 256 + n]));
            const int kh = k >> 7, kk = k & 127;
            const uint32_t off = kh * 65536u + n * 256u + (uint32_t)((kk * 2) ^ ((n & 7) << 4));
            *reinterpret_cast<__half*>(reinterpret_cast<char*>(g_wimg1) + off) = hi;
        }
    }

    for (int f = t; f < 8 * 256; f += 256) xs[f] = X[r0 * 256 + f];

    float a1[8], a2[8];
#pragma unroll
    for (int r = 0; r < 8; ++r) { a1[r] = 0.f; a2[r] = 0.f; }

    for (int dt = 0; dt < 8; ++dt) {
        __syncthreads();
        const float4* W1v = reinterpret_cast<const float4*>(W1 + dt * 32 * 256);
        const float4* W2v = reinterpret_cast<const float4*>(W2 + dt * 32 * 256);
        float4* w1s = reinterpret_cast<float4*>(ws1);
        float4* w2s = reinterpret_cast<float4*>(ws2);
        for (int i = t; i < 2048; i += 256) { w1s[i] = __ldg(&W1v[i]); w2s[i] = __ldg(&W2v[i]); }
        __syncthreads();
#pragma unroll
        for (int d4 = 0; d4 < 32; d4 += 4) {
            float u0 = ws1[(d4 + 0) * 256 + t], v0 = ws2[(d4 + 0) * 256 + t];
            float u1 = ws1[(d4 + 1) * 256 + t], v1 = ws2[(d4 + 1) * 256 + t];
            float u2 = ws1[(d4 + 2) * 256 + t], v2 = ws2[(d4 + 2) * 256 + t];
            float u3 = ws1[(d4 + 3) * 256 + t], v3 = ws2[(d4 + 3) * 256 + t];
#pragma unroll
            for (int r = 0; r < 8; ++r) {
                const float4 xv = *reinterpret_cast<const float4*>(&xs[r * 256 + dt * 32 + d4]);
                a1[r] = fmaf(xv.x, u0, a1[r]); a2[r] = fmaf(xv.x, v0, a2[r]);
                a1[r] = fmaf(xv.y, u1, a1[r]); a2[r] = fmaf(xv.y, v1, a2[r]);
                a1[r] = fmaf(xv.z, u2, a1[r]); a2[r] = fmaf(xv.z, v2, a2[r]);
                a1[r] = fmaf(xv.w, u3, a1[r]); a2[r] = fmaf(xv.w, v3, a2[r]);
            }
        }
    }
    const float bk = bias_k ? __ldg(&bias_k[t]) : 0.f;
#pragma unroll
    for (int r = 0; r < 8; ++r) {
        const int row = r0 + r;
        out1[row * 256 + t] = a1[r];
        out2[row * 256 + t] = __float2half_rn(a2[r] + bk + __ldg(&bias_nk[(row & (PN - 1)) * 256 + t]));
    }
}

// ---------------------------------------------------------------------------
// Fused chain: x1 = relu(AH0 @ Wn0); xi1 = x1 @ Wvi1; c1 = fp16(x1 @ Wvj1 + bias_h1).
// ---------------------------------------------------------------------------
__global__ __launch_bounds__(256) void chain_kernel(
    const float* __restrict__ AH0, const float* __restrict__ Wn0,
    const float* __restrict__ Wvi1, const float* __restrict__ Wvj1,
    const float* __restrict__ bias_h1,
    float* __restrict__ xi1, __half* __restrict__ c1)
{
    extern __shared__ float dsm[];
    float* xs  = dsm;          // 2048
    float* ws1 = dsm + 2048;   // 8192
    float* ws2 = dsm + 10240;  // 8192
    const int r0 = blockIdx.x * 8;
    const int t  = threadIdx.x;
    for (int f = t; f < 8 * 256; f += 256) xs[f] = AH0[r0 * 256 + f];

    float acc[8];
#pragma unroll
    for (int r = 0; r < 8; ++r) acc[r] = 0.f;

    for (int dt = 0; dt < 8; ++dt) {
        __syncthreads();
        const float4* Wv = reinterpret_cast<const float4*>(Wn0 + dt * 32 * 256);
        float4* wsv = reinterpret_cast<float4*>(ws1);
        for (int i = t; i < 2048; i += 256) wsv[i] = __ldg(&Wv[i]);
        __syncthreads();
#pragma unroll
        for (int d4 = 0; d4 < 32; d4 += 4) {
            float wv0 = ws1[(d4 + 0) * 256 + t];
            float wv1 = ws1[(d4 + 1) * 256 + t];
            float wv2 = ws1[(d4 + 2) * 256 + t];
            float wv3 = ws1[(d4 + 3) * 256 + t];
#pragma unroll
            for (int r = 0; r < 8; ++r) {
                const float4 xv = *reinterpret_cast<const float4*>(&xs[r * 256 + dt * 32 + d4]);
                acc[r] = fmaf(xv.x, wv0, acc[r]);
                acc[r] = fmaf(xv.y, wv1, acc[r]);
                acc[r] = fmaf(xv.z, wv2, acc[r]);
                acc[r] = fmaf(xv.w, wv3, acc[r]);
            }
        }
    }
    __syncthreads();
#pragma unroll
    for (int r = 0; r < 8; ++r) xs[r * 256 + t] = fmaxf(acc[r], 0.f);   // x1 in smem

    float a1[8], a2[8];
#pragma unroll
    for (int r = 0; r < 8; ++r) { a1[r] = 0.f; a2[r] = 0.f; }

    for (int dt = 0; dt < 8; ++dt) {
        __syncthreads();
        const float4* W1v = reinterpret_cast<const float4*>(Wvi1 + dt * 32 * 256);
        const float4* W2v = reinterpret_cast<const float4*>(Wvj1 + dt * 32 * 256);
        float4* w1s = reinterpret_cast<float4*>(ws1);
        float4* w2s = reinterpret_cast<float4*>(ws2);
        for (int i = t; i < 2048; i += 256) { w1s[i] = __ldg(&W1v[i]); w2s[i] = __ldg(&W2v[i]); }
        __syncthreads();
#pragma unroll
        for (int d4 = 0; d4 < 32; d4 += 4) {
            float u0 = ws1[(d4 + 0) * 256 + t], v0 = ws2[(d4 + 0) * 256 + t];
            float u1 = ws1[(d4 + 1) * 256 + t], v1 = ws2[(d4 + 1) * 256 + t];
            float u2 = ws1[(d4 + 2) * 256 + t], v2 = ws2[(d4 + 2) * 256 + t];
            float u3 = ws1[(d4 + 3) * 256 + t], v3 = ws2[(d4 + 3) * 256 + t];
#pragma unroll
            for (int r = 0; r < 8; ++r) {
                const float4 xv = *reinterpret_cast<const float4*>(&xs[r * 256 + dt * 32 + d4]);
                a1[r] = fmaf(xv.x, u0, a1[r]); a2[r] = fmaf(xv.x, v0, a2[r]);
                a1[r] = fmaf(xv.y, u1, a1[r]); a2[r] = fmaf(xv.y, v1, a2[r]);
                a1[r] = fmaf(xv.z, u2, a1[r]); a2[r] = fmaf(xv.z, v2, a2[r]);
                a1[r] = fmaf(xv.w, u3, a1[r]); a2[r] = fmaf(xv.w, v3, a2[r]);
            }
        }
    }
#pragma unroll
    for (int r = 0; r < 8; ++r) {
        const int row = r0 + r;
        xi1[row * 256 + t] = a1[r];
        c1[row * 256 + t]  = __float2half_rn(a2[r] + __ldg(&bias_h1[(row & (PN - 1)) * 256 + t]));
    }
}

// ---------------------------------------------------------------------------
// Final: out = relu((A + B) @ W)
// ---------------------------------------------------------------------------
__global__ __launch_bounds__(256) void rowgemm8_sum_kernel(
    const float* __restrict__ A, const float* __restrict__ B,
    const float* __restrict__ W, float* __restrict__ out)
{
    __shared__ float xs[8 * 256];
    __shared__ float ws[32 * 256];
    const int r0 = blockIdx.x * 8;
    const int t  = threadIdx.x;
    for (int f = t; f < 8 * 256; f += 256) xs[f] = A[r0 * 256 + f] + B[r0 * 256 + f];

    float acc[8];
#pragma unroll
    for (int r = 0; r < 8; ++r) acc[r] = 0.f;

    for (int dt = 0; dt < 8; ++dt) {
        __syncthreads();
        const float4* Wv = reinterpret_cast<const float4*>(W + dt * 32 * 256);
        float4* wsv = reinterpret_cast<float4*>(ws);
        for (int i = t; i < 2048; i += 256) wsv[i] = __ldg(&Wv[i]);
        __syncthreads();
#pragma unroll
        for (int d4 = 0; d4 < 32; d4 += 4) {
            float wv0 = ws[(d4 + 0) * 256 + t];
            float wv1 = ws[(d4 + 1) * 256 + t];
            float wv2 = ws[(d4 + 2) * 256 + t];
            float wv3 = ws[(d4 + 3) * 256 + t];
#pragma unroll
            for (int r = 0; r < 8; ++r) {
                const float4 xv = *reinterpret_cast<const float4*>(&xs[r * 256 + dt * 32 + d4]);
                acc[r] = fmaf(xv.x, wv0, acc[r]);
                acc[r] = fmaf(xv.y, wv1, acc[r]);
                acc[r] = fmaf(xv.z, wv2, acc[r]);
                acc[r] = fmaf(xv.w, wv3, acc[r]);
            }
        }
    }
#pragma unroll
    for (int r = 0; r < 8; ++r) out[(r0 + r) * 256 + t] = fmaxf(acc[r], 0.f);
}

// ---------------------------------------------------------------------------
// Fused graph-learning kernel.
// ---------------------------------------------------------------------------
__global__ void pair_softadj_kernel(const float* __restrict__ xhat,
                                    const float* __restrict__ adj,
                                    const float* __restrict__ learn_w,
                                    const int*   __restrict__ box_num,
                                    float* __restrict__ soft_adj_out,
                                    float* __restrict__ adj2,
                                    float* __restrict__ pair_norm)
{
    const int row = blockIdx.x;
    const int b = row >> 8;
    const int i = row & 255;
    const int t = threadIdx.x;
    const int warp = t >> 5, lane = t & 31;

    __shared__ float xi_s[128];
    __shared__ float w_s[128];
    __shared__ float sval[256];
    __shared__ float red[256];
    __shared__ float wsum_s, rmax_s;

    if (t < 128) { xi_s[t] = xhat[row * 128 + t]; w_s[t] = learn_w[t]; }
    __syncthreads();
    if (t == 0) {
        float s = 0.f;
        for (int d = 0; d < 128; ++d) s += w_s[d];
        wsum_s = s;
    }
    __syncthreads();

    const int bn = box_num[b];
    const bool vi = (i < bn);
    const float wsum = wsum_s;
    const float4 xi4 = reinterpret_cast<const float4*>(xi_s)[lane];
    const float4 w4  = reinterpret_cast<const float4*>(w_s)[lane];

    for (int j = warp; j < 256; j += 8) {
        const float4 xj4 = __ldg(reinterpret_cast<const float4*>(xhat + (b * 256 + j) * 128) + lane);
        const float d0 = xi4.x - xj4.x, d1 = xi4.y - xj4.y;
        const float d2 = xi4.z - xj4.z, d3 = xi4.w - xj4.w;
        float s = fabsf(d0) * w4.x + fabsf(d1) * w4.y + fabsf(d2) * w4.z + fabsf(d3) * w4.w;
        float q = d0 * d0 + d1 * d1 + d2 * d2 + d3 * d3;
#pragma unroll
        for (int off = 16; off; off >>= 1) {
            s += __shfl_down_sync(0xffffffffu, s, off);
            q += __shfl_down_sync(0xffffffffu, q, off);
        }
        if (lane == 0) {
            const float m = (vi && (j < bn)) ? 0.f : -1.f;
            float v = s + m * wsum;
            v = (v > 0.f) ? v : 0.01f * v;
            sval[j] = v;
            pair_norm[row * 256 + j] = sqrtf(q + 1e-12f);
        }
    }
    __syncthreads();

    const float v = sval[t];
    red[t] = v;
    __syncthreads();
    for (int sft = 128; sft; sft >>= 1) {
        if (t < sft) red[t] = fmaxf(red[t], red[t + sft]);
        __syncthreads();
    }
    if (t == 0) rmax_s = red[0];
    __syncthreads();

    const float a = adj[row * 256 + t];
    const float e = expf(v - rmax_s) * a;
    red[t] = e;
    __syncthreads();
    for (int sft = 128; sft; sft >>= 1) {
        if (t < sft) red[t] += red[t + sft];
        __syncthreads();
    }
    const float sa = e / red[0] + 1e-10f;
    soft_adj_out[row * 256 + t] = sa;
    adj2[row * 256 + t] = a * sa;
}

// ---------------------------------------------------------------------------
// gl_loss two-phase reduction.
// ---------------------------------------------------------------------------
__global__ void glloss_part_kernel(const float* __restrict__ soft_adj,
                                   const float* __restrict__ pair_norm)
{
    const int blk = blockIdx.x;
    const int b = blk >> 7;
    const int t = threadIdx.x;
    const int base = b * 65536 + (blk & 127) * 512;
    float s1 = 0.f, s2 = 0.f;
#pragma unroll
    for (int u = 0; u < 2; ++u) {
        const int idx = base + u * 256 + t;
        const float s = soft_adj[idx];
        s1 += expf(s + pair_norm[idx]);
        s2 += s * s;
    }
    __shared__ float r1[256], r2[256];
    r1[t] = s1; r2[t] = s2;
    __syncthreads();
    for (int sft = 128; sft; sft >>= 1) {
        if (t < sft) { r1[t] += r1[t + sft]; r2[t] += r2[t + sft]; }
        __syncthreads();
    }
    if (t == 0) { g_part1[blk] = r1[0]; g_part2[blk] = r2[0]; }
}

__global__ void glloss_fin_kernel(const int* __restrict__ box_num, float* __restrict__ gl_out)
{
    const int b = blockIdx.x;
    const int t = threadIdx.x;
    __shared__ float r1[128], r2[128];
    r1[t] = g_part1[b * 128 + t];
    r2[t] = g_part2[b * 128 + t];
    __syncthreads();
    for (int sft = 64; sft; sft >>= 1) {
        if (t < sft) { r1[t] += r1[t + sft]; r2[t] += r2[t + sft]; }
        __syncthreads();
    }
    if (t == 0) {
        const float bnf = (float)box_num[b];
        gl_out[b] = r1[0] / (bnf * bnf) + 1e-4f * sqrtf(r2[0]);
    }
}

// ---------------------------------------------------------------------------
// Kernel A: AH0 only. H on the fly; c0 fp16, loads front-batched 8x (MLP=8).
// ---------------------------------------------------------------------------
__global__ __launch_bounds__(256) void ah0_kernel(
    const float* __restrict__ xi0, const __half* __restrict__ c0,
    const float* __restrict__ rel, const float* __restrict__ Wt,
    const float* __restrict__ adj2, float* __restrict__ AH0)
{
    __shared__ __align__(16) float rel_s[1536];
    __shared__ __align__(16) float wt_s[1536];
    __shared__ __align__(16) float adj_s[256];
    __shared__ __align__(16) float ahred[2048];
    __shared__ __align__(16) float xi_s[256];

    const int t = threadIdx.x;
    const int wid = t >> 5;
    const int lane = t & 31;
    const int row = blockIdx.x;
    const int b = row >> 8;

    const float* relrow = rel + (size_t)row * 256 * 6;
    for (int f = t; f < 1536; f += 256) { rel_s[f] = relrow[f]; wt_s[f] = Wt[f]; }
    adj_s[t] = adj2[row * 256 + t];
    xi_s[t]  = xi0[row * 256 + t];
    __syncthreads();

    const uint2* c0q = reinterpret_cast<const uint2*>(c0 + b * 65536);  // 4 halves per uint2

#pragma unroll
    for (int kq2 = 0; kq2 < 2; ++kq2) {
        const int q = lane + 32 * kq2;     // k-quad index 0..63
        const ulonglong2 xiv = *reinterpret_cast<const ulonglong2*>(&xi_s[4 * q]);
        ull_t wt2[6][2];
#pragma unroll
        for (int c = 0; c < 6; ++c) {
            const ulonglong2 w = *reinterpret_cast<const ulonglong2*>(&wt_s[c * 256 + 4 * q]);
            wt2[c][0] = w.x; wt2[c][1] = w.y;
        }

        float ah0 = 0.f, ah1 = 0.f, ah2 = 0.f, ah3 = 0.f;
#pragma unroll 1
        for (int s = 0; s < 32; s += 8) {
            // front-batch 8 independent c0 loads (MLP=8, 8B each)
            uint2 cv[8];
#pragma unroll
            for (int u = 0; u < 8; ++u)
                cv[u] = __ldg(&c0q[(wid * 32 + s + u) * 64 + q]);
#pragma unroll
            for (int u = 0; u < 8; ++u) {
                const int j = wid * 32 + s + u;
                const float* rj = rel_s + j * 6;
                ull_t t0 = add2(xiv.x, h2_to_pk(cv[u].x));
                ull_t t1 = add2(xiv.y, h2_to_pk(cv[u].y));
#pragma unroll
                for (int c = 0; c < 6; ++c) {
                    const ull_t rp = pk2(rj[c], rj[c]);
                    t0 = fma2(rp, wt2[c][0], t0);
                    t1 = fma2(rp, wt2[c][1], t1);
                }
                float h0, h1, h2, h3;
                upk2(t0, h0, h1);
                upk2(t1, h2, h3);
                const float aw = adj_s[j];
                ah0 = fmaf(aw, fmaxf(h0, 0.f), ah0);
                ah1 = fmaf(aw, fmaxf(h1, 0.f), ah1);
                ah2 = fmaf(aw, fmaxf(h2, 0.f), ah2);
                ah3 = fmaf(aw, fmaxf(h3, 0.f), ah3);
            }
        }
        float4 o; o.x = ah0; o.y = ah1; o.z = ah2; o.w = ah3;
        *reinterpret_cast<float4*>(&ahred[wid * 256 + 4 * q]) = o;
    }
    __syncthreads();

    float s = 0.f;
#pragma unroll
    for (int g = 0; g < 8; ++g) s += ahred[g * 256 + t];
    AH0[row * 256 + t] = s;
}

// ---------------------------------------------------------------------------
// Kernel C: fused layer0 GEMM + layer1 reduction, one jh half PER BLOCK.
// Grid (1024, 2). c0/c1 fp16; H build packed f32x2 with MLP=4 c0 batching.
// ---------------------------------------------------------------------------
// SMEM byte offsets
#define SM_A       0         // 128 j x 256 k fp16, 512B rows, xor-swizzled = 65536
#define SM_B1      65536     // 32768
#define SM_REL     98304     // 3072
#define SM_ADJ     101376    // 1024
#define SM_AHRED   102400    // 8192 (8 warps x 256 n)
#define SM_XI      110592    // 1024
#define SM_XI1     111616    // 1024
#define SM_TOTAL   112640

__global__ void __launch_bounds__(256, 2) layer01_mma_kernel(
    const float* __restrict__ xi0, const __half* __restrict__ c0,
    const float* __restrict__ rel, const float* __restrict__ Wt,
    const float* __restrict__ adj2,
    const float* __restrict__ xi1, const __half* __restrict__ c1,
    float* __restrict__ AH1a, float* __restrict__ AH1b)
{
    extern __shared__ char sm[];
    const uint32_t sb = smem_to_u32(sm);
    float* rel_s  = reinterpret_cast<float*>(sm + SM_REL);
    float* adj_s  = reinterpret_cast<float*>(sm + SM_ADJ);
    float* ah1red = reinterpret_cast<float*>(sm + SM_AHRED);
    float* xi_s   = reinterpret_cast<float*>(sm + SM_XI);
    float* xi1_s  = reinterpret_cast<float*>(sm + SM_XI1);

    const int t = threadIdx.x;
    const int wid = t >> 5;
    const int lane = t & 31;
    const int row = blockIdx.x;      // b*256 + i
    const int jh  = blockIdx.y;      // 0 or 1
    const int b = row >> 8;

    adj_s[t]  = adj2[row * 256 + t];
    xi_s[t]   = xi0[row * 256 + t];
    xi1_s[t]  = xi1[row * 256 + t];
    const float* relrow = rel + ((size_t)row * 256 + jh * 128) * 6;
    for (int f = t; f < 768; f += 256) rel_s[f] = relrow[f];
    __syncthreads();

    const uint2* c0q = reinterpret_cast<const uint2*>(c0 + b * 65536);
    const __half* c1b = c1 + b * 65536;

    // --- per-lane ldmatrix address components ---
    const int jrl = wid * 16 + (lane & 15);
    const uint32_t acolByte = (uint32_t)((lane >> 4) * 16);
    const uint32_t jmask = (uint32_t)((jrl & 7) << 4);
    const uint32_t aRowByte = (uint32_t)jrl * 512u;
    const int nrow_l = (lane & 7) | ((lane & 16) >> 1);
    const uint32_t kbB = (uint32_t)(((lane >> 3) & 1) * 16);
    const uint32_t nmask = (uint32_t)((nrow_l & 7) << 4);
    const uint32_t bRowByte = (uint32_t)nrow_l * 256u;

    const int r  = lane >> 2;    // 0..7
    const int cq = lane & 3;     // 0..3

    // ---- build H half (128 j x 256 k) as fp16; 4 k per iter, MLP=4 ----
#pragma unroll
    for (int kq2 = 0; kq2 < 2; ++kq2) {
        const int q = lane + 32 * kq2;     // k-quad 0..63
        const ulonglong2 xiv = *reinterpret_cast<const ulonglong2*>(&xi_s[4 * q]);
        ull_t wt2[6][2];
#pragma unroll
        for (int c = 0; c < 6; ++c) {
            const float2 wa = __ldg(reinterpret_cast<const float2*>(&Wt[c * 256 + 4 * q]));
            const float2 wb = __ldg(reinterpret_cast<const float2*>(&Wt[c * 256 + 4 * q + 2]));
            wt2[c][0] = pk2(wa.x, wa.y);
            wt2[c][1] = pk2(wb.x, wb.y);
        }

#pragma unroll 1
        for (int s = 0; s < 16; s += 4) {
            uint2 cv[4];
#pragma unroll
            for (int u = 0; u < 4; ++u) {
                const int j = jh * 128 + wid * 16 + s + u;
                cv[u] = __ldg(&c0q[j * 64 + q]);
            }
#pragma unroll
            for (int u = 0; u < 4; ++u) {
                const int jl = wid * 16 + s + u;
                const float* rj = rel_s + jl * 6;
                ull_t t0 = add2(xiv.x, h2_to_pk(cv[u].x));
                ull_t t1 = add2(xiv.y, h2_to_pk(cv[u].y));
#pragma unroll
                for (int c = 0; c < 6; ++c) {
                    const ull_t rp = pk2(rj[c], rj[c]);
                    t0 = fma2(rp, wt2[c][0], t0);
                    t1 = fma2(rp, wt2[c][1], t1);
                }
                float h0, h1, h2, h3;
                upk2(t0, h0, h1);
                upk2(t1, h2, h3);
                __half2 ha = __floats2half2_rn(fmaxf(h0, 0.f), fmaxf(h1, 0.f));
                __half2 hb = __floats2half2_rn(fmaxf(h2, 0.f), fmaxf(h3, 0.f));
                uint2 hv;
                hv.x = *reinterpret_cast<uint32_t*>(&ha);
                hv.y = *reinterpret_cast<uint32_t*>(&hb);
                const uint32_t off = (uint32_t)jl * 512u + ((uint32_t)(8 * q) ^ ((uint32_t)(jl & 7) << 4));
                *reinterpret_cast<uint2*>(sm + SM_A + off) = hv;
            }
        }
    }

#pragma unroll 1
    for (int nc = 0; nc < 2; ++nc) {
        float C[16][4];
#pragma unroll
        for (int nt = 0; nt < 16; ++nt)
#pragma unroll
            for (int u = 0; u < 4; ++u) C[nt][u] = 0.f;

#pragma unroll 1
        for (int kh = 0; kh < 2; ++kh) {
            __syncthreads();   // prior B consumers done (first iter: A build visibility)
            {
                const uint4* s1 = reinterpret_cast<const uint4*>(
                    reinterpret_cast<const char*>(g_wimg1) + kh * 65536 + nc * 32768);
                uint4* d1 = reinterpret_cast<uint4*>(sm + SM_B1);
                for (int i = t; i < 2048; i += 256) d1[i] = __ldg(&s1[i]);
            }
            __syncthreads();

            // ---- HMMA: C += A * B ----
#pragma unroll 1
            for (int ks = 0; ks < 8; ++ks) {
                const uint32_t aoff = ((uint32_t)((kh * 8 + ks) * 32) + acolByte) ^ jmask;
                const uint32_t boff = ((uint32_t)(ks * 32) + kbB) ^ nmask;
                uint32_t Ah[4];
                ldsm4(Ah, sb + SM_A + aRowByte + aoff);

                uint32_t bb[4];
#pragma unroll
                for (int p = 0; p < 8; ++p) {
                    ldsm4(bb, sb + SM_B1 + (uint32_t)p * 4096 + bRowByte + boff);
                    mma_f16(C[2 * p],     Ah, bb[0], bb[1]);
                    mma_f16(C[2 * p + 1], Ah, bb[2], bb[3]);
                }
            }
        }

        // ---- fused layer1 epilogue: consume alpha1 = relu(C) in registers ----
        {
            float acc0[16], acc1[16];
#pragma unroll
            for (int nt = 0; nt < 16; ++nt) { acc0[nt] = 0.f; acc1[nt] = 0.f; }

            const int j1 = jh * 128 + wid * 16 + r;
            const int j2 = j1 + 8;
            const float aw1 = adj_s[j1];
            const float aw2 = adj_s[j2];

            // front-batch c1 loads (fp16 pairs) in groups of 4 nt
#pragma unroll
            for (int ntb = 0; ntb < 16; ntb += 4) {
                uint32_t cA[4], cB[4];
#pragma unroll
                for (int u = 0; u < 4; ++u) {
                    const int n0 = nc * 128 + (ntb + u) * 8 + 2 * cq;
                    cA[u] = __ldg(reinterpret_cast<const uint32_t*>(c1b + j1 * 256 + n0));
                    cB[u] = __ldg(reinterpret_cast<const uint32_t*>(c1b + j2 * 256 + n0));
                }
#pragma unroll
                for (int u = 0; u < 4; ++u) {
                    const int nt = ntb + u;
                    const int n0 = nc * 128 + nt * 8 + 2 * cq;
                    const float2 fA = __half22float2(*reinterpret_cast<const __half2*>(&cA[u]));
                    const float2 fB = __half22float2(*reinterpret_cast<const __half2*>(&cB[u]));
                    const float x0 = xi1_s[n0];
                    const float x1v = xi1_s[n0 + 1];
                    const float a0 = fmaxf(C[nt][0], 0.f);
                    const float a1 = fmaxf(C[nt][1], 0.f);
                    const float a2 = fmaxf(C[nt][2], 0.f);
                    const float a3 = fmaxf(C[nt][3], 0.f);
                    acc0[nt] = fmaf(aw1, fmaxf(x0 + fA.x + a0, 0.f), acc0[nt]);
                    acc1[nt] = fmaf(aw1, fmaxf(x1v + fA.y + a1, 0.f), acc1[nt]);
                    acc0[nt] = fmaf(aw2, fmaxf(x0 + fB.x + a2, 0.f), acc0[nt]);
                    acc1[nt] = fmaf(aw2, fmaxf(x1v + fB.y + a3, 0.f), acc1[nt]);
                }
            }

#pragma unroll
            for (int nt = 0; nt < 16; ++nt) {
                float v0 = acc0[nt], v1 = acc1[nt];
#pragma unroll
                for (int off = 4; off <= 16; off <<= 1) {
                    v0 += __shfl_xor_sync(0xffffffffu, v0, off);
                    v1 += __shfl_xor_sync(0xffffffffu, v1, off);
                }
                if (r == 0) {
                    const int n0 = nc * 128 + nt * 8 + 2 * cq;
                    ah1red[wid * 256 + n0]     = v0;
                    ah1red[wid * 256 + n0 + 1] = v1;
                }
            }
        }
    }
    __syncthreads();

    // cross-warp reduce -> AH1part[jh]
    {
        float s = 0.f;
#pragma unroll
        for (int g = 0; g < 8; ++g) s += ah1red[g * 256 + t];
        float* dst = jh ? AH1b : AH1a;
        dst[row * 256 + t] = s;
    }
}

// ---------------------------------------------------------------------------
extern "C" void kernel_launch(void* const* d_in, const int* in_sizes, int n_in,
                              void* d_out, int out_size)
{
    (void)in_sizes; (void)n_in; (void)out_size;

    const float* x        = (const float*)d_in[0];
    const float* rel      = (const float*)d_in[1];
    const float* adj      = (const float*)d_in[2];
    const int*   bnum     = (const int*)  d_in[3];
    const float* Wt       = (const float*)d_in[4];
    const float* b_alpha  = (const float*)d_in[5];
    const float* W_proj   = (const float*)d_in[6];
    const float* b_proj   = (const float*)d_in[7];
    const float* learn_w  = (const float*)d_in[8];
    const float* w_alpha0 = (const float*)d_in[9];
    const float* w_vi0    = (const float*)d_in[10];
    const float* w_vj0    = (const float*)d_in[11];
    const float* bias_h0  = (const float*)d_in[12];
    const float* w_node0  = (const float*)d_in[13];
    /* d_in[14] = l1_w_alpha: unused (alpha2 discarded) */
    const float* w_vi1    = (const float*)d_in[15];
    const float* w_vj1    = (const float*)d_in[16];
    const float* bias_h1  = (const float*)d_in[17];
    const float* w_node1  = (const float*)d_in[18];

    float* out      = (float*)d_out;
    float* out_x2   = out;
    float* out_sadj = out + 262144;
    float* out_gl   = out + 524288;

    float *xhat, *pnorm, *adj2, *xi0, *AH0, *xi1, *AH1a, *AH1b;
    __half *c0, *c1;
    cudaGetSymbolAddress((void**)&xhat,  g_xhat);
    cudaGetSymbolAddress((void**)&pnorm, g_pnorm);
    cudaGetSymbolAddress((void**)&adj2,  g_adj2);
    cudaGetSymbolAddress((void**)&xi0,   g_xi0);
    cudaGetSymbolAddress((void**)&c0,    g_c0);
    cudaGetSymbolAddress((void**)&AH0,   g_AH0);
    cudaGetSymbolAddress((void**)&xi1,   g_xi1);
    cudaGetSymbolAddress((void**)&c1,    g_c1);
    cudaGetSymbolAddress((void**)&AH1a,  g_AH1a);
    cudaGetSymbolAddress((void**)&AH1b,  g_AH1b);

    const int DUAL_SMEM = 18432 * 4;

    cudaFuncSetAttribute(rowgemm8_dual_prep_kernel, cudaFuncAttributeMaxDynamicSharedMemorySize, DUAL_SMEM);
    rowgemm8_dual_prep_kernel<<<128, 256, DUAL_SMEM>>>(x, w_vi0, w_vj0, bias_h0, b_alpha, w_alpha0, xi0, c0);

    rowgemm_kernel<<<256, 128>>>(x, W_proj, b_proj, xhat);
    pair_softadj_kernel<<<1024, 256>>>(xhat, adj, learn_w, bnum, out_sadj, adj2, pnorm);

    ah0_kernel<<<1024, 256>>>(xi0, c0, rel, Wt, adj2, AH0);
    cudaFuncSetAttribute(chain_kernel, cudaFuncAttributeMaxDynamicSharedMemorySize, DUAL_SMEM);
    chain_kernel<<<128, 256, DUAL_SMEM>>>(AH0, w_node0, w_vi1, w_vj1, bias_h1, xi1, c1);

    cudaFuncSetAttribute(layer01_mma_kernel, cudaFuncAttributeMaxDynamicSharedMemorySize, SM_TOTAL);
    layer01_mma_kernel<<<dim3(1024, 2), 256, SM_TOTAL>>>(xi0, c0, rel, Wt, adj2, xi1, c1, AH1a, AH1b);

    glloss_part_kernel<<<512, 256>>>(out_sadj, pnorm);
    glloss_fin_kernel<<<4, 128>>>(bnum, out_gl);
    rowgemm8_sum_kernel<<<128, 256>>>(AH1a, AH1b, w_node1, out_x2);
}